// round 11
// baseline (speedup 1.0000x reference)
#include <cuda_runtime.h>
#include <cuda_bf16.h>
#include <cuda_fp16.h>
#include <math.h>
#include <stdint.h>

// Problem constants
#define DMODEL 768
#define NTOK   2048          // B*N = 2*1024
#define NSEQ   1024
#define NHEAD  12
#define HDIM   64
#define NLAYER 12
#define NVOCAB 50257

#define KS 40                 // gemm smem k-stride in 16-bit elems (conflict-free)
#define TILE_E (128 * KS)     // elems per smem tile array
#define KSQ 72                // flash Q/K smem stride (64+8)
#define KSVR 72               // flash V row-major smem stride (64+8)

typedef __half f16;

// ---------------------------------------------------------------------------
// Device-global scratch (allocation-free)
// ---------------------------------------------------------------------------
__device__ float g_x[NTOK * DMODEL];                  // residual stream (fp32)
__device__ float g_part[3L * NTOK * DMODEL];          // split-K partials (fp32)

// activations, fp16 hi/lo (lo = A-side correction term)
__device__ f16 g_lnh[NTOK * DMODEL],      g_lnl[NTOK * DMODEL];
__device__ f16 g_qkvh[NTOK * 3 * DMODEL], g_qkvl[NTOK * 3 * DMODEL];
__device__ f16 g_attnh[NTOK * DMODEL],    g_attnl[NTOK * DMODEL];
__device__ f16 g_midh[NTOK * 4 * DMODEL], g_midl[NTOK * 4 * DMODEL];

// final-LN output in fp16 (lm_head only)
__device__ f16 g_lnf16[NTOK * DMODEL];

// weights, transposed to [N,K], fp16 (hi only — B side is single-term)
__device__ f16 g_wqkvh[NLAYER * 3 * DMODEL * DMODEL];
__device__ f16 g_waph [NLAYER * DMODEL * DMODEL];
__device__ f16 g_wfch [NLAYER * 4 * DMODEL * DMODEL];
__device__ f16 g_wmph [NLAYER * DMODEL * 4 * DMODEL];
__device__ f16 g_wtef[(long)NVOCAB * DMODEL];         // wte in fp16 (lm_head)

// ---------------------------------------------------------------------------
// Helpers
// ---------------------------------------------------------------------------
__device__ __forceinline__ float blockReduceSum(float v) {
    __shared__ float sh[8];
    int lane = threadIdx.x & 31, w = threadIdx.x >> 5;
#pragma unroll
    for (int o = 16; o; o >>= 1) v += __shfl_xor_sync(0xffffffffu, v, o);
    __syncthreads();
    if (lane == 0) sh[w] = v;
    __syncthreads();
    if (threadIdx.x == 0) {
        float s = sh[0];
#pragma unroll
        for (int i = 1; i < 8; i++) s += sh[i];
        sh[0] = s;
    }
    __syncthreads();
    return sh[0];
}

__device__ __forceinline__ void cp16(uint32_t saddr, const void* gaddr) {
    asm volatile("cp.async.cg.shared.global [%0], [%1], 16;\n"
                 :: "r"(saddr), "l"(gaddr));
}

__device__ __forceinline__ void mma16816h(float* d, const uint32_t* a, const uint32_t* b) {
    asm volatile(
        "mma.sync.aligned.m16n8k16.row.col.f32.f16.f16.f32 "
        "{%0,%1,%2,%3},{%4,%5,%6,%7},{%8,%9},{%0,%1,%2,%3};\n"
        : "+f"(d[0]), "+f"(d[1]), "+f"(d[2]), "+f"(d[3])
        : "r"(a[0]), "r"(a[1]), "r"(a[2]), "r"(a[3]), "r"(b[0]), "r"(b[1]));
}

__device__ __forceinline__ void ldm4(uint32_t* r, uint32_t addr) {
    asm volatile("ldmatrix.sync.aligned.m8n8.x4.shared.b16 {%0,%1,%2,%3}, [%4];\n"
                 : "=r"(r[0]), "=r"(r[1]), "=r"(r[2]), "=r"(r[3]) : "r"(addr));
}

__device__ __forceinline__ void ldm4t(uint32_t* r, uint32_t addr) {
    asm volatile("ldmatrix.sync.aligned.m8n8.x4.trans.shared.b16 {%0,%1,%2,%3}, [%4];\n"
                 : "=r"(r[0]), "=r"(r[1]), "=r"(r[2]), "=r"(r[3]) : "r"(addr));
}

__device__ __forceinline__ uint32_t pack2h(float a, float b) {
    __half2 t = __floats2half2_rn(a, b);
    return *(uint32_t*)&t;
}
__device__ __forceinline__ uint32_t packlo2h(float a, float b) {
    float la = a - __half2float(__float2half(a));
    float lb = b - __half2float(__float2half(b));
    return pack2h(la, lb);
}

// ---------------------------------------------------------------------------
// Weight prep: transpose W[z][K][N] -> T[z][N][K], fp16 (hi only)
// ---------------------------------------------------------------------------
__global__ void tsplit_kernel(const float* __restrict__ W,
                              f16* __restrict__ Th, int K, int N) {
    __shared__ float t[32][33];
    long zoff = (long)blockIdx.z * K * N;
    W += zoff; Th += zoff;
    int k0 = blockIdx.x * 32, n0 = blockIdx.y * 32;
    int tx = threadIdx.x, ty = threadIdx.y;
#pragma unroll
    for (int i = 0; i < 4; i++)
        t[ty + i * 8][tx] = W[(long)(k0 + ty + i * 8) * N + n0 + tx];
    __syncthreads();
#pragma unroll
    for (int i = 0; i < 4; i++) {
        int n = n0 + ty + i * 8, k = k0 + tx;
        Th[(long)n * K + k] = __float2half(t[tx][ty + i * 8]);
    }
}

// Elementwise fp32 -> fp16 (wte is already [V, D] = [N, K])
__global__ void splitf16_kernel(const float* __restrict__ in,
                                f16* __restrict__ o, long n) {
    long i = (long)blockIdx.x * 256 + threadIdx.x;
    if (i < n) o[i] = __float2half(in[i]);
}

// ---------------------------------------------------------------------------
// Embedding
// ---------------------------------------------------------------------------
__global__ void embed_kernel(const int* __restrict__ tok,
                             const float* __restrict__ wte,
                             const float* __restrict__ wpe,
                             float* __restrict__ x) {
    int t = blockIdx.x;
    int n = t & (NSEQ - 1);
    int id = tok[t];
    const float* w1 = wte + (long)id * DMODEL;
    const float* w2 = wpe + (long)n * DMODEL;
    float* xo = x + (long)t * DMODEL;
    for (int d = threadIdx.x; d < DMODEL; d += blockDim.x)
        xo[d] = w1[d] + w2[d];
}

// ---------------------------------------------------------------------------
// LayerNorm: fp32 in -> fp16 hi/lo out (standalone; used once at start)
// ---------------------------------------------------------------------------
__global__ __launch_bounds__(256) void layernorm_kernel(
    const float* __restrict__ x, const float* __restrict__ w,
    const float* __restrict__ b,
    f16* __restrict__ oh, f16* __restrict__ ol) {
    int t = blockIdx.x;
    const float* xr = x + (long)t * DMODEL;
    int tid = threadIdx.x;

    float lx[3];
    float s = 0.f;
#pragma unroll
    for (int i = 0; i < 3; i++) { lx[i] = xr[tid + i * 256]; s += lx[i]; }
    s = blockReduceSum(s);
    float mu = s * (1.f / 768.f);

    float var = 0.f;
#pragma unroll
    for (int i = 0; i < 3; i++) { float d = lx[i] - mu; var += d * d; }
    var = blockReduceSum(var);
    float rstd = rsqrtf(var * (1.f / 768.f) + 1e-5f);

#pragma unroll
    for (int i = 0; i < 3; i++) {
        int d = tid + i * 256;
        float v = (lx[i] - mu) * rstd * w[d] + b[d];
        f16 h = __float2half(v);
        oh[(long)t * DMODEL + d] = h;
        ol[(long)t * DMODEL + d] = __float2half(v - __half2float(h));
    }
}

// ---------------------------------------------------------------------------
// Fused split-K reduce + residual + bias + LayerNorm.
//   x[t][d] += bias[d] + part0 + part1 + part2;  then LN(x) -> oh/ol (hi/lo)
// ---------------------------------------------------------------------------
__global__ __launch_bounds__(256) void reduce_ln_kernel(
    float* __restrict__ x, const float* __restrict__ part,
    const float* __restrict__ bias,
    const float* __restrict__ w, const float* __restrict__ b,
    f16* __restrict__ oh, f16* __restrict__ ol) {
    int t = blockIdx.x, tid = threadIdx.x;
    long base = (long)t * DMODEL;
    const long PS = (long)NTOK * DMODEL;

    float lx[3];
    float s = 0.f;
#pragma unroll
    for (int i = 0; i < 3; i++) {
        int d = tid + i * 256;
        float v = x[base + d] + bias[d]
                + part[base + d] + part[PS + base + d] + part[2 * PS + base + d];
        x[base + d] = v;
        lx[i] = v;
        s += v;
    }
    s = blockReduceSum(s);
    float mu = s * (1.f / 768.f);

    float var = 0.f;
#pragma unroll
    for (int i = 0; i < 3; i++) { float d = lx[i] - mu; var += d * d; }
    var = blockReduceSum(var);
    float rstd = rsqrtf(var * (1.f / 768.f) + 1e-5f);

#pragma unroll
    for (int i = 0; i < 3; i++) {
        int d = tid + i * 256;
        float v = (lx[i] - mu) * rstd * w[d] + b[d];
        f16 h = __float2half(v);
        oh[base + d] = h;
        ol[base + d] = __float2half(v - __half2float(h));
    }
}

// Same, but LN output single fp16 (final LN feeding lm_head)
__global__ __launch_bounds__(256) void reduce_lnf_kernel(
    float* __restrict__ x, const float* __restrict__ part,
    const float* __restrict__ bias,
    const float* __restrict__ w, const float* __restrict__ b,
    f16* __restrict__ o) {
    int t = blockIdx.x, tid = threadIdx.x;
    long base = (long)t * DMODEL;
    const long PS = (long)NTOK * DMODEL;

    float lx[3];
    float s = 0.f;
#pragma unroll
    for (int i = 0; i < 3; i++) {
        int d = tid + i * 256;
        float v = x[base + d] + bias[d]
                + part[base + d] + part[PS + base + d] + part[2 * PS + base + d];
        lx[i] = v;
        s += v;
    }
    s = blockReduceSum(s);
    float mu = s * (1.f / 768.f);

    float var = 0.f;
#pragma unroll
    for (int i = 0; i < 3; i++) { float d = lx[i] - mu; var += d * d; }
    var = blockReduceSum(var);
    float rstd = rsqrtf(var * (1.f / 768.f) + 1e-5f);

#pragma unroll
    for (int i = 0; i < 3; i++) {
        int d = tid + i * 256;
        float v = (lx[i] - mu) * rstd * w[d] + b[d];
        o[base + d] = __float2half(v);
    }
}

// ---------------------------------------------------------------------------
// Flash attention, fp16 2-term: S = Qh.Kh + Ql.Kh ; O += Ph.Vh + Pl.Vh.
// One block per (q-tile of 128 rows, head z); 8 warps, 16 q-rows each.
// Smem: Qh, Ql, Kh [128*KSQ each] + V row-major [128*KSVR] (ldmatrix.trans).
// ---------------------------------------------------------------------------
__global__ __launch_bounds__(256) void flash_kernel(
    const f16* __restrict__ qkvh, const f16* __restrict__ qkvl,
    f16* __restrict__ attnh, f16* __restrict__ attnl) {

    int qi = blockIdx.x;
    int z = blockIdx.y;
    int b = z / NHEAD, h = z - b * NHEAD;
    const int rs = 3 * DMODEL;
    long base = (long)b * NSEQ * rs + h * HDIM;

    extern __shared__ f16 SM[];
    uint32_t u0 = (uint32_t)__cvta_generic_to_shared(SM);
    const uint32_t uQh = u0;
    const uint32_t uQl = uQh + 128 * KSQ * 2;
    const uint32_t uKh = uQl + 128 * KSQ * 2;
    const uint32_t uVh = uKh + 128 * KSQ * 2;

    int tid = threadIdx.x, lane = tid & 31, wq = tid >> 5;
    int fr = lane >> 2, fc = lane & 3;

    // ---- load Q tile (cp.async, hi/lo) ----
    {
        int r = tid >> 1, c0 = (tid & 1) * 32;
        const f16* g = qkvh + base + (long)(qi * 128 + r) * rs + c0;
        uint32_t s = uQh + (r * KSQ + c0) * 2;
        cp16(s, g); cp16(s + 16, g + 8); cp16(s + 32, g + 16); cp16(s + 48, g + 24);
        g = qkvl + base + (long)(qi * 128 + r) * rs + c0;
        s = uQl + (r * KSQ + c0) * 2;
        cp16(s, g); cp16(s + 16, g + 8); cp16(s + 32, g + 16); cp16(s + 48, g + 24);
        asm volatile("cp.async.commit_group;\n" ::: "memory");
    }

    float m0 = -1e30f, m1 = -1e30f, l0 = 0.f, l1 = 0.f;
    float o[8][4] = {};

    for (int kt = 0; kt <= qi; kt++) {
        __syncthreads();

        // ---- load K tile hi + V tile (both cp.async, one group) ----
        {
            int r = tid >> 1, c0 = (tid & 1) * 32;
            const f16* g = qkvh + base + DMODEL + (long)(kt * 128 + r) * rs + c0;
            uint32_t s = uKh + (r * KSQ + c0) * 2;
            cp16(s, g); cp16(s + 16, g + 8); cp16(s + 32, g + 16); cp16(s + 48, g + 24);
            g = qkvh + base + 2 * DMODEL + (long)(kt * 128 + r) * rs + c0;
            s = uVh + (r * KSVR + c0) * 2;
            cp16(s, g); cp16(s + 16, g + 8); cp16(s + 32, g + 16); cp16(s + 48, g + 24);
            asm volatile("cp.async.commit_group;\n" ::: "memory");
        }
        asm volatile("cp.async.wait_group 0;\n" ::: "memory");
        __syncthreads();

        // ---- S = Q @ K^T (2-term fp16) ----
        float ss[16][4];
#pragma unroll
        for (int i = 0; i < 16; i++)
#pragma unroll
            for (int r = 0; r < 4; r++) ss[i][r] = 0.f;

#pragma unroll
        for (int ks4 = 0; ks4 < 4; ks4++) {
            int ks = ks4 * 16;
            uint32_t ah[4], al[4];
            uint32_t aoff = ((wq * 16 + (lane & 15)) * KSQ + ks + ((lane >> 4) << 3)) * 2;
            ldm4(ah, uQh + aoff);
            ldm4(al, uQl + aoff);
#pragma unroll
            for (int nip = 0; nip < 8; nip++) {
                uint32_t bh[4];
                uint32_t boff = ((nip * 16 + ((lane >> 4) << 3) + (lane & 7)) * KSQ
                                 + ks + (((lane >> 3) & 1) << 3)) * 2;
                ldm4(bh, uKh + boff);
                int ni = nip * 2;
                mma16816h(ss[ni], ah, bh);     mma16816h(ss[ni + 1], ah, bh + 2);
                mma16816h(ss[ni], al, bh);     mma16816h(ss[ni + 1], al, bh + 2);
            }
        }

        // ---- scale + causal mask ----
#pragma unroll
        for (int i = 0; i < 16; i++)
#pragma unroll
            for (int r = 0; r < 4; r++) ss[i][r] *= 0.125f;
        if (kt == qi) {
#pragma unroll
            for (int i = 0; i < 16; i++)
#pragma unroll
                for (int r = 0; r < 4; r++) {
                    int col = i * 8 + fc * 2 + (r & 1);
                    int row = wq * 16 + fr + ((r >> 1) << 3);
                    if (col > row) ss[i][r] = -1e30f;
                }
        }

        // ---- online softmax ----
        float mx0 = -1e30f, mx1 = -1e30f;
#pragma unroll
        for (int i = 0; i < 16; i++) {
            mx0 = fmaxf(mx0, fmaxf(ss[i][0], ss[i][1]));
            mx1 = fmaxf(mx1, fmaxf(ss[i][2], ss[i][3]));
        }
        mx0 = fmaxf(mx0, __shfl_xor_sync(0xffffffffu, mx0, 1));
        mx0 = fmaxf(mx0, __shfl_xor_sync(0xffffffffu, mx0, 2));
        mx1 = fmaxf(mx1, __shfl_xor_sync(0xffffffffu, mx1, 1));
        mx1 = fmaxf(mx1, __shfl_xor_sync(0xffffffffu, mx1, 2));

        float mn0 = fmaxf(m0, mx0), mn1 = fmaxf(m1, mx1);
        float al0 = __expf(m0 - mn0), al1 = __expf(m1 - mn1);
        float sum0 = 0.f, sum1 = 0.f;
#pragma unroll
        for (int i = 0; i < 16; i++) {
            ss[i][0] = __expf(ss[i][0] - mn0); sum0 += ss[i][0];
            ss[i][1] = __expf(ss[i][1] - mn0); sum0 += ss[i][1];
            ss[i][2] = __expf(ss[i][2] - mn1); sum1 += ss[i][2];
            ss[i][3] = __expf(ss[i][3] - mn1); sum1 += ss[i][3];
        }
        sum0 += __shfl_xor_sync(0xffffffffu, sum0, 1);
        sum0 += __shfl_xor_sync(0xffffffffu, sum0, 2);
        sum1 += __shfl_xor_sync(0xffffffffu, sum1, 1);
        sum1 += __shfl_xor_sync(0xffffffffu, sum1, 2);
        l0 = l0 * al0 + sum0;
        l1 = l1 * al1 + sum1;
        m0 = mn0; m1 = mn1;
#pragma unroll
        for (int v = 0; v < 8; v++) {
            o[v][0] *= al0; o[v][1] *= al0;
            o[v][2] *= al1; o[v][3] *= al1;
        }

        // ---- O += P @ V (P hi/lo fp16 from regs, V via ldmatrix.trans) ----
        int g8 = lane >> 3;                    // 0..3
        int koff = (g8 & 1) * 8 + (lane & 7);  // source k-row within 16
        int noff = (g8 >> 1) * 8;              // source n-col base within 16
#pragma unroll
        for (int ks = 0; ks < 8; ks++) {
            uint32_t ahi[4], alo[4];
            ahi[0] = pack2h(ss[2 * ks][0], ss[2 * ks][1]);
            ahi[1] = pack2h(ss[2 * ks][2], ss[2 * ks][3]);
            ahi[2] = pack2h(ss[2 * ks + 1][0], ss[2 * ks + 1][1]);
            ahi[3] = pack2h(ss[2 * ks + 1][2], ss[2 * ks + 1][3]);
            alo[0] = packlo2h(ss[2 * ks][0], ss[2 * ks][1]);
            alo[1] = packlo2h(ss[2 * ks][2], ss[2 * ks][3]);
            alo[2] = packlo2h(ss[2 * ks + 1][0], ss[2 * ks + 1][1]);
            alo[3] = packlo2h(ss[2 * ks + 1][2], ss[2 * ks + 1][3]);
#pragma unroll
            for (int nvp = 0; nvp < 4; nvp++) {
                uint32_t bv[4];
                uint32_t boff = ((ks * 16 + koff) * KSVR + nvp * 16 + noff) * 2;
                ldm4t(bv, uVh + boff);
                int nv = nvp * 2;
                mma16816h(o[nv], ahi, bv);     mma16816h(o[nv + 1], ahi, bv + 2);
                mma16816h(o[nv], alo, bv);     mma16816h(o[nv + 1], alo, bv + 2);
            }
        }
    }

    // ---- epilogue: O /= l, write fp16 hi/lo ----
    float inv0 = 1.f / l0, inv1 = 1.f / l1;
    int row0 = qi * 128 + wq * 16 + fr;
#pragma unroll
    for (int v = 0; v < 8; v++) {
#pragma unroll
        for (int r = 0; r < 4; r++) {
            int row = row0 + ((r >> 1) << 3);
            int col = h * HDIM + v * 8 + fc * 2 + (r & 1);
            float val = o[v][r] * ((r >> 1) ? inv1 : inv0);
            long gi = (long)(b * NSEQ + row) * DMODEL + col;
            f16 hh = __float2half(val);
            attnh[gi] = hh;
            attnl[gi] = __float2half(val - __half2float(hh));
        }
    }
}

// ---------------------------------------------------------------------------
// Tensor-core GEMM template (fp16), 3-stage cp.async pipeline, split-K.
//   NMMA=2: 2-term hi/lo (Ah/Al + Bh; acc = Ah.Bh + Al.Bh).
//   NMMA=1: single-term (Ah, Bh only).
//   A: [M,K], stride lda.  B: [N,K], stride ldb.  K = chunk size.
//   blockIdx.z selects K-chunk z: operands offset by z*K; C (fp32) offset by
//   z*M*ldc (partial buffer).  flags: 1=residual, 2=exact GELU,
//   8=write fp32 C, 16=write fp16 hi/lo.  Requires K >= 64 (KT >= 2).
// ---------------------------------------------------------------------------
template<int NMMA>
__global__ __launch_bounds__(256, 2) void bgemm_kernel(
    const uint16_t* __restrict__ Ah, const uint16_t* __restrict__ Al, int lda,
    const uint16_t* __restrict__ Bh, int ldb,
    float* __restrict__ C, f16* __restrict__ Ch, f16* __restrict__ Cl, int ldc,
    const float* __restrict__ bias,
    int M, int N, int K, int flags) {

    constexpr int TPS = (NMMA == 2) ? 3 : 2;             // tiles per stage
    constexpr int BH_OFF = (NMMA == 2) ? 2 * TILE_E : TILE_E;

    int m0 = blockIdx.y * 128, n0 = blockIdx.x * 128;

    // split-K offsets
    {
        long koff = (long)blockIdx.z * K;
        Ah += koff;
        if (NMMA == 2) Al += koff;
        Bh += koff;
        if (C) C += (long)blockIdx.z * (long)M * (long)ldc;
    }

    extern __shared__ uint16_t S[];
    uint32_t sbase = (uint32_t)__cvta_generic_to_shared(S);

    int tid = threadIdx.x, lane = tid & 31, wid = tid >> 5;
    int wm = wid & 1, wn = wid >> 1;
    int fr = lane >> 2, fc = lane & 3;

    int r2 = tid >> 1;
    int c2 = (tid & 1) * 16;

    float acc[4][4][4];
#pragma unroll
    for (int i = 0; i < 4; i++)
#pragma unroll
        for (int j = 0; j < 4; j++)
#pragma unroll
            for (int r = 0; r < 4; r++) acc[i][j][r] = 0.f;

    auto ldStage = [&](int k0, int st) {
        uint32_t sb = sbase + st * (TPS * TILE_E * 2);
        uint32_t sa = sb + r2 * (KS * 2) + c2 * 2;
        const uint16_t* ga = Ah + (long)(m0 + r2) * lda + k0 + c2;
        cp16(sa, ga);            cp16(sa + 16, ga + 8);
        if (NMMA == 2) {
            ga = Al + (long)(m0 + r2) * lda + k0 + c2;
            cp16(sa + TILE_E * 2, ga); cp16(sa + TILE_E * 2 + 16, ga + 8);
        }
        int gn = n0 + r2;
        uint32_t sbB = sb + BH_OFF * 2 + r2 * (KS * 2) + c2 * 2;
        if (gn < N) {
            const uint16_t* gb = Bh + (long)gn * ldb + k0 + c2;
            cp16(sbB, gb);            cp16(sbB + 16, gb + 8);
        } else {
            uint4 zz = make_uint4(0, 0, 0, 0);
            uint16_t* p = S + st * TPS * TILE_E + BH_OFF + r2 * KS + c2;
            *(uint4*)p = zz; *(uint4*)(p + 8) = zz;
        }
        asm volatile("cp.async.commit_group;\n" ::: "memory");
    };

    ldStage(0, 0);
    ldStage(32, 1);

    // per-thread ldmatrix address components (elem offsets)
    int aRow = wm * 64 + (lane & 15);
    int aColX = (lane >> 4) << 3;
    int bRow = wn * 32 + ((lane >> 4) << 3) + (lane & 7);
    int bColX = ((lane >> 3) & 1) << 3;

    int KT = K >> 5;
    for (int kt = 0; kt < KT; kt++) {
        if (kt + 1 < KT)
            asm volatile("cp.async.wait_group 1;\n" ::: "memory");
        else
            asm volatile("cp.async.wait_group 0;\n" ::: "memory");
        __syncthreads();
        if (kt + 2 < KT) ldStage((kt + 2) << 5, (kt + 2) % 3);

        uint32_t sb = sbase + (kt % 3) * (TPS * TILE_E * 2);

#pragma unroll
        for (int ks = 0; ks < 32; ks += 16) {
            uint32_t ah[4][4], bh[4][2];
            uint32_t aA = sb + (aRow * KS + ks + aColX) * 2;
            uint32_t bB = sb + BH_OFF * 2 + (bRow * KS + ks + bColX) * 2;
#pragma unroll
            for (int mi = 0; mi < 4; mi++) ldm4(ah[mi], aA + mi * (16 * KS * 2));
#pragma unroll
            for (int nip = 0; nip < 2; nip++)
                ldm4(&bh[nip * 2][0], bB + nip * (16 * KS * 2));

#pragma unroll
            for (int mi = 0; mi < 4; mi++)
#pragma unroll
                for (int ni = 0; ni < 4; ni++)
                    mma16816h(acc[mi][ni], ah[mi], bh[ni]);

            if (NMMA == 2) {
                uint32_t al[4][4];
#pragma unroll
                for (int mi = 0; mi < 4; mi++)
                    ldm4(al[mi], aA + mi * (16 * KS * 2) + TILE_E * 2);
#pragma unroll
                for (int mi = 0; mi < 4; mi++)
#pragma unroll
                    for (int ni = 0; ni < 4; ni++)
                        mma16816h(acc[mi][ni], al[mi], bh[ni]);
            }
        }
    }

    // Epilogue
#pragma unroll
    for (int mi = 0; mi < 4; mi++) {
        int gm0 = m0 + wm * 64 + mi * 16 + fr;
#pragma unroll
        for (int ni = 0; ni < 4; ni++) {
            int gn = n0 + wn * 32 + ni * 8 + fc * 2;
#pragma unroll
            for (int r = 0; r < 4; r++) {
                int gm = gm0 + (r >= 2 ? 8 : 0);
                int gc = gn + (r & 1);
                if (gc < N) {
                    float v = acc[mi][ni][r];
                    if (bias) v += bias[gc];
                    if (flags & 2) v = 0.5f * v * (1.f + erff(v * 0.70710678118654752f));
                    long idx = (long)gm * ldc + gc;
                    if (flags & 1) v += C[idx];
                    if (flags & 8) C[idx] = v;
                    if (flags & 16) {
                        f16 h = __float2half(v);
                        Ch[idx] = h;
                        Cl[idx] = __float2half(v - __half2float(h));
                    }
                }
            }
        }
    }
}

// ---------------------------------------------------------------------------
// Host-side orchestration
// ---------------------------------------------------------------------------
extern "C" void kernel_launch(void* const* d_in, const int* in_sizes, int n_in,
                              void* d_out, int out_size) {
    (void)in_sizes; (void)n_in; (void)out_size;

    const int*   tok     = (const int*)  d_in[0];
    const float* wte     = (const float*)d_in[1];
    const float* wpe     = (const float*)d_in[2];
    const float* ln1_w   = (const float*)d_in[3];
    const float* ln1_b   = (const float*)d_in[4];
    const float* attn_w  = (const float*)d_in[5];
    const float* attn_b  = (const float*)d_in[6];
    const float* aproj_w = (const float*)d_in[7];
    const float* aproj_b = (const float*)d_in[8];
    const float* ln2_w   = (const float*)d_in[9];
    const float* ln2_b   = (const float*)d_in[10];
    const float* fc_w    = (const float*)d_in[11];
    const float* fc_b    = (const float*)d_in[12];
    const float* mproj_w = (const float*)d_in[13];
    const float* mproj_b = (const float*)d_in[14];
    const float* lnf_w   = (const float*)d_in[15];
    const float* lnf_b   = (const float*)d_in[16];
    float* out = (float*)d_out;

    float *x, *part;
    f16 *lnh, *lnl, *qkvh, *qkvl, *attnh, *attnl, *midh, *midl;
    f16 *wqkvh, *waph, *wfch, *wmph, *wtef, *lnf16;
    cudaGetSymbolAddress((void**)&x,      g_x);
    cudaGetSymbolAddress((void**)&part,   g_part);
    cudaGetSymbolAddress((void**)&lnh,    g_lnh);
    cudaGetSymbolAddress((void**)&lnl,    g_lnl);
    cudaGetSymbolAddress((void**)&qkvh,   g_qkvh);
    cudaGetSymbolAddress((void**)&qkvl,   g_qkvl);
    cudaGetSymbolAddress((void**)&attnh,  g_attnh);
    cudaGetSymbolAddress((void**)&attnl,  g_attnl);
    cudaGetSymbolAddress((void**)&midh,   g_midh);
    cudaGetSymbolAddress((void**)&midl,   g_midl);
    cudaGetSymbolAddress((void**)&wqkvh,  g_wqkvh);
    cudaGetSymbolAddress((void**)&waph,   g_waph);
    cudaGetSymbolAddress((void**)&wfch,   g_wfch);
    cudaGetSymbolAddress((void**)&wmph,   g_wmph);
    cudaGetSymbolAddress((void**)&wtef,   g_wtef);
    cudaGetSymbolAddress((void**)&lnf16,  g_lnf16);

    const int D = DMODEL;
    const int SMEM2 = 3 * 3 * TILE_E * 2;                  // 92160 (3 stages x 3 tiles)
    const int SMEM1 = 3 * 2 * TILE_E * 2;                  // 61440 (3 stages x 2 tiles)
    const int FSMEM = (3 * 128 * KSQ + 128 * KSVR) * 2;    // 73728

    cudaFuncSetAttribute(bgemm_kernel<2>,
                         cudaFuncAttributeMaxDynamicSharedMemorySize, SMEM2);
    cudaFuncSetAttribute(bgemm_kernel<1>,
                         cudaFuncAttributeMaxDynamicSharedMemorySize, SMEM1);
    cudaFuncSetAttribute(flash_kernel,
                         cudaFuncAttributeMaxDynamicSharedMemorySize, FSMEM);

    // ---- weight prep (once per call) ----
    {
        dim3 b32(32, 8);
        tsplit_kernel<<<dim3(D / 32, 3 * D / 32, NLAYER), b32>>>(attn_w,  wqkvh, D, 3 * D);
        tsplit_kernel<<<dim3(D / 32, D / 32, NLAYER),     b32>>>(aproj_w, waph,  D, D);
        tsplit_kernel<<<dim3(D / 32, 4 * D / 32, NLAYER), b32>>>(fc_w,    wfch,  D, 4 * D);
        tsplit_kernel<<<dim3(4 * D / 32, D / 32, NLAYER), b32>>>(mproj_w, wmph,  4 * D, D);
        long nwte = (long)NVOCAB * D;
        splitf16_kernel<<<(unsigned)((nwte + 255) / 256), 256>>>(wte, wtef, nwte);
    }

    embed_kernel<<<NTOK, 256>>>(tok, wte, wpe, x);
    layernorm_kernel<<<NTOK, 256>>>(x, ln1_w, ln1_b, lnh, lnl);  // layer-0 ln1

    for (int l = 0; l < NLAYER; l++) {
        // qkv = h @ attn_w[l] + attn_b[l] -> fp16 hi/lo
        {
            dim3 g(3 * D / 128, NTOK / 128);
            bgemm_kernel<2><<<g, 256, SMEM2>>>(
                (const uint16_t*)lnh, (const uint16_t*)lnl, D,
                (const uint16_t*)(wqkvh + (long)l * 3 * D * D), D,
                nullptr, qkvh, qkvl, 3 * D,
                attn_b + (long)l * 3 * D,
                NTOK, 3 * D, D, 16);
        }

        // fused flash attention -> attnh/attnl
        flash_kernel<<<dim3(NSEQ / 128, 2 * NHEAD), 256, FSMEM>>>(qkvh, qkvl, attnh, attnl);

        // aproj: split-K=3 (K=768 -> 3x256) into partials
        {
            dim3 g(D / 128, NTOK / 128, 3);
            bgemm_kernel<2><<<g, 256, SMEM2>>>(
                (const uint16_t*)attnh, (const uint16_t*)attnl, D,
                (const uint16_t*)(waph + (long)l * D * D), D,
                part, nullptr, nullptr, D,
                nullptr,
                NTOK, D, D / 3, 8);
        }
        // x += sum(parts) + aproj_b; ln2 -> lnh/lnl
        reduce_ln_kernel<<<NTOK, 256>>>(x, part, aproj_b + (long)l * D,
                                        ln2_w + l * D, ln2_b + l * D, lnh, lnl);

        // mid = gelu(h @ fc_w[l] + fc_b[l]) -> fp16 hi/lo
        {
            dim3 g(4 * D / 128, NTOK / 128);
            bgemm_kernel<2><<<g, 256, SMEM2>>>(
                (const uint16_t*)lnh, (const uint16_t*)lnl, D,
                (const uint16_t*)(wfch + (long)l * 4 * D * D), D,
                nullptr, midh, midl, 4 * D,
                fc_b + (long)l * 4 * D,
                NTOK, 4 * D, D, 2 | 16);
        }

        // mproj: split-K=3 (K=3072 -> 3x1024) into partials
        {
            dim3 g(D / 128, NTOK / 128, 3);
            bgemm_kernel<2><<<g, 256, SMEM2>>>(
                (const uint16_t*)midh, (const uint16_t*)midl, 4 * D,
                (const uint16_t*)(wmph + (long)l * D * 4 * D), 4 * D,
                part, nullptr, nullptr, D,
                nullptr,
                NTOK, D, 4 * D / 3, 8);
        }
        // x += sum(parts) + mproj_b; next LN
        if (l + 1 < NLAYER) {
            reduce_ln_kernel<<<NTOK, 256>>>(x, part, mproj_b + (long)l * D,
                                            ln1_w + (l + 1) * D, ln1_b + (l + 1) * D,
                                            lnh, lnl);
        } else {
            reduce_lnf_kernel<<<NTOK, 256>>>(x, part, mproj_b + (long)l * D,
                                             lnf_w, lnf_b, lnf16);
        }
    }

    // tied lm_head in single-term fp16: out = LN_f(x) @ wte^T
    {
        dim3 g((NVOCAB + 127) / 128, NTOK / 128);
        bgemm_kernel<1><<<g, 256, SMEM1>>>(
            (const uint16_t*)lnf16, nullptr, D,
            (const uint16_t*)wtef, D,
            out, nullptr, nullptr, NVOCAB,
            nullptr,
            NTOK, NVOCAB, D, 8);
    }
}

// round 12
// speedup vs baseline: 1.3332x; 1.3332x over previous
#include <cuda_runtime.h>
#include <cuda_bf16.h>
#include <cuda_fp16.h>
#include <math.h>
#include <stdint.h>

// Problem constants
#define DMODEL 768
#define NTOK   2048          // B*N = 2*1024
#define NSEQ   1024
#define NHEAD  12
#define HDIM   64
#define NLAYER 12
#define NVOCAB 50257

#define KS 40                 // gemm smem k-stride in 16-bit elems (conflict-free)
#define TILE_E (128 * KS)     // elems per smem tile array
#define KSQ 72                // flash Q/K smem stride (64+8)
#define KSVR 72               // flash V row-major smem stride (64+8)

typedef __half f16;

// ---------------------------------------------------------------------------
// Device-global scratch (allocation-free)
// ---------------------------------------------------------------------------
__device__ float g_x[NTOK * DMODEL];                  // residual stream (fp32)

// activations, fp16 hi/lo (lo = A-side correction term)
__device__ f16 g_lnh[NTOK * DMODEL],      g_lnl[NTOK * DMODEL];
__device__ f16 g_qkvh[NTOK * 3 * DMODEL], g_qkvl[NTOK * 3 * DMODEL];
__device__ f16 g_attnh[NTOK * DMODEL],    g_attnl[NTOK * DMODEL];
__device__ f16 g_midh[NTOK * 4 * DMODEL], g_midl[NTOK * 4 * DMODEL];

// final-LN output in fp16 (lm_head only)
__device__ f16 g_lnf16[NTOK * DMODEL];

// weights, transposed to [N,K], fp16 (hi only — B side is single-term)
__device__ f16 g_wqkvh[NLAYER * 3 * DMODEL * DMODEL];
__device__ f16 g_waph [NLAYER * DMODEL * DMODEL];
__device__ f16 g_wfch [NLAYER * 4 * DMODEL * DMODEL];
__device__ f16 g_wmph [NLAYER * DMODEL * 4 * DMODEL];
__device__ f16 g_wtef[(long)NVOCAB * DMODEL];         // wte in fp16 (lm_head)

// ---------------------------------------------------------------------------
// Helpers
// ---------------------------------------------------------------------------
__device__ __forceinline__ float blockReduceSum(float v) {
    __shared__ float sh[8];
    int lane = threadIdx.x & 31, w = threadIdx.x >> 5;
#pragma unroll
    for (int o = 16; o; o >>= 1) v += __shfl_xor_sync(0xffffffffu, v, o);
    __syncthreads();
    if (lane == 0) sh[w] = v;
    __syncthreads();
    if (threadIdx.x == 0) {
        float s = sh[0];
#pragma unroll
        for (int i = 1; i < 8; i++) s += sh[i];
        sh[0] = s;
    }
    __syncthreads();
    return sh[0];
}

__device__ __forceinline__ void cp16(uint32_t saddr, const void* gaddr) {
    asm volatile("cp.async.cg.shared.global [%0], [%1], 16;\n"
                 :: "r"(saddr), "l"(gaddr));
}

__device__ __forceinline__ void mma16816h(float* d, const uint32_t* a, const uint32_t* b) {
    asm volatile(
        "mma.sync.aligned.m16n8k16.row.col.f32.f16.f16.f32 "
        "{%0,%1,%2,%3},{%4,%5,%6,%7},{%8,%9},{%0,%1,%2,%3};\n"
        : "+f"(d[0]), "+f"(d[1]), "+f"(d[2]), "+f"(d[3])
        : "r"(a[0]), "r"(a[1]), "r"(a[2]), "r"(a[3]), "r"(b[0]), "r"(b[1]));
}

__device__ __forceinline__ void ldm4(uint32_t* r, uint32_t addr) {
    asm volatile("ldmatrix.sync.aligned.m8n8.x4.shared.b16 {%0,%1,%2,%3}, [%4];\n"
                 : "=r"(r[0]), "=r"(r[1]), "=r"(r[2]), "=r"(r[3]) : "r"(addr));
}

__device__ __forceinline__ void ldm4t(uint32_t* r, uint32_t addr) {
    asm volatile("ldmatrix.sync.aligned.m8n8.x4.trans.shared.b16 {%0,%1,%2,%3}, [%4];\n"
                 : "=r"(r[0]), "=r"(r[1]), "=r"(r[2]), "=r"(r[3]) : "r"(addr));
}

__device__ __forceinline__ uint32_t pack2h(float a, float b) {
    __half2 t = __floats2half2_rn(a, b);
    return *(uint32_t*)&t;
}
__device__ __forceinline__ uint32_t packlo2h(float a, float b) {
    float la = a - __half2float(__float2half(a));
    float lb = b - __half2float(__float2half(b));
    return pack2h(la, lb);
}

// ---------------------------------------------------------------------------
// Weight prep: transpose W[z][K][N] -> T[z][N][K], fp16 (hi only)
// ---------------------------------------------------------------------------
__global__ void tsplit_kernel(const float* __restrict__ W,
                              f16* __restrict__ Th, int K, int N) {
    __shared__ float t[32][33];
    long zoff = (long)blockIdx.z * K * N;
    W += zoff; Th += zoff;
    int k0 = blockIdx.x * 32, n0 = blockIdx.y * 32;
    int tx = threadIdx.x, ty = threadIdx.y;
#pragma unroll
    for (int i = 0; i < 4; i++)
        t[ty + i * 8][tx] = W[(long)(k0 + ty + i * 8) * N + n0 + tx];
    __syncthreads();
#pragma unroll
    for (int i = 0; i < 4; i++) {
        int n = n0 + ty + i * 8, k = k0 + tx;
        Th[(long)n * K + k] = __float2half(t[tx][ty + i * 8]);
    }
}

// Elementwise fp32 -> fp16 (wte is already [V, D] = [N, K])
__global__ void splitf16_kernel(const float* __restrict__ in,
                                f16* __restrict__ o, long n) {
    long i = (long)blockIdx.x * 256 + threadIdx.x;
    if (i < n) o[i] = __float2half(in[i]);
}

// ---------------------------------------------------------------------------
// Embedding
// ---------------------------------------------------------------------------
__global__ void embed_kernel(const int* __restrict__ tok,
                             const float* __restrict__ wte,
                             const float* __restrict__ wpe,
                             float* __restrict__ x) {
    int t = blockIdx.x;
    int n = t & (NSEQ - 1);
    int id = tok[t];
    const float* w1 = wte + (long)id * DMODEL;
    const float* w2 = wpe + (long)n * DMODEL;
    float* xo = x + (long)t * DMODEL;
    for (int d = threadIdx.x; d < DMODEL; d += blockDim.x)
        xo[d] = w1[d] + w2[d];
}

// ---------------------------------------------------------------------------
// LayerNorm: fp32 in -> fp16 hi/lo out
// ---------------------------------------------------------------------------
__global__ __launch_bounds__(256) void layernorm_kernel(
    const float* __restrict__ x, const float* __restrict__ w,
    const float* __restrict__ b,
    f16* __restrict__ oh, f16* __restrict__ ol) {
    int t = blockIdx.x;
    const float* xr = x + (long)t * DMODEL;
    int tid = threadIdx.x;

    float lx[3];
    float s = 0.f;
#pragma unroll
    for (int i = 0; i < 3; i++) { lx[i] = xr[tid + i * 256]; s += lx[i]; }
    s = blockReduceSum(s);
    float mu = s * (1.f / 768.f);

    float var = 0.f;
#pragma unroll
    for (int i = 0; i < 3; i++) { float d = lx[i] - mu; var += d * d; }
    var = blockReduceSum(var);
    float rstd = rsqrtf(var * (1.f / 768.f) + 1e-5f);

#pragma unroll
    for (int i = 0; i < 3; i++) {
        int d = tid + i * 256;
        float v = (lx[i] - mu) * rstd * w[d] + b[d];
        f16 h = __float2half(v);
        oh[(long)t * DMODEL + d] = h;
        ol[(long)t * DMODEL + d] = __float2half(v - __half2float(h));
    }
}

// LayerNorm: fp32 in -> fp16 out (final LN, feeds fp16 lm_head)
__global__ __launch_bounds__(256) void layernorm_f16_kernel(
    const float* __restrict__ x, const float* __restrict__ w,
    const float* __restrict__ b, f16* __restrict__ o) {
    int t = blockIdx.x;
    const float* xr = x + (long)t * DMODEL;
    int tid = threadIdx.x;

    float lx[3];
    float s = 0.f;
#pragma unroll
    for (int i = 0; i < 3; i++) { lx[i] = xr[tid + i * 256]; s += lx[i]; }
    s = blockReduceSum(s);
    float mu = s * (1.f / 768.f);

    float var = 0.f;
#pragma unroll
    for (int i = 0; i < 3; i++) { float d = lx[i] - mu; var += d * d; }
    var = blockReduceSum(var);
    float rstd = rsqrtf(var * (1.f / 768.f) + 1e-5f);

#pragma unroll
    for (int i = 0; i < 3; i++) {
        int d = tid + i * 256;
        float v = (lx[i] - mu) * rstd * w[d] + b[d];
        o[(long)t * DMODEL + d] = __float2half(v);
    }
}

// ---------------------------------------------------------------------------
// Flash attention, fp16 2-term: S = Qh.Kh + Ql.Kh ; O += Ph.Vh + Pl.Vh.
// One block per (q-tile of 128 rows, head z); 8 warps, 16 q-rows each.
// Smem: Qh, Ql, Kh [128*KSQ each] + V row-major [128*KSVR] (ldmatrix.trans).
// ---------------------------------------------------------------------------
__global__ __launch_bounds__(256) void flash_kernel(
    const f16* __restrict__ qkvh, const f16* __restrict__ qkvl,
    f16* __restrict__ attnh, f16* __restrict__ attnl) {

    int qi = blockIdx.x;
    int z = blockIdx.y;
    int b = z / NHEAD, h = z - b * NHEAD;
    const int rs = 3 * DMODEL;
    long base = (long)b * NSEQ * rs + h * HDIM;

    extern __shared__ f16 SM[];
    uint32_t u0 = (uint32_t)__cvta_generic_to_shared(SM);
    const uint32_t uQh = u0;
    const uint32_t uQl = uQh + 128 * KSQ * 2;
    const uint32_t uKh = uQl + 128 * KSQ * 2;
    const uint32_t uVh = uKh + 128 * KSQ * 2;

    int tid = threadIdx.x, lane = tid & 31, wq = tid >> 5;
    int fr = lane >> 2, fc = lane & 3;

    // ---- load Q tile (cp.async, hi/lo) ----
    {
        int r = tid >> 1, c0 = (tid & 1) * 32;
        const f16* g = qkvh + base + (long)(qi * 128 + r) * rs + c0;
        uint32_t s = uQh + (r * KSQ + c0) * 2;
        cp16(s, g); cp16(s + 16, g + 8); cp16(s + 32, g + 16); cp16(s + 48, g + 24);
        g = qkvl + base + (long)(qi * 128 + r) * rs + c0;
        s = uQl + (r * KSQ + c0) * 2;
        cp16(s, g); cp16(s + 16, g + 8); cp16(s + 32, g + 16); cp16(s + 48, g + 24);
        asm volatile("cp.async.commit_group;\n" ::: "memory");
    }

    float m0 = -1e30f, m1 = -1e30f, l0 = 0.f, l1 = 0.f;
    float o[8][4] = {};

    for (int kt = 0; kt <= qi; kt++) {
        __syncthreads();

        // ---- load K tile hi + V tile (both cp.async, one group) ----
        {
            int r = tid >> 1, c0 = (tid & 1) * 32;
            const f16* g = qkvh + base + DMODEL + (long)(kt * 128 + r) * rs + c0;
            uint32_t s = uKh + (r * KSQ + c0) * 2;
            cp16(s, g); cp16(s + 16, g + 8); cp16(s + 32, g + 16); cp16(s + 48, g + 24);
            g = qkvh + base + 2 * DMODEL + (long)(kt * 128 + r) * rs + c0;
            s = uVh + (r * KSVR + c0) * 2;
            cp16(s, g); cp16(s + 16, g + 8); cp16(s + 32, g + 16); cp16(s + 48, g + 24);
            asm volatile("cp.async.commit_group;\n" ::: "memory");
        }
        asm volatile("cp.async.wait_group 0;\n" ::: "memory");
        __syncthreads();

        // ---- S = Q @ K^T (2-term fp16) ----
        float ss[16][4];
#pragma unroll
        for (int i = 0; i < 16; i++)
#pragma unroll
            for (int r = 0; r < 4; r++) ss[i][r] = 0.f;

#pragma unroll
        for (int ks4 = 0; ks4 < 4; ks4++) {
            int ks = ks4 * 16;
            uint32_t ah[4], al[4];
            uint32_t aoff = ((wq * 16 + (lane & 15)) * KSQ + ks + ((lane >> 4) << 3)) * 2;
            ldm4(ah, uQh + aoff);
            ldm4(al, uQl + aoff);
#pragma unroll
            for (int nip = 0; nip < 8; nip++) {
                uint32_t bh[4];
                uint32_t boff = ((nip * 16 + ((lane >> 4) << 3) + (lane & 7)) * KSQ
                                 + ks + (((lane >> 3) & 1) << 3)) * 2;
                ldm4(bh, uKh + boff);
                int ni = nip * 2;
                mma16816h(ss[ni], ah, bh);     mma16816h(ss[ni + 1], ah, bh + 2);
                mma16816h(ss[ni], al, bh);     mma16816h(ss[ni + 1], al, bh + 2);
            }
        }

        // ---- scale + causal mask ----
#pragma unroll
        for (int i = 0; i < 16; i++)
#pragma unroll
            for (int r = 0; r < 4; r++) ss[i][r] *= 0.125f;
        if (kt == qi) {
#pragma unroll
            for (int i = 0; i < 16; i++)
#pragma unroll
                for (int r = 0; r < 4; r++) {
                    int col = i * 8 + fc * 2 + (r & 1);
                    int row = wq * 16 + fr + ((r >> 1) << 3);
                    if (col > row) ss[i][r] = -1e30f;
                }
        }

        // ---- online softmax ----
        float mx0 = -1e30f, mx1 = -1e30f;
#pragma unroll
        for (int i = 0; i < 16; i++) {
            mx0 = fmaxf(mx0, fmaxf(ss[i][0], ss[i][1]));
            mx1 = fmaxf(mx1, fmaxf(ss[i][2], ss[i][3]));
        }
        mx0 = fmaxf(mx0, __shfl_xor_sync(0xffffffffu, mx0, 1));
        mx0 = fmaxf(mx0, __shfl_xor_sync(0xffffffffu, mx0, 2));
        mx1 = fmaxf(mx1, __shfl_xor_sync(0xffffffffu, mx1, 1));
        mx1 = fmaxf(mx1, __shfl_xor_sync(0xffffffffu, mx1, 2));

        float mn0 = fmaxf(m0, mx0), mn1 = fmaxf(m1, mx1);
        float al0 = __expf(m0 - mn0), al1 = __expf(m1 - mn1);
        float sum0 = 0.f, sum1 = 0.f;
#pragma unroll
        for (int i = 0; i < 16; i++) {
            ss[i][0] = __expf(ss[i][0] - mn0); sum0 += ss[i][0];
            ss[i][1] = __expf(ss[i][1] - mn0); sum0 += ss[i][1];
            ss[i][2] = __expf(ss[i][2] - mn1); sum1 += ss[i][2];
            ss[i][3] = __expf(ss[i][3] - mn1); sum1 += ss[i][3];
        }
        sum0 += __shfl_xor_sync(0xffffffffu, sum0, 1);
        sum0 += __shfl_xor_sync(0xffffffffu, sum0, 2);
        sum1 += __shfl_xor_sync(0xffffffffu, sum1, 1);
        sum1 += __shfl_xor_sync(0xffffffffu, sum1, 2);
        l0 = l0 * al0 + sum0;
        l1 = l1 * al1 + sum1;
        m0 = mn0; m1 = mn1;
#pragma unroll
        for (int v = 0; v < 8; v++) {
            o[v][0] *= al0; o[v][1] *= al0;
            o[v][2] *= al1; o[v][3] *= al1;
        }

        // ---- O += P @ V (P hi/lo fp16 from regs, V via ldmatrix.trans) ----
        int g8 = lane >> 3;                    // 0..3
        int koff = (g8 & 1) * 8 + (lane & 7);  // source k-row within 16
        int noff = (g8 >> 1) * 8;              // source n-col base within 16
#pragma unroll
        for (int ks = 0; ks < 8; ks++) {
            uint32_t ahi[4], alo[4];
            ahi[0] = pack2h(ss[2 * ks][0], ss[2 * ks][1]);
            ahi[1] = pack2h(ss[2 * ks][2], ss[2 * ks][3]);
            ahi[2] = pack2h(ss[2 * ks + 1][0], ss[2 * ks + 1][1]);
            ahi[3] = pack2h(ss[2 * ks + 1][2], ss[2 * ks + 1][3]);
            alo[0] = packlo2h(ss[2 * ks][0], ss[2 * ks][1]);
            alo[1] = packlo2h(ss[2 * ks][2], ss[2 * ks][3]);
            alo[2] = packlo2h(ss[2 * ks + 1][0], ss[2 * ks + 1][1]);
            alo[3] = packlo2h(ss[2 * ks + 1][2], ss[2 * ks + 1][3]);
#pragma unroll
            for (int nvp = 0; nvp < 4; nvp++) {
                uint32_t bv[4];
                uint32_t boff = ((ks * 16 + koff) * KSVR + nvp * 16 + noff) * 2;
                ldm4t(bv, uVh + boff);
                int nv = nvp * 2;
                mma16816h(o[nv], ahi, bv);     mma16816h(o[nv + 1], ahi, bv + 2);
                mma16816h(o[nv], alo, bv);     mma16816h(o[nv + 1], alo, bv + 2);
            }
        }
    }

    // ---- epilogue: O /= l, write fp16 hi/lo ----
    float inv0 = 1.f / l0, inv1 = 1.f / l1;
    int row0 = qi * 128 + wq * 16 + fr;
#pragma unroll
    for (int v = 0; v < 8; v++) {
#pragma unroll
        for (int r = 0; r < 4; r++) {
            int row = row0 + ((r >> 1) << 3);
            int col = h * HDIM + v * 8 + fc * 2 + (r & 1);
            float val = o[v][r] * ((r >> 1) ? inv1 : inv0);
            long gi = (long)(b * NSEQ + row) * DMODEL + col;
            f16 hh = __float2half(val);
            attnh[gi] = hh;
            attnl[gi] = __float2half(val - __half2float(hh));
        }
    }
}

// ---------------------------------------------------------------------------
// Tensor-core GEMM template (fp16), 2-stage cp.async double buffer.
//   NMMA=2: 2-term hi/lo (Ah/Al + Bh; acc = Ah.Bh + Al.Bh).
//   NMMA=1: single-term (Ah, Bh only).
//   A: [M,K], stride lda.  B: [N,K], stride ldb.
//   128x128 tile, BK=32, 8 warps (2m x 4n), ldmatrix fragment loads.
//   flags: 1=residual, 2=exact GELU, 8=write fp32 C, 16=write fp16 hi/lo.
// ---------------------------------------------------------------------------
template<int NMMA>
__global__ __launch_bounds__(256, 2) void bgemm_kernel(
    const uint16_t* __restrict__ Ah, const uint16_t* __restrict__ Al, int lda,
    const uint16_t* __restrict__ Bh, int ldb,
    float* __restrict__ C, f16* __restrict__ Ch, f16* __restrict__ Cl, int ldc,
    const float* __restrict__ bias,
    int M, int N, int K, int flags) {

    constexpr int TPS = (NMMA == 2) ? 3 : 2;             // tiles per stage
    constexpr int BH_OFF = (NMMA == 2) ? 2 * TILE_E : TILE_E;

    int m0 = blockIdx.y * 128, n0 = blockIdx.x * 128;

    extern __shared__ uint16_t S[];
    uint32_t sbase = (uint32_t)__cvta_generic_to_shared(S);

    int tid = threadIdx.x, lane = tid & 31, wid = tid >> 5;
    int wm = wid & 1, wn = wid >> 1;
    int fr = lane >> 2, fc = lane & 3;

    int r2 = tid >> 1;
    int c2 = (tid & 1) * 16;

    float acc[4][4][4];
#pragma unroll
    for (int i = 0; i < 4; i++)
#pragma unroll
        for (int j = 0; j < 4; j++)
#pragma unroll
            for (int r = 0; r < 4; r++) acc[i][j][r] = 0.f;

    auto ldStage = [&](int k0, int bufi) {
        uint32_t sb = sbase + bufi * (TPS * TILE_E * 2);
        uint32_t sa = sb + r2 * (KS * 2) + c2 * 2;
        const uint16_t* ga = Ah + (long)(m0 + r2) * lda + k0 + c2;
        cp16(sa, ga);            cp16(sa + 16, ga + 8);
        if (NMMA == 2) {
            ga = Al + (long)(m0 + r2) * lda + k0 + c2;
            cp16(sa + TILE_E * 2, ga); cp16(sa + TILE_E * 2 + 16, ga + 8);
        }
        int gn = n0 + r2;
        uint32_t sbB = sb + BH_OFF * 2 + r2 * (KS * 2) + c2 * 2;
        if (gn < N) {
            const uint16_t* gb = Bh + (long)gn * ldb + k0 + c2;
            cp16(sbB, gb);            cp16(sbB + 16, gb + 8);
        } else {
            uint4 zz = make_uint4(0, 0, 0, 0);
            uint16_t* p = S + bufi * TPS * TILE_E + BH_OFF + r2 * KS + c2;
            *(uint4*)p = zz; *(uint4*)(p + 8) = zz;
        }
        asm volatile("cp.async.commit_group;\n" ::: "memory");
    };

    ldStage(0, 0);

    // per-thread ldmatrix address components (elem offsets)
    int aRow = wm * 64 + (lane & 15);
    int aColX = (lane >> 4) << 3;
    int bRow = wn * 32 + ((lane >> 4) << 3) + (lane & 7);
    int bColX = ((lane >> 3) & 1) << 3;

    int KT = K >> 5;
    int buf = 0;
    for (int kt = 0; kt < KT; kt++) {
        asm volatile("cp.async.wait_group 0;\n" ::: "memory");
        __syncthreads();
        if (kt + 1 < KT) ldStage((kt + 1) << 5, buf ^ 1);

        uint32_t sb = sbase + buf * (TPS * TILE_E * 2);

#pragma unroll
        for (int ks = 0; ks < 32; ks += 16) {
            uint32_t ah[4][4], bh[4][2];
            uint32_t aA = sb + (aRow * KS + ks + aColX) * 2;
            uint32_t bB = sb + BH_OFF * 2 + (bRow * KS + ks + bColX) * 2;
#pragma unroll
            for (int mi = 0; mi < 4; mi++) ldm4(ah[mi], aA + mi * (16 * KS * 2));
#pragma unroll
            for (int nip = 0; nip < 2; nip++)
                ldm4(&bh[nip * 2][0], bB + nip * (16 * KS * 2));

#pragma unroll
            for (int mi = 0; mi < 4; mi++)
#pragma unroll
                for (int ni = 0; ni < 4; ni++)
                    mma16816h(acc[mi][ni], ah[mi], bh[ni]);

            if (NMMA == 2) {
                uint32_t al[4][4];
#pragma unroll
                for (int mi = 0; mi < 4; mi++)
                    ldm4(al[mi], aA + mi * (16 * KS * 2) + TILE_E * 2);
#pragma unroll
                for (int mi = 0; mi < 4; mi++)
#pragma unroll
                    for (int ni = 0; ni < 4; ni++)
                        mma16816h(acc[mi][ni], al[mi], bh[ni]);
            }
        }
        __syncthreads();
        buf ^= 1;
    }

    // Epilogue
#pragma unroll
    for (int mi = 0; mi < 4; mi++) {
        int gm0 = m0 + wm * 64 + mi * 16 + fr;
#pragma unroll
        for (int ni = 0; ni < 4; ni++) {
            int gn = n0 + wn * 32 + ni * 8 + fc * 2;
#pragma unroll
            for (int r = 0; r < 4; r++) {
                int gm = gm0 + (r >= 2 ? 8 : 0);
                int gc = gn + (r & 1);
                if (gc < N) {
                    float v = acc[mi][ni][r];
                    if (bias) v += bias[gc];
                    if (flags & 2) v = 0.5f * v * (1.f + erff(v * 0.70710678118654752f));
                    long idx = (long)gm * ldc + gc;
                    if (flags & 1) v += C[idx];
                    if (flags & 8) C[idx] = v;
                    if (flags & 16) {
                        f16 h = __float2half(v);
                        Ch[idx] = h;
                        Cl[idx] = __float2half(v - __half2float(h));
                    }
                }
            }
        }
    }
}

// ---------------------------------------------------------------------------
// Host-side orchestration
// ---------------------------------------------------------------------------
extern "C" void kernel_launch(void* const* d_in, const int* in_sizes, int n_in,
                              void* d_out, int out_size) {
    (void)in_sizes; (void)n_in; (void)out_size;

    const int*   tok     = (const int*)  d_in[0];
    const float* wte     = (const float*)d_in[1];
    const float* wpe     = (const float*)d_in[2];
    const float* ln1_w   = (const float*)d_in[3];
    const float* ln1_b   = (const float*)d_in[4];
    const float* attn_w  = (const float*)d_in[5];
    const float* attn_b  = (const float*)d_in[6];
    const float* aproj_w = (const float*)d_in[7];
    const float* aproj_b = (const float*)d_in[8];
    const float* ln2_w   = (const float*)d_in[9];
    const float* ln2_b   = (const float*)d_in[10];
    const float* fc_w    = (const float*)d_in[11];
    const float* fc_b    = (const float*)d_in[12];
    const float* mproj_w = (const float*)d_in[13];
    const float* mproj_b = (const float*)d_in[14];
    const float* lnf_w   = (const float*)d_in[15];
    const float* lnf_b   = (const float*)d_in[16];
    float* out = (float*)d_out;

    float *x;
    f16 *lnh, *lnl, *qkvh, *qkvl, *attnh, *attnl, *midh, *midl;
    f16 *wqkvh, *waph, *wfch, *wmph, *wtef, *lnf16;
    cudaGetSymbolAddress((void**)&x,      g_x);
    cudaGetSymbolAddress((void**)&lnh,    g_lnh);
    cudaGetSymbolAddress((void**)&lnl,    g_lnl);
    cudaGetSymbolAddress((void**)&qkvh,   g_qkvh);
    cudaGetSymbolAddress((void**)&qkvl,   g_qkvl);
    cudaGetSymbolAddress((void**)&attnh,  g_attnh);
    cudaGetSymbolAddress((void**)&attnl,  g_attnl);
    cudaGetSymbolAddress((void**)&midh,   g_midh);
    cudaGetSymbolAddress((void**)&midl,   g_midl);
    cudaGetSymbolAddress((void**)&wqkvh,  g_wqkvh);
    cudaGetSymbolAddress((void**)&waph,   g_waph);
    cudaGetSymbolAddress((void**)&wfch,   g_wfch);
    cudaGetSymbolAddress((void**)&wmph,   g_wmph);
    cudaGetSymbolAddress((void**)&wtef,   g_wtef);
    cudaGetSymbolAddress((void**)&lnf16,  g_lnf16);

    const int D = DMODEL;
    const int SMEM2 = 2 * 3 * TILE_E * 2;                  // 61440 (2 stages x 3 tiles)
    const int SMEM1 = 2 * 2 * TILE_E * 2;                  // 40960 (2 stages x 2 tiles)
    const int FSMEM = (3 * 128 * KSQ + 128 * KSVR) * 2;    // 73728

    cudaFuncSetAttribute(bgemm_kernel<2>,
                         cudaFuncAttributeMaxDynamicSharedMemorySize, SMEM2);
    cudaFuncSetAttribute(bgemm_kernel<1>,
                         cudaFuncAttributeMaxDynamicSharedMemorySize, SMEM1);
    cudaFuncSetAttribute(flash_kernel,
                         cudaFuncAttributeMaxDynamicSharedMemorySize, FSMEM);

    // ---- weight prep (once per call) ----
    {
        dim3 b32(32, 8);
        tsplit_kernel<<<dim3(D / 32, 3 * D / 32, NLAYER), b32>>>(attn_w,  wqkvh, D, 3 * D);
        tsplit_kernel<<<dim3(D / 32, D / 32, NLAYER),     b32>>>(aproj_w, waph,  D, D);
        tsplit_kernel<<<dim3(D / 32, 4 * D / 32, NLAYER), b32>>>(fc_w,    wfch,  D, 4 * D);
        tsplit_kernel<<<dim3(4 * D / 32, D / 32, NLAYER), b32>>>(mproj_w, wmph,  4 * D, D);
        long nwte = (long)NVOCAB * D;
        splitf16_kernel<<<(unsigned)((nwte + 255) / 256), 256>>>(wte, wtef, nwte);
    }

    embed_kernel<<<NTOK, 256>>>(tok, wte, wpe, x);

    for (int l = 0; l < NLAYER; l++) {
        layernorm_kernel<<<NTOK, 256>>>(x, ln1_w + l * D, ln1_b + l * D, lnh, lnl);

        // qkv = h @ attn_w[l] + attn_b[l] -> fp16 hi/lo
        {
            dim3 g(3 * D / 128, NTOK / 128);
            bgemm_kernel<2><<<g, 256, SMEM2>>>(
                (const uint16_t*)lnh, (const uint16_t*)lnl, D,
                (const uint16_t*)(wqkvh + (long)l * 3 * D * D), D,
                nullptr, qkvh, qkvl, 3 * D,
                attn_b + (long)l * 3 * D,
                NTOK, 3 * D, D, 16);
        }

        // fused flash attention -> attnh/attnl
        flash_kernel<<<dim3(NSEQ / 128, 2 * NHEAD), 256, FSMEM>>>(qkvh, qkvl, attnh, attnl);

        // x += attn @ aproj_w[l] + aproj_b[l]
        {
            dim3 g(D / 128, NTOK / 128);
            bgemm_kernel<2><<<g, 256, SMEM2>>>(
                (const uint16_t*)attnh, (const uint16_t*)attnl, D,
                (const uint16_t*)(waph + (long)l * D * D), D,
                x, nullptr, nullptr, D,
                aproj_b + (long)l * D,
                NTOK, D, D, 1 | 8);
        }

        layernorm_kernel<<<NTOK, 256>>>(x, ln2_w + l * D, ln2_b + l * D, lnh, lnl);

        // mid = gelu(h @ fc_w[l] + fc_b[l]) -> fp16 hi/lo
        {
            dim3 g(4 * D / 128, NTOK / 128);
            bgemm_kernel<2><<<g, 256, SMEM2>>>(
                (const uint16_t*)lnh, (const uint16_t*)lnl, D,
                (const uint16_t*)(wfch + (long)l * 4 * D * D), D,
                nullptr, midh, midl, 4 * D,
                fc_b + (long)l * 4 * D,
                NTOK, 4 * D, D, 2 | 16);
        }

        // x += mid @ mproj_w[l] + mproj_b[l]
        {
            dim3 g(D / 128, NTOK / 128);
            bgemm_kernel<2><<<g, 256, SMEM2>>>(
                (const uint16_t*)midh, (const uint16_t*)midl, 4 * D,
                (const uint16_t*)(wmph + (long)l * D * 4 * D), 4 * D,
                x, nullptr, nullptr, D,
                mproj_b + (long)l * D,
                NTOK, D, 4 * D, 1 | 8);
        }
    }

    // final LN (fp16) + tied lm_head in single-term fp16: out = LN_f(x) @ wte^T
    layernorm_f16_kernel<<<NTOK, 256>>>(x, lnf_w, lnf_b, lnf16);
    {
        dim3 g((NVOCAB + 127) / 128, NTOK / 128);
        bgemm_kernel<1><<<g, 256, SMEM1>>>(
            (const uint16_t*)lnf16, nullptr, D,
            (const uint16_t*)wtef, D,
            out, nullptr, nullptr, NVOCAB,
            nullptr,
            NTOK, NVOCAB, D, 8);
    }
}

// round 13
// speedup vs baseline: 1.3459x; 1.0096x over previous
#include <cuda_runtime.h>
#include <cuda_bf16.h>
#include <cuda_fp16.h>
#include <math.h>
#include <stdint.h>

// Problem constants
#define DMODEL 768
#define NTOK   2048          // B*N = 2*1024
#define NSEQ   1024
#define NHEAD  12
#define HDIM   64
#define NLAYER 12
#define NVOCAB 50257

#define KS 40                 // gemm smem k-stride in 16-bit elems (conflict-free)
#define TILE_E (128 * KS)     // elems per smem tile array
#define KSQ 72                // flash Q/K smem stride (64+8)
#define KSVR 72               // flash V row-major smem stride (64+8)

typedef __half f16;

// ---------------------------------------------------------------------------
// Device-global scratch (allocation-free)
// ---------------------------------------------------------------------------
__device__ float g_x[NTOK * DMODEL];                  // residual stream (fp32)

// activations, fp16 hi/lo (lo = A-side correction term)
__device__ f16 g_lnh[NTOK * DMODEL],      g_lnl[NTOK * DMODEL];
__device__ f16 g_qkvh[NTOK * 3 * DMODEL], g_qkvl[NTOK * 3 * DMODEL];
__device__ f16 g_attnh[NTOK * DMODEL],    g_attnl[NTOK * DMODEL];
__device__ f16 g_midh[NTOK * 4 * DMODEL], g_midl[NTOK * 4 * DMODEL];

// final-LN output in fp16 (lm_head only)
__device__ f16 g_lnf16[NTOK * DMODEL];

// weights, transposed to [N,K], fp16 (hi only — B side is single-term)
__device__ f16 g_wqkvh[NLAYER * 3 * DMODEL * DMODEL];
__device__ f16 g_waph [NLAYER * DMODEL * DMODEL];
__device__ f16 g_wfch [NLAYER * 4 * DMODEL * DMODEL];
__device__ f16 g_wmph [NLAYER * DMODEL * 4 * DMODEL];
__device__ f16 g_wtef[(long)NVOCAB * DMODEL];         // wte in fp16 (lm_head)

// ---------------------------------------------------------------------------
// Helpers
// ---------------------------------------------------------------------------
__device__ __forceinline__ void cp16(uint32_t saddr, const void* gaddr) {
    asm volatile("cp.async.cg.shared.global [%0], [%1], 16;\n"
                 :: "r"(saddr), "l"(gaddr));
}

__device__ __forceinline__ void mma16816h(float* d, const uint32_t* a, const uint32_t* b) {
    asm volatile(
        "mma.sync.aligned.m16n8k16.row.col.f32.f16.f16.f32 "
        "{%0,%1,%2,%3},{%4,%5,%6,%7},{%8,%9},{%0,%1,%2,%3};\n"
        : "+f"(d[0]), "+f"(d[1]), "+f"(d[2]), "+f"(d[3])
        : "r"(a[0]), "r"(a[1]), "r"(a[2]), "r"(a[3]), "r"(b[0]), "r"(b[1]));
}

__device__ __forceinline__ void ldm4(uint32_t* r, uint32_t addr) {
    asm volatile("ldmatrix.sync.aligned.m8n8.x4.shared.b16 {%0,%1,%2,%3}, [%4];\n"
                 : "=r"(r[0]), "=r"(r[1]), "=r"(r[2]), "=r"(r[3]) : "r"(addr));
}

__device__ __forceinline__ void ldm4t(uint32_t* r, uint32_t addr) {
    asm volatile("ldmatrix.sync.aligned.m8n8.x4.trans.shared.b16 {%0,%1,%2,%3}, [%4];\n"
                 : "=r"(r[0]), "=r"(r[1]), "=r"(r[2]), "=r"(r[3]) : "r"(addr));
}

__device__ __forceinline__ uint32_t pack2h(float a, float b) {
    __half2 t = __floats2half2_rn(a, b);
    return *(uint32_t*)&t;
}
__device__ __forceinline__ uint32_t packlo2h(float a, float b) {
    float la = a - __half2float(__float2half(a));
    float lb = b - __half2float(__float2half(b));
    return pack2h(la, lb);
}

__device__ __forceinline__ float warpReduceSum(float v) {
#pragma unroll
    for (int o = 16; o; o >>= 1) v += __shfl_xor_sync(0xffffffffu, v, o);
    return v;
}

// ---------------------------------------------------------------------------
// Weight prep: transpose W[z][K][N] -> T[z][N][K], fp16 (hi only)
// ---------------------------------------------------------------------------
__global__ void tsplit_kernel(const float* __restrict__ W,
                              f16* __restrict__ Th, int K, int N) {
    __shared__ float t[32][33];
    long zoff = (long)blockIdx.z * K * N;
    W += zoff; Th += zoff;
    int k0 = blockIdx.x * 32, n0 = blockIdx.y * 32;
    int tx = threadIdx.x, ty = threadIdx.y;
#pragma unroll
    for (int i = 0; i < 4; i++)
        t[ty + i * 8][tx] = W[(long)(k0 + ty + i * 8) * N + n0 + tx];
    __syncthreads();
#pragma unroll
    for (int i = 0; i < 4; i++) {
        int n = n0 + ty + i * 8, k = k0 + tx;
        Th[(long)n * K + k] = __float2half(t[tx][ty + i * 8]);
    }
}

// Elementwise fp32 -> fp16 (wte is already [V, D] = [N, K])
__global__ void splitf16_kernel(const float* __restrict__ in,
                                f16* __restrict__ o, long n) {
    long i = (long)blockIdx.x * 256 + threadIdx.x;
    if (i < n) o[i] = __float2half(in[i]);
}

// ---------------------------------------------------------------------------
// Embedding
// ---------------------------------------------------------------------------
__global__ void embed_kernel(const int* __restrict__ tok,
                             const float* __restrict__ wte,
                             const float* __restrict__ wpe,
                             float* __restrict__ x) {
    int t = blockIdx.x;
    int n = t & (NSEQ - 1);
    int id = tok[t];
    const float* w1 = wte + (long)id * DMODEL;
    const float* w2 = wpe + (long)n * DMODEL;
    float* xo = x + (long)t * DMODEL;
    for (int d = threadIdx.x; d < DMODEL; d += blockDim.x)
        xo[d] = w1[d] + w2[d];
}

// ---------------------------------------------------------------------------
// Warp-per-row LayerNorm: fp32 in -> fp16 hi/lo out.
// 8 rows/block (one per warp), 24 elems per lane, shuffle-only reductions.
// ---------------------------------------------------------------------------
__global__ __launch_bounds__(256) void layernorm_kernel(
    const float* __restrict__ x, const float* __restrict__ w,
    const float* __restrict__ b,
    f16* __restrict__ oh, f16* __restrict__ ol) {
    int lane = threadIdx.x & 31, wq = threadIdx.x >> 5;
    int t = blockIdx.x * 8 + wq;
    const float* xr = x + (long)t * DMODEL;
    long base = (long)t * DMODEL;

    float lx[24];
    float s = 0.f;
#pragma unroll
    for (int i = 0; i < 24; i++) { lx[i] = xr[lane + i * 32]; s += lx[i]; }
    s = warpReduceSum(s);
    float mu = s * (1.f / 768.f);

    float var = 0.f;
#pragma unroll
    for (int i = 0; i < 24; i++) { float d = lx[i] - mu; var += d * d; }
    var = warpReduceSum(var);
    float rstd = rsqrtf(var * (1.f / 768.f) + 1e-5f);

#pragma unroll
    for (int i = 0; i < 24; i++) {
        int d = lane + i * 32;
        float v = (lx[i] - mu) * rstd * w[d] + b[d];
        f16 h = __float2half(v);
        oh[base + d] = h;
        ol[base + d] = __float2half(v - __half2float(h));
    }
}

// Warp-per-row LayerNorm: fp32 in -> single fp16 out (final LN)
__global__ __launch_bounds__(256) void layernorm_f16_kernel(
    const float* __restrict__ x, const float* __restrict__ w,
    const float* __restrict__ b, f16* __restrict__ o) {
    int lane = threadIdx.x & 31, wq = threadIdx.x >> 5;
    int t = blockIdx.x * 8 + wq;
    const float* xr = x + (long)t * DMODEL;
    long base = (long)t * DMODEL;

    float lx[24];
    float s = 0.f;
#pragma unroll
    for (int i = 0; i < 24; i++) { lx[i] = xr[lane + i * 32]; s += lx[i]; }
    s = warpReduceSum(s);
    float mu = s * (1.f / 768.f);

    float var = 0.f;
#pragma unroll
    for (int i = 0; i < 24; i++) { float d = lx[i] - mu; var += d * d; }
    var = warpReduceSum(var);
    float rstd = rsqrtf(var * (1.f / 768.f) + 1e-5f);

#pragma unroll
    for (int i = 0; i < 24; i++) {
        int d = lane + i * 32;
        float v = (lx[i] - mu) * rstd * w[d] + b[d];
        o[base + d] = __float2half(v);
    }
}

// ---------------------------------------------------------------------------
// Flash attention, fp16 2-term: S = Qh.Kh + Ql.Kh ; O += Ph.Vh + Pl.Vh.
// One block per (q-tile of 128 rows, head z); 8 warps, 16 q-rows each.
// Smem: Qh, Ql, Kh [128*KSQ each] + V row-major [128*KSVR] (ldmatrix.trans).
// ---------------------------------------------------------------------------
__global__ __launch_bounds__(256) void flash_kernel(
    const f16* __restrict__ qkvh, const f16* __restrict__ qkvl,
    f16* __restrict__ attnh, f16* __restrict__ attnl) {

    int qi = blockIdx.x;
    int z = blockIdx.y;
    int b = z / NHEAD, h = z - b * NHEAD;
    const int rs = 3 * DMODEL;
    long base = (long)b * NSEQ * rs + h * HDIM;

    extern __shared__ f16 SM[];
    uint32_t u0 = (uint32_t)__cvta_generic_to_shared(SM);
    const uint32_t uQh = u0;
    const uint32_t uQl = uQh + 128 * KSQ * 2;
    const uint32_t uKh = uQl + 128 * KSQ * 2;
    const uint32_t uVh = uKh + 128 * KSQ * 2;

    int tid = threadIdx.x, lane = tid & 31, wq = tid >> 5;
    int fr = lane >> 2, fc = lane & 3;

    // ---- load Q tile (cp.async, hi/lo) ----
    {
        int r = tid >> 1, c0 = (tid & 1) * 32;
        const f16* g = qkvh + base + (long)(qi * 128 + r) * rs + c0;
        uint32_t s = uQh + (r * KSQ + c0) * 2;
        cp16(s, g); cp16(s + 16, g + 8); cp16(s + 32, g + 16); cp16(s + 48, g + 24);
        g = qkvl + base + (long)(qi * 128 + r) * rs + c0;
        s = uQl + (r * KSQ + c0) * 2;
        cp16(s, g); cp16(s + 16, g + 8); cp16(s + 32, g + 16); cp16(s + 48, g + 24);
        asm volatile("cp.async.commit_group;\n" ::: "memory");
    }

    float m0 = -1e30f, m1 = -1e30f, l0 = 0.f, l1 = 0.f;
    float o[8][4] = {};

    for (int kt = 0; kt <= qi; kt++) {
        __syncthreads();

        // ---- load K tile hi + V tile (both cp.async, one group) ----
        {
            int r = tid >> 1, c0 = (tid & 1) * 32;
            const f16* g = qkvh + base + DMODEL + (long)(kt * 128 + r) * rs + c0;
            uint32_t s = uKh + (r * KSQ + c0) * 2;
            cp16(s, g); cp16(s + 16, g + 8); cp16(s + 32, g + 16); cp16(s + 48, g + 24);
            g = qkvh + base + 2 * DMODEL + (long)(kt * 128 + r) * rs + c0;
            s = uVh + (r * KSVR + c0) * 2;
            cp16(s, g); cp16(s + 16, g + 8); cp16(s + 32, g + 16); cp16(s + 48, g + 24);
            asm volatile("cp.async.commit_group;\n" ::: "memory");
        }
        asm volatile("cp.async.wait_group 0;\n" ::: "memory");
        __syncthreads();

        // ---- S = Q @ K^T (2-term fp16) ----
        float ss[16][4];
#pragma unroll
        for (int i = 0; i < 16; i++)
#pragma unroll
            for (int r = 0; r < 4; r++) ss[i][r] = 0.f;

#pragma unroll
        for (int ks4 = 0; ks4 < 4; ks4++) {
            int ks = ks4 * 16;
            uint32_t ah[4], al[4];
            uint32_t aoff = ((wq * 16 + (lane & 15)) * KSQ + ks + ((lane >> 4) << 3)) * 2;
            ldm4(ah, uQh + aoff);
            ldm4(al, uQl + aoff);
#pragma unroll
            for (int nip = 0; nip < 8; nip++) {
                uint32_t bh[4];
                uint32_t boff = ((nip * 16 + ((lane >> 4) << 3) + (lane & 7)) * KSQ
                                 + ks + (((lane >> 3) & 1) << 3)) * 2;
                ldm4(bh, uKh + boff);
                int ni = nip * 2;
                mma16816h(ss[ni], ah, bh);     mma16816h(ss[ni + 1], ah, bh + 2);
                mma16816h(ss[ni], al, bh);     mma16816h(ss[ni + 1], al, bh + 2);
            }
        }

        // ---- scale + causal mask ----
#pragma unroll
        for (int i = 0; i < 16; i++)
#pragma unroll
            for (int r = 0; r < 4; r++) ss[i][r] *= 0.125f;
        if (kt == qi) {
#pragma unroll
            for (int i = 0; i < 16; i++)
#pragma unroll
                for (int r = 0; r < 4; r++) {
                    int col = i * 8 + fc * 2 + (r & 1);
                    int row = wq * 16 + fr + ((r >> 1) << 3);
                    if (col > row) ss[i][r] = -1e30f;
                }
        }

        // ---- online softmax ----
        float mx0 = -1e30f, mx1 = -1e30f;
#pragma unroll
        for (int i = 0; i < 16; i++) {
            mx0 = fmaxf(mx0, fmaxf(ss[i][0], ss[i][1]));
            mx1 = fmaxf(mx1, fmaxf(ss[i][2], ss[i][3]));
        }
        mx0 = fmaxf(mx0, __shfl_xor_sync(0xffffffffu, mx0, 1));
        mx0 = fmaxf(mx0, __shfl_xor_sync(0xffffffffu, mx0, 2));
        mx1 = fmaxf(mx1, __shfl_xor_sync(0xffffffffu, mx1, 1));
        mx1 = fmaxf(mx1, __shfl_xor_sync(0xffffffffu, mx1, 2));

        float mn0 = fmaxf(m0, mx0), mn1 = fmaxf(m1, mx1);
        float al0 = __expf(m0 - mn0), al1 = __expf(m1 - mn1);
        float sum0 = 0.f, sum1 = 0.f;
#pragma unroll
        for (int i = 0; i < 16; i++) {
            ss[i][0] = __expf(ss[i][0] - mn0); sum0 += ss[i][0];
            ss[i][1] = __expf(ss[i][1] - mn0); sum0 += ss[i][1];
            ss[i][2] = __expf(ss[i][2] - mn1); sum1 += ss[i][2];
            ss[i][3] = __expf(ss[i][3] - mn1); sum1 += ss[i][3];
        }
        sum0 += __shfl_xor_sync(0xffffffffu, sum0, 1);
        sum0 += __shfl_xor_sync(0xffffffffu, sum0, 2);
        sum1 += __shfl_xor_sync(0xffffffffu, sum1, 1);
        sum1 += __shfl_xor_sync(0xffffffffu, sum1, 2);
        l0 = l0 * al0 + sum0;
        l1 = l1 * al1 + sum1;
        m0 = mn0; m1 = mn1;
#pragma unroll
        for (int v = 0; v < 8; v++) {
            o[v][0] *= al0; o[v][1] *= al0;
            o[v][2] *= al1; o[v][3] *= al1;
        }

        // ---- O += P @ V (P hi/lo fp16 from regs, V via ldmatrix.trans) ----
        int g8 = lane >> 3;                    // 0..3
        int koff = (g8 & 1) * 8 + (lane & 7);  // source k-row within 16
        int noff = (g8 >> 1) * 8;              // source n-col base within 16
#pragma unroll
        for (int ks = 0; ks < 8; ks++) {
            uint32_t ahi[4], alo[4];
            ahi[0] = pack2h(ss[2 * ks][0], ss[2 * ks][1]);
            ahi[1] = pack2h(ss[2 * ks][2], ss[2 * ks][3]);
            ahi[2] = pack2h(ss[2 * ks + 1][0], ss[2 * ks + 1][1]);
            ahi[3] = pack2h(ss[2 * ks + 1][2], ss[2 * ks + 1][3]);
            alo[0] = packlo2h(ss[2 * ks][0], ss[2 * ks][1]);
            alo[1] = packlo2h(ss[2 * ks][2], ss[2 * ks][3]);
            alo[2] = packlo2h(ss[2 * ks + 1][0], ss[2 * ks + 1][1]);
            alo[3] = packlo2h(ss[2 * ks + 1][2], ss[2 * ks + 1][3]);
#pragma unroll
            for (int nvp = 0; nvp < 4; nvp++) {
                uint32_t bv[4];
                uint32_t boff = ((ks * 16 + koff) * KSVR + nvp * 16 + noff) * 2;
                ldm4t(bv, uVh + boff);
                int nv = nvp * 2;
                mma16816h(o[nv], ahi, bv);     mma16816h(o[nv + 1], ahi, bv + 2);
                mma16816h(o[nv], alo, bv);     mma16816h(o[nv + 1], alo, bv + 2);
            }
        }
    }

    // ---- epilogue: O /= l, write fp16 hi/lo ----
    float inv0 = 1.f / l0, inv1 = 1.f / l1;
    int row0 = qi * 128 + wq * 16 + fr;
#pragma unroll
    for (int v = 0; v < 8; v++) {
#pragma unroll
        for (int r = 0; r < 4; r++) {
            int row = row0 + ((r >> 1) << 3);
            int col = h * HDIM + v * 8 + fc * 2 + (r & 1);
            float val = o[v][r] * ((r >> 1) ? inv1 : inv0);
            long gi = (long)(b * NSEQ + row) * DMODEL + col;
            f16 hh = __float2half(val);
            attnh[gi] = hh;
            attnl[gi] = __float2half(val - __half2float(hh));
        }
    }
}

// ---------------------------------------------------------------------------
// Tensor-core GEMM template (fp16), 2-stage cp.async double buffer.
//   NMMA=2: 2-term hi/lo (Ah/Al + Bh; acc = Ah.Bh + Al.Bh).
//   NMMA=1: single-term (Ah, Bh only).
//   A: [M,K], stride lda.  B: [N,K], stride ldb.
//   128x128 tile, BK=32, 8 warps (2m x 4n), ldmatrix fragment loads.
//   flags: 1=residual, 2=exact GELU, 8=write fp32 C, 16=write fp16 hi/lo.
//   loN: Cl (lo) written only for columns < loN (dead-store elimination).
// ---------------------------------------------------------------------------
template<int NMMA>
__global__ __launch_bounds__(256, 2) void bgemm_kernel(
    const uint16_t* __restrict__ Ah, const uint16_t* __restrict__ Al, int lda,
    const uint16_t* __restrict__ Bh, int ldb,
    float* __restrict__ C, f16* __restrict__ Ch, f16* __restrict__ Cl, int ldc,
    const float* __restrict__ bias,
    int M, int N, int K, int flags, int loN) {

    constexpr int TPS = (NMMA == 2) ? 3 : 2;             // tiles per stage
    constexpr int BH_OFF = (NMMA == 2) ? 2 * TILE_E : TILE_E;

    int m0 = blockIdx.y * 128, n0 = blockIdx.x * 128;

    extern __shared__ uint16_t S[];
    uint32_t sbase = (uint32_t)__cvta_generic_to_shared(S);

    int tid = threadIdx.x, lane = tid & 31, wid = tid >> 5;
    int wm = wid & 1, wn = wid >> 1;
    int fr = lane >> 2, fc = lane & 3;

    int r2 = tid >> 1;
    int c2 = (tid & 1) * 16;

    float acc[4][4][4];
#pragma unroll
    for (int i = 0; i < 4; i++)
#pragma unroll
        for (int j = 0; j < 4; j++)
#pragma unroll
            for (int r = 0; r < 4; r++) acc[i][j][r] = 0.f;

    auto ldStage = [&](int k0, int bufi) {
        uint32_t sb = sbase + bufi * (TPS * TILE_E * 2);
        uint32_t sa = sb + r2 * (KS * 2) + c2 * 2;
        const uint16_t* ga = Ah + (long)(m0 + r2) * lda + k0 + c2;
        cp16(sa, ga);            cp16(sa + 16, ga + 8);
        if (NMMA == 2) {
            ga = Al + (long)(m0 + r2) * lda + k0 + c2;
            cp16(sa + TILE_E * 2, ga); cp16(sa + TILE_E * 2 + 16, ga + 8);
        }
        int gn = n0 + r2;
        uint32_t sbB = sb + BH_OFF * 2 + r2 * (KS * 2) + c2 * 2;
        if (gn < N) {
            const uint16_t* gb = Bh + (long)gn * ldb + k0 + c2;
            cp16(sbB, gb);            cp16(sbB + 16, gb + 8);
        } else {
            uint4 zz = make_uint4(0, 0, 0, 0);
            uint16_t* p = S + bufi * TPS * TILE_E + BH_OFF + r2 * KS + c2;
            *(uint4*)p = zz; *(uint4*)(p + 8) = zz;
        }
        asm volatile("cp.async.commit_group;\n" ::: "memory");
    };

    ldStage(0, 0);

    // per-thread ldmatrix address components (elem offsets)
    int aRow = wm * 64 + (lane & 15);
    int aColX = (lane >> 4) << 3;
    int bRow = wn * 32 + ((lane >> 4) << 3) + (lane & 7);
    int bColX = ((lane >> 3) & 1) << 3;

    int KT = K >> 5;
    int buf = 0;
    for (int kt = 0; kt < KT; kt++) {
        asm volatile("cp.async.wait_group 0;\n" ::: "memory");
        __syncthreads();
        if (kt + 1 < KT) ldStage((kt + 1) << 5, buf ^ 1);

        uint32_t sb = sbase + buf * (TPS * TILE_E * 2);

#pragma unroll
        for (int ks = 0; ks < 32; ks += 16) {
            uint32_t ah[4][4], bh[4][2];
            uint32_t aA = sb + (aRow * KS + ks + aColX) * 2;
            uint32_t bB = sb + BH_OFF * 2 + (bRow * KS + ks + bColX) * 2;
#pragma unroll
            for (int mi = 0; mi < 4; mi++) ldm4(ah[mi], aA + mi * (16 * KS * 2));
#pragma unroll
            for (int nip = 0; nip < 2; nip++)
                ldm4(&bh[nip * 2][0], bB + nip * (16 * KS * 2));

#pragma unroll
            for (int mi = 0; mi < 4; mi++)
#pragma unroll
                for (int ni = 0; ni < 4; ni++)
                    mma16816h(acc[mi][ni], ah[mi], bh[ni]);

            if (NMMA == 2) {
                uint32_t al[4][4];
#pragma unroll
                for (int mi = 0; mi < 4; mi++)
                    ldm4(al[mi], aA + mi * (16 * KS * 2) + TILE_E * 2);
#pragma unroll
                for (int mi = 0; mi < 4; mi++)
#pragma unroll
                    for (int ni = 0; ni < 4; ni++)
                        mma16816h(acc[mi][ni], al[mi], bh[ni]);
            }
        }
        __syncthreads();
        buf ^= 1;
    }

    // Epilogue
#pragma unroll
    for (int mi = 0; mi < 4; mi++) {
        int gm0 = m0 + wm * 64 + mi * 16 + fr;
#pragma unroll
        for (int ni = 0; ni < 4; ni++) {
            int gn = n0 + wn * 32 + ni * 8 + fc * 2;
#pragma unroll
            for (int r = 0; r < 4; r++) {
                int gm = gm0 + (r >= 2 ? 8 : 0);
                int gc = gn + (r & 1);
                if (gc < N) {
                    float v = acc[mi][ni][r];
                    if (bias) v += bias[gc];
                    if (flags & 2) v = 0.5f * v * (1.f + erff(v * 0.70710678118654752f));
                    long idx = (long)gm * ldc + gc;
                    if (flags & 1) v += C[idx];
                    if (flags & 8) C[idx] = v;
                    if (flags & 16) {
                        f16 h = __float2half(v);
                        Ch[idx] = h;
                        if (gc < loN)
                            Cl[idx] = __float2half(v - __half2float(h));
                    }
                }
            }
        }
    }
}

// ---------------------------------------------------------------------------
// Host-side orchestration
// ---------------------------------------------------------------------------
extern "C" void kernel_launch(void* const* d_in, const int* in_sizes, int n_in,
                              void* d_out, int out_size) {
    (void)in_sizes; (void)n_in; (void)out_size;

    const int*   tok     = (const int*)  d_in[0];
    const float* wte     = (const float*)d_in[1];
    const float* wpe     = (const float*)d_in[2];
    const float* ln1_w   = (const float*)d_in[3];
    const float* ln1_b   = (const float*)d_in[4];
    const float* attn_w  = (const float*)d_in[5];
    const float* attn_b  = (const float*)d_in[6];
    const float* aproj_w = (const float*)d_in[7];
    const float* aproj_b = (const float*)d_in[8];
    const float* ln2_w   = (const float*)d_in[9];
    const float* ln2_b   = (const float*)d_in[10];
    const float* fc_w    = (const float*)d_in[11];
    const float* fc_b    = (const float*)d_in[12];
    const float* mproj_w = (const float*)d_in[13];
    const float* mproj_b = (const float*)d_in[14];
    const float* lnf_w   = (const float*)d_in[15];
    const float* lnf_b   = (const float*)d_in[16];
    float* out = (float*)d_out;

    float *x;
    f16 *lnh, *lnl, *qkvh, *qkvl, *attnh, *attnl, *midh, *midl;
    f16 *wqkvh, *waph, *wfch, *wmph, *wtef, *lnf16;
    cudaGetSymbolAddress((void**)&x,      g_x);
    cudaGetSymbolAddress((void**)&lnh,    g_lnh);
    cudaGetSymbolAddress((void**)&lnl,    g_lnl);
    cudaGetSymbolAddress((void**)&qkvh,   g_qkvh);
    cudaGetSymbolAddress((void**)&qkvl,   g_qkvl);
    cudaGetSymbolAddress((void**)&attnh,  g_attnh);
    cudaGetSymbolAddress((void**)&attnl,  g_attnl);
    cudaGetSymbolAddress((void**)&midh,   g_midh);
    cudaGetSymbolAddress((void**)&midl,   g_midl);
    cudaGetSymbolAddress((void**)&wqkvh,  g_wqkvh);
    cudaGetSymbolAddress((void**)&waph,   g_waph);
    cudaGetSymbolAddress((void**)&wfch,   g_wfch);
    cudaGetSymbolAddress((void**)&wmph,   g_wmph);
    cudaGetSymbolAddress((void**)&wtef,   g_wtef);
    cudaGetSymbolAddress((void**)&lnf16,  g_lnf16);

    const int D = DMODEL;
    const int SMEM2 = 2 * 3 * TILE_E * 2;                  // 61440 (2 stages x 3 tiles)
    const int SMEM1 = 2 * 2 * TILE_E * 2;                  // 40960 (2 stages x 2 tiles)
    const int FSMEM = (3 * 128 * KSQ + 128 * KSVR) * 2;    // 73728

    cudaFuncSetAttribute(bgemm_kernel<2>,
                         cudaFuncAttributeMaxDynamicSharedMemorySize, SMEM2);
    cudaFuncSetAttribute(bgemm_kernel<1>,
                         cudaFuncAttributeMaxDynamicSharedMemorySize, SMEM1);
    cudaFuncSetAttribute(flash_kernel,
                         cudaFuncAttributeMaxDynamicSharedMemorySize, FSMEM);

    // ---- weight prep (once per call) ----
    {
        dim3 b32(32, 8);
        tsplit_kernel<<<dim3(D / 32, 3 * D / 32, NLAYER), b32>>>(attn_w,  wqkvh, D, 3 * D);
        tsplit_kernel<<<dim3(D / 32, D / 32, NLAYER),     b32>>>(aproj_w, waph,  D, D);
        tsplit_kernel<<<dim3(D / 32, 4 * D / 32, NLAYER), b32>>>(fc_w,    wfch,  D, 4 * D);
        tsplit_kernel<<<dim3(4 * D / 32, D / 32, NLAYER), b32>>>(mproj_w, wmph,  4 * D, D);
        long nwte = (long)NVOCAB * D;
        splitf16_kernel<<<(unsigned)((nwte + 255) / 256), 256>>>(wte, wtef, nwte);
    }

    embed_kernel<<<NTOK, 256>>>(tok, wte, wpe, x);

    for (int l = 0; l < NLAYER; l++) {
        layernorm_kernel<<<NTOK / 8, 256>>>(x, ln1_w + l * D, ln1_b + l * D, lnh, lnl);

        // qkv = h @ attn_w[l] + attn_b[l] -> fp16 hi (+lo for Q cols only)
        {
            dim3 g(3 * D / 128, NTOK / 128);
            bgemm_kernel<2><<<g, 256, SMEM2>>>(
                (const uint16_t*)lnh, (const uint16_t*)lnl, D,
                (const uint16_t*)(wqkvh + (long)l * 3 * D * D), D,
                nullptr, qkvh, qkvl, 3 * D,
                attn_b + (long)l * 3 * D,
                NTOK, 3 * D, D, 16, D);
        }

        // fused flash attention -> attnh/attnl
        flash_kernel<<<dim3(NSEQ / 128, 2 * NHEAD), 256, FSMEM>>>(qkvh, qkvl, attnh, attnl);

        // x += attn @ aproj_w[l] + aproj_b[l]
        {
            dim3 g(D / 128, NTOK / 128);
            bgemm_kernel<2><<<g, 256, SMEM2>>>(
                (const uint16_t*)attnh, (const uint16_t*)attnl, D,
                (const uint16_t*)(waph + (long)l * D * D), D,
                x, nullptr, nullptr, D,
                aproj_b + (long)l * D,
                NTOK, D, D, 1 | 8, 0);
        }

        layernorm_kernel<<<NTOK / 8, 256>>>(x, ln2_w + l * D, ln2_b + l * D, lnh, lnl);

        // mid = gelu(h @ fc_w[l] + fc_b[l]) -> fp16 hi/lo
        {
            dim3 g(4 * D / 128, NTOK / 128);
            bgemm_kernel<2><<<g, 256, SMEM2>>>(
                (const uint16_t*)lnh, (const uint16_t*)lnl, D,
                (const uint16_t*)(wfch + (long)l * 4 * D * D), D,
                nullptr, midh, midl, 4 * D,
                fc_b + (long)l * 4 * D,
                NTOK, 4 * D, D, 2 | 16, 4 * D);
        }

        // x += mid @ mproj_w[l] + mproj_b[l]
        {
            dim3 g(D / 128, NTOK / 128);
            bgemm_kernel<2><<<g, 256, SMEM2>>>(
                (const uint16_t*)midh, (const uint16_t*)midl, 4 * D,
                (const uint16_t*)(wmph + (long)l * D * 4 * D), 4 * D,
                x, nullptr, nullptr, D,
                mproj_b + (long)l * D,
                NTOK, D, 4 * D, 1 | 8, 0);
        }
    }

    // final LN (fp16) + tied lm_head in single-term fp16: out = LN_f(x) @ wte^T
    layernorm_f16_kernel<<<NTOK / 8, 256>>>(x, lnf_w, lnf_b, lnf16);
    {
        dim3 g((NVOCAB + 127) / 128, NTOK / 128);
        bgemm_kernel<1><<<g, 256, SMEM1>>>(
            (const uint16_t*)lnf16, nullptr, D,
            (const uint16_t*)wtef, D,
            out, nullptr, nullptr, NVOCAB,
            nullptr,
            NTOK, NVOCAB, D, 8, 0);
    }
}

// round 14
// speedup vs baseline: 1.3577x; 1.0087x over previous
#include <cuda_runtime.h>
#include <cuda_bf16.h>
#include <cuda_fp16.h>
#include <math.h>
#include <stdint.h>

// Problem constants
#define DMODEL 768
#define NTOK   2048          // B*N = 2*1024
#define NSEQ   1024
#define NHEAD  12
#define HDIM   64
#define NLAYER 12
#define NVOCAB 50257

#define KS 40                 // gemm smem k-stride in 16-bit elems (conflict-free)
#define TILE_E (128 * KS)     // elems per smem tile array
#define KSQ 72                // flash Q/K smem stride (64+8)
#define KSVR 72               // flash V row-major smem stride (64+8)

typedef __half f16;

// ---------------------------------------------------------------------------
// Device-global scratch (allocation-free)
// ---------------------------------------------------------------------------
__device__ float g_x[NTOK * DMODEL];                  // residual stream (fp32)

// activations, fp16 hi/lo (lo = A-side correction term)
__device__ f16 g_lnh[NTOK * DMODEL],      g_lnl[NTOK * DMODEL];
__device__ f16 g_qkvh[NTOK * 3 * DMODEL], g_qkvl[NTOK * 3 * DMODEL];
__device__ f16 g_attnh[NTOK * DMODEL],    g_attnl[NTOK * DMODEL];
__device__ f16 g_midh[NTOK * 4 * DMODEL], g_midl[NTOK * 4 * DMODEL];

// final-LN output in fp16 (lm_head only)
__device__ f16 g_lnf16[NTOK * DMODEL];

// weights, transposed to [N,K], fp16 (hi only — B side is single-term)
__device__ f16 g_wqkvh[NLAYER * 3 * DMODEL * DMODEL];
__device__ f16 g_waph [NLAYER * DMODEL * DMODEL];
__device__ f16 g_wfch [NLAYER * 4 * DMODEL * DMODEL];
__device__ f16 g_wmph [NLAYER * DMODEL * 4 * DMODEL];
__device__ f16 g_wtef[(long)NVOCAB * DMODEL];         // wte in fp16 (lm_head)

// ---------------------------------------------------------------------------
// Helpers
// ---------------------------------------------------------------------------
__device__ __forceinline__ void cp16(uint32_t saddr, const void* gaddr) {
    asm volatile("cp.async.cg.shared.global [%0], [%1], 16;\n"
                 :: "r"(saddr), "l"(gaddr));
}

__device__ __forceinline__ void mma16816h(float* d, const uint32_t* a, const uint32_t* b) {
    asm volatile(
        "mma.sync.aligned.m16n8k16.row.col.f32.f16.f16.f32 "
        "{%0,%1,%2,%3},{%4,%5,%6,%7},{%8,%9},{%0,%1,%2,%3};\n"
        : "+f"(d[0]), "+f"(d[1]), "+f"(d[2]), "+f"(d[3])
        : "r"(a[0]), "r"(a[1]), "r"(a[2]), "r"(a[3]), "r"(b[0]), "r"(b[1]));
}

__device__ __forceinline__ void ldm4(uint32_t* r, uint32_t addr) {
    asm volatile("ldmatrix.sync.aligned.m8n8.x4.shared.b16 {%0,%1,%2,%3}, [%4];\n"
                 : "=r"(r[0]), "=r"(r[1]), "=r"(r[2]), "=r"(r[3]) : "r"(addr));
}

__device__ __forceinline__ void ldm4t(uint32_t* r, uint32_t addr) {
    asm volatile("ldmatrix.sync.aligned.m8n8.x4.trans.shared.b16 {%0,%1,%2,%3}, [%4];\n"
                 : "=r"(r[0]), "=r"(r[1]), "=r"(r[2]), "=r"(r[3]) : "r"(addr));
}

__device__ __forceinline__ uint32_t pack2h(float a, float b) {
    __half2 t = __floats2half2_rn(a, b);
    return *(uint32_t*)&t;
}
__device__ __forceinline__ uint32_t packlo2h(float a, float b) {
    float la = a - __half2float(__float2half(a));
    float lb = b - __half2float(__float2half(b));
    return pack2h(la, lb);
}

__device__ __forceinline__ float warpReduceSum(float v) {
#pragma unroll
    for (int o = 16; o; o >>= 1) v += __shfl_xor_sync(0xffffffffu, v, o);
    return v;
}

// ---------------------------------------------------------------------------
// Weight prep: transpose W[z][K][N] -> T[z][N][K], fp16 (hi only)
// ---------------------------------------------------------------------------
__global__ void tsplit_kernel(const float* __restrict__ W,
                              f16* __restrict__ Th, int K, int N) {
    __shared__ float t[32][33];
    long zoff = (long)blockIdx.z * K * N;
    W += zoff; Th += zoff;
    int k0 = blockIdx.x * 32, n0 = blockIdx.y * 32;
    int tx = threadIdx.x, ty = threadIdx.y;
#pragma unroll
    for (int i = 0; i < 4; i++)
        t[ty + i * 8][tx] = W[(long)(k0 + ty + i * 8) * N + n0 + tx];
    __syncthreads();
#pragma unroll
    for (int i = 0; i < 4; i++) {
        int n = n0 + ty + i * 8, k = k0 + tx;
        Th[(long)n * K + k] = __float2half(t[tx][ty + i * 8]);
    }
}

// Elementwise fp32 -> fp16 (wte is already [V, D] = [N, K])
__global__ void splitf16_kernel(const float* __restrict__ in,
                                f16* __restrict__ o, long n) {
    long i = (long)blockIdx.x * 256 + threadIdx.x;
    if (i < n) o[i] = __float2half(in[i]);
}

// ---------------------------------------------------------------------------
// Embedding
// ---------------------------------------------------------------------------
__global__ void embed_kernel(const int* __restrict__ tok,
                             const float* __restrict__ wte,
                             const float* __restrict__ wpe,
                             float* __restrict__ x) {
    int t = blockIdx.x;
    int n = t & (NSEQ - 1);
    int id = tok[t];
    const float* w1 = wte + (long)id * DMODEL;
    const float* w2 = wpe + (long)n * DMODEL;
    float* xo = x + (long)t * DMODEL;
    for (int d = threadIdx.x; d < DMODEL; d += blockDim.x)
        xo[d] = w1[d] + w2[d];
}

// ---------------------------------------------------------------------------
// Warp-per-row LayerNorm: fp32 in -> fp16 hi/lo out.
// 8 rows/block (one per warp), 24 elems per lane, shuffle-only reductions.
// ---------------------------------------------------------------------------
__global__ __launch_bounds__(256) void layernorm_kernel(
    const float* __restrict__ x, const float* __restrict__ w,
    const float* __restrict__ b,
    f16* __restrict__ oh, f16* __restrict__ ol) {
    int lane = threadIdx.x & 31, wq = threadIdx.x >> 5;
    int t = blockIdx.x * 8 + wq;
    const float* xr = x + (long)t * DMODEL;
    long base = (long)t * DMODEL;

    float lx[24];
    float s = 0.f;
#pragma unroll
    for (int i = 0; i < 24; i++) { lx[i] = xr[lane + i * 32]; s += lx[i]; }
    s = warpReduceSum(s);
    float mu = s * (1.f / 768.f);

    float var = 0.f;
#pragma unroll
    for (int i = 0; i < 24; i++) { float d = lx[i] - mu; var += d * d; }
    var = warpReduceSum(var);
    float rstd = rsqrtf(var * (1.f / 768.f) + 1e-5f);

#pragma unroll
    for (int i = 0; i < 24; i++) {
        int d = lane + i * 32;
        float v = (lx[i] - mu) * rstd * w[d] + b[d];
        f16 h = __float2half(v);
        oh[base + d] = h;
        ol[base + d] = __float2half(v - __half2float(h));
    }
}

// Warp-per-row LayerNorm: fp32 in -> single fp16 out (final LN)
__global__ __launch_bounds__(256) void layernorm_f16_kernel(
    const float* __restrict__ x, const float* __restrict__ w,
    const float* __restrict__ b, f16* __restrict__ o) {
    int lane = threadIdx.x & 31, wq = threadIdx.x >> 5;
    int t = blockIdx.x * 8 + wq;
    const float* xr = x + (long)t * DMODEL;
    long base = (long)t * DMODEL;

    float lx[24];
    float s = 0.f;
#pragma unroll
    for (int i = 0; i < 24; i++) { lx[i] = xr[lane + i * 32]; s += lx[i]; }
    s = warpReduceSum(s);
    float mu = s * (1.f / 768.f);

    float var = 0.f;
#pragma unroll
    for (int i = 0; i < 24; i++) { float d = lx[i] - mu; var += d * d; }
    var = warpReduceSum(var);
    float rstd = rsqrtf(var * (1.f / 768.f) + 1e-5f);

#pragma unroll
    for (int i = 0; i < 24; i++) {
        int d = lane + i * 32;
        float v = (lx[i] - mu) * rstd * w[d] + b[d];
        o[base + d] = __float2half(v);
    }
}

// ---------------------------------------------------------------------------
// Flash attention, fp16 2-term: S = Qh.Kh + Ql.Kh ; O += Ph.Vh + Pl.Vh.
// One block per (q-tile of 128 rows, head z); 8 warps, 16 q-rows each.
// qi reversed (longest-processing-time-first scheduling).
// Smem: Qh, Ql, Kh [128*KSQ each] + V row-major [128*KSVR] (ldmatrix.trans).
// ---------------------------------------------------------------------------
__global__ __launch_bounds__(256) void flash_kernel(
    const f16* __restrict__ qkvh, const f16* __restrict__ qkvl,
    f16* __restrict__ attnh, f16* __restrict__ attnl) {

    int qi = gridDim.x - 1 - blockIdx.x;   // LPT: heavy q-tiles start first
    int z = blockIdx.y;
    int b = z / NHEAD, h = z - b * NHEAD;
    const int rs = 3 * DMODEL;
    long base = (long)b * NSEQ * rs + h * HDIM;

    extern __shared__ f16 SM[];
    uint32_t u0 = (uint32_t)__cvta_generic_to_shared(SM);
    const uint32_t uQh = u0;
    const uint32_t uQl = uQh + 128 * KSQ * 2;
    const uint32_t uKh = uQl + 128 * KSQ * 2;
    const uint32_t uVh = uKh + 128 * KSQ * 2;

    int tid = threadIdx.x, lane = tid & 31, wq = tid >> 5;
    int fr = lane >> 2, fc = lane & 3;

    // ---- load Q tile (cp.async, hi/lo) ----
    {
        int r = tid >> 1, c0 = (tid & 1) * 32;
        const f16* g = qkvh + base + (long)(qi * 128 + r) * rs + c0;
        uint32_t s = uQh + (r * KSQ + c0) * 2;
        cp16(s, g); cp16(s + 16, g + 8); cp16(s + 32, g + 16); cp16(s + 48, g + 24);
        g = qkvl + base + (long)(qi * 128 + r) * rs + c0;
        s = uQl + (r * KSQ + c0) * 2;
        cp16(s, g); cp16(s + 16, g + 8); cp16(s + 32, g + 16); cp16(s + 48, g + 24);
        asm volatile("cp.async.commit_group;\n" ::: "memory");
    }

    float m0 = -1e30f, m1 = -1e30f, l0 = 0.f, l1 = 0.f;
    float o[8][4] = {};

    for (int kt = 0; kt <= qi; kt++) {
        __syncthreads();

        // ---- load K tile hi + V tile (both cp.async, one group) ----
        {
            int r = tid >> 1, c0 = (tid & 1) * 32;
            const f16* g = qkvh + base + DMODEL + (long)(kt * 128 + r) * rs + c0;
            uint32_t s = uKh + (r * KSQ + c0) * 2;
            cp16(s, g); cp16(s + 16, g + 8); cp16(s + 32, g + 16); cp16(s + 48, g + 24);
            g = qkvh + base + 2 * DMODEL + (long)(kt * 128 + r) * rs + c0;
            s = uVh + (r * KSVR + c0) * 2;
            cp16(s, g); cp16(s + 16, g + 8); cp16(s + 32, g + 16); cp16(s + 48, g + 24);
            asm volatile("cp.async.commit_group;\n" ::: "memory");
        }
        asm volatile("cp.async.wait_group 0;\n" ::: "memory");
        __syncthreads();

        // ---- S = Q @ K^T (2-term fp16) ----
        float ss[16][4];
#pragma unroll
        for (int i = 0; i < 16; i++)
#pragma unroll
            for (int r = 0; r < 4; r++) ss[i][r] = 0.f;

#pragma unroll
        for (int ks4 = 0; ks4 < 4; ks4++) {
            int ks = ks4 * 16;
            uint32_t ah[4], al[4];
            uint32_t aoff = ((wq * 16 + (lane & 15)) * KSQ + ks + ((lane >> 4) << 3)) * 2;
            ldm4(ah, uQh + aoff);
            ldm4(al, uQl + aoff);
#pragma unroll
            for (int nip = 0; nip < 8; nip++) {
                uint32_t bh[4];
                uint32_t boff = ((nip * 16 + ((lane >> 4) << 3) + (lane & 7)) * KSQ
                                 + ks + (((lane >> 3) & 1) << 3)) * 2;
                ldm4(bh, uKh + boff);
                int ni = nip * 2;
                mma16816h(ss[ni], ah, bh);     mma16816h(ss[ni + 1], ah, bh + 2);
                mma16816h(ss[ni], al, bh);     mma16816h(ss[ni + 1], al, bh + 2);
            }
        }

        // ---- scale + causal mask ----
#pragma unroll
        for (int i = 0; i < 16; i++)
#pragma unroll
            for (int r = 0; r < 4; r++) ss[i][r] *= 0.125f;
        if (kt == qi) {
#pragma unroll
            for (int i = 0; i < 16; i++)
#pragma unroll
                for (int r = 0; r < 4; r++) {
                    int col = i * 8 + fc * 2 + (r & 1);
                    int row = wq * 16 + fr + ((r >> 1) << 3);
                    if (col > row) ss[i][r] = -1e30f;
                }
        }

        // ---- online softmax ----
        float mx0 = -1e30f, mx1 = -1e30f;
#pragma unroll
        for (int i = 0; i < 16; i++) {
            mx0 = fmaxf(mx0, fmaxf(ss[i][0], ss[i][1]));
            mx1 = fmaxf(mx1, fmaxf(ss[i][2], ss[i][3]));
        }
        mx0 = fmaxf(mx0, __shfl_xor_sync(0xffffffffu, mx0, 1));
        mx0 = fmaxf(mx0, __shfl_xor_sync(0xffffffffu, mx0, 2));
        mx1 = fmaxf(mx1, __shfl_xor_sync(0xffffffffu, mx1, 1));
        mx1 = fmaxf(mx1, __shfl_xor_sync(0xffffffffu, mx1, 2));

        float mn0 = fmaxf(m0, mx0), mn1 = fmaxf(m1, mx1);
        float al0 = __expf(m0 - mn0), al1 = __expf(m1 - mn1);
        float sum0 = 0.f, sum1 = 0.f;
#pragma unroll
        for (int i = 0; i < 16; i++) {
            ss[i][0] = __expf(ss[i][0] - mn0); sum0 += ss[i][0];
            ss[i][1] = __expf(ss[i][1] - mn0); sum0 += ss[i][1];
            ss[i][2] = __expf(ss[i][2] - mn1); sum1 += ss[i][2];
            ss[i][3] = __expf(ss[i][3] - mn1); sum1 += ss[i][3];
        }
        sum0 += __shfl_xor_sync(0xffffffffu, sum0, 1);
        sum0 += __shfl_xor_sync(0xffffffffu, sum0, 2);
        sum1 += __shfl_xor_sync(0xffffffffu, sum1, 1);
        sum1 += __shfl_xor_sync(0xffffffffu, sum1, 2);
        l0 = l0 * al0 + sum0;
        l1 = l1 * al1 + sum1;
        m0 = mn0; m1 = mn1;
#pragma unroll
        for (int v = 0; v < 8; v++) {
            o[v][0] *= al0; o[v][1] *= al0;
            o[v][2] *= al1; o[v][3] *= al1;
        }

        // ---- O += P @ V (P hi/lo fp16 from regs, V via ldmatrix.trans) ----
        int g8 = lane >> 3;                    // 0..3
        int koff = (g8 & 1) * 8 + (lane & 7);  // source k-row within 16
        int noff = (g8 >> 1) * 8;              // source n-col base within 16
#pragma unroll
        for (int ks = 0; ks < 8; ks++) {
            uint32_t ahi[4], alo[4];
            ahi[0] = pack2h(ss[2 * ks][0], ss[2 * ks][1]);
            ahi[1] = pack2h(ss[2 * ks][2], ss[2 * ks][3]);
            ahi[2] = pack2h(ss[2 * ks + 1][0], ss[2 * ks + 1][1]);
            ahi[3] = pack2h(ss[2 * ks + 1][2], ss[2 * ks + 1][3]);
            alo[0] = packlo2h(ss[2 * ks][0], ss[2 * ks][1]);
            alo[1] = packlo2h(ss[2 * ks][2], ss[2 * ks][3]);
            alo[2] = packlo2h(ss[2 * ks + 1][0], ss[2 * ks + 1][1]);
            alo[3] = packlo2h(ss[2 * ks + 1][2], ss[2 * ks + 1][3]);
#pragma unroll
            for (int nvp = 0; nvp < 4; nvp++) {
                uint32_t bv[4];
                uint32_t boff = ((ks * 16 + koff) * KSVR + nvp * 16 + noff) * 2;
                ldm4t(bv, uVh + boff);
                int nv = nvp * 2;
                mma16816h(o[nv], ahi, bv);     mma16816h(o[nv + 1], ahi, bv + 2);
                mma16816h(o[nv], alo, bv);     mma16816h(o[nv + 1], alo, bv + 2);
            }
        }
    }

    // ---- epilogue: O /= l, write fp16 hi/lo ----
    float inv0 = 1.f / l0, inv1 = 1.f / l1;
    int row0 = qi * 128 + wq * 16 + fr;
#pragma unroll
    for (int v = 0; v < 8; v++) {
#pragma unroll
        for (int r = 0; r < 4; r++) {
            int row = row0 + ((r >> 1) << 3);
            int col = h * HDIM + v * 8 + fc * 2 + (r & 1);
            float val = o[v][r] * ((r >> 1) ? inv1 : inv0);
            long gi = (long)(b * NSEQ + row) * DMODEL + col;
            f16 hh = __float2half(val);
            attnh[gi] = hh;
            attnl[gi] = __float2half(val - __half2float(hh));
        }
    }
}

// ---------------------------------------------------------------------------
// Tensor-core GEMM template (fp16), 2-stage cp.async double buffer.
//   NMMA=2: 2-term hi/lo (Ah/Al + Bh; acc = Ah.Bh + Al.Bh).
//   NMMA=1: single-term (Ah, Bh only).
//   A: [M,K], stride lda.  B: [N,K], stride ldb.
//   128x128 tile, BK=32, 8 warps (2m x 4n), ldmatrix fragment loads.
//   flags: 1=residual, 2=exact GELU, 8=write fp32 C, 16=write fp16 hi/lo,
//          32=grid swapped (blockIdx.x = m-tile, blockIdx.y = n-tile).
//   loN: Cl (lo) written only for columns < loN (dead-store elimination).
// ---------------------------------------------------------------------------
template<int NMMA>
__global__ __launch_bounds__(256, 2) void bgemm_kernel(
    const uint16_t* __restrict__ Ah, const uint16_t* __restrict__ Al, int lda,
    const uint16_t* __restrict__ Bh, int ldb,
    float* __restrict__ C, f16* __restrict__ Ch, f16* __restrict__ Cl, int ldc,
    const float* __restrict__ bias,
    int M, int N, int K, int flags, int loN) {

    constexpr int TPS = (NMMA == 2) ? 3 : 2;             // tiles per stage
    constexpr int BH_OFF = (NMMA == 2) ? 2 * TILE_E : TILE_E;

    int m0, n0;
    if (flags & 32) { m0 = blockIdx.x * 128; n0 = blockIdx.y * 128; }
    else            { m0 = blockIdx.y * 128; n0 = blockIdx.x * 128; }

    extern __shared__ uint16_t S[];
    uint32_t sbase = (uint32_t)__cvta_generic_to_shared(S);

    int tid = threadIdx.x, lane = tid & 31, wid = tid >> 5;
    int wm = wid & 1, wn = wid >> 1;
    int fr = lane >> 2, fc = lane & 3;

    int r2 = tid >> 1;
    int c2 = (tid & 1) * 16;

    float acc[4][4][4];
#pragma unroll
    for (int i = 0; i < 4; i++)
#pragma unroll
        for (int j = 0; j < 4; j++)
#pragma unroll
            for (int r = 0; r < 4; r++) acc[i][j][r] = 0.f;

    auto ldStage = [&](int k0, int bufi) {
        uint32_t sb = sbase + bufi * (TPS * TILE_E * 2);
        uint32_t sa = sb + r2 * (KS * 2) + c2 * 2;
        const uint16_t* ga = Ah + (long)(m0 + r2) * lda + k0 + c2;
        cp16(sa, ga);            cp16(sa + 16, ga + 8);
        if (NMMA == 2) {
            ga = Al + (long)(m0 + r2) * lda + k0 + c2;
            cp16(sa + TILE_E * 2, ga); cp16(sa + TILE_E * 2 + 16, ga + 8);
        }
        int gn = n0 + r2;
        uint32_t sbB = sb + BH_OFF * 2 + r2 * (KS * 2) + c2 * 2;
        if (gn < N) {
            const uint16_t* gb = Bh + (long)gn * ldb + k0 + c2;
            cp16(sbB, gb);            cp16(sbB + 16, gb + 8);
        } else {
            uint4 zz = make_uint4(0, 0, 0, 0);
            uint16_t* p = S + bufi * TPS * TILE_E + BH_OFF + r2 * KS + c2;
            *(uint4*)p = zz; *(uint4*)(p + 8) = zz;
        }
        asm volatile("cp.async.commit_group;\n" ::: "memory");
    };

    ldStage(0, 0);

    // per-thread ldmatrix address components (elem offsets)
    int aRow = wm * 64 + (lane & 15);
    int aColX = (lane >> 4) << 3;
    int bRow = wn * 32 + ((lane >> 4) << 3) + (lane & 7);
    int bColX = ((lane >> 3) & 1) << 3;

    int KT = K >> 5;
    int buf = 0;
    for (int kt = 0; kt < KT; kt++) {
        asm volatile("cp.async.wait_group 0;\n" ::: "memory");
        __syncthreads();
        if (kt + 1 < KT) ldStage((kt + 1) << 5, buf ^ 1);

        uint32_t sb = sbase + buf * (TPS * TILE_E * 2);

#pragma unroll
        for (int ks = 0; ks < 32; ks += 16) {
            uint32_t ah[4][4], bh[4][2];
            uint32_t aA = sb + (aRow * KS + ks + aColX) * 2;
            uint32_t bB = sb + BH_OFF * 2 + (bRow * KS + ks + bColX) * 2;
#pragma unroll
            for (int mi = 0; mi < 4; mi++) ldm4(ah[mi], aA + mi * (16 * KS * 2));
#pragma unroll
            for (int nip = 0; nip < 2; nip++)
                ldm4(&bh[nip * 2][0], bB + nip * (16 * KS * 2));

#pragma unroll
            for (int mi = 0; mi < 4; mi++)
#pragma unroll
                for (int ni = 0; ni < 4; ni++)
                    mma16816h(acc[mi][ni], ah[mi], bh[ni]);

            if (NMMA == 2) {
                uint32_t al[4][4];
#pragma unroll
                for (int mi = 0; mi < 4; mi++)
                    ldm4(al[mi], aA + mi * (16 * KS * 2) + TILE_E * 2);
#pragma unroll
                for (int mi = 0; mi < 4; mi++)
#pragma unroll
                    for (int ni = 0; ni < 4; ni++)
                        mma16816h(acc[mi][ni], al[mi], bh[ni]);
            }
        }
        __syncthreads();
        buf ^= 1;
    }

    // Epilogue
#pragma unroll
    for (int mi = 0; mi < 4; mi++) {
        int gm0 = m0 + wm * 64 + mi * 16 + fr;
#pragma unroll
        for (int ni = 0; ni < 4; ni++) {
            int gn = n0 + wn * 32 + ni * 8 + fc * 2;
#pragma unroll
            for (int r = 0; r < 4; r++) {
                int gm = gm0 + (r >= 2 ? 8 : 0);
                int gc = gn + (r & 1);
                if (gc < N) {
                    float v = acc[mi][ni][r];
                    if (bias) v += bias[gc];
                    if (flags & 2) v = 0.5f * v * (1.f + erff(v * 0.70710678118654752f));
                    long idx = (long)gm * ldc + gc;
                    if (flags & 1) v += C[idx];
                    if (flags & 8) C[idx] = v;
                    if (flags & 16) {
                        f16 h = __float2half(v);
                        Ch[idx] = h;
                        if (gc < loN)
                            Cl[idx] = __float2half(v - __half2float(h));
                    }
                }
            }
        }
    }
}

// ---------------------------------------------------------------------------
// Host-side orchestration
// ---------------------------------------------------------------------------
extern "C" void kernel_launch(void* const* d_in, const int* in_sizes, int n_in,
                              void* d_out, int out_size) {
    (void)in_sizes; (void)n_in; (void)out_size;

    const int*   tok     = (const int*)  d_in[0];
    const float* wte     = (const float*)d_in[1];
    const float* wpe     = (const float*)d_in[2];
    const float* ln1_w   = (const float*)d_in[3];
    const float* ln1_b   = (const float*)d_in[4];
    const float* attn_w  = (const float*)d_in[5];
    const float* attn_b  = (const float*)d_in[6];
    const float* aproj_w = (const float*)d_in[7];
    const float* aproj_b = (const float*)d_in[8];
    const float* ln2_w   = (const float*)d_in[9];
    const float* ln2_b   = (const float*)d_in[10];
    const float* fc_w    = (const float*)d_in[11];
    const float* fc_b    = (const float*)d_in[12];
    const float* mproj_w = (const float*)d_in[13];
    const float* mproj_b = (const float*)d_in[14];
    const float* lnf_w   = (const float*)d_in[15];
    const float* lnf_b   = (const float*)d_in[16];
    float* out = (float*)d_out;

    float *x;
    f16 *lnh, *lnl, *qkvh, *qkvl, *attnh, *attnl, *midh, *midl;
    f16 *wqkvh, *waph, *wfch, *wmph, *wtef, *lnf16;
    cudaGetSymbolAddress((void**)&x,      g_x);
    cudaGetSymbolAddress((void**)&lnh,    g_lnh);
    cudaGetSymbolAddress((void**)&lnl,    g_lnl);
    cudaGetSymbolAddress((void**)&qkvh,   g_qkvh);
    cudaGetSymbolAddress((void**)&qkvl,   g_qkvl);
    cudaGetSymbolAddress((void**)&attnh,  g_attnh);
    cudaGetSymbolAddress((void**)&attnl,  g_attnl);
    cudaGetSymbolAddress((void**)&midh,   g_midh);
    cudaGetSymbolAddress((void**)&midl,   g_midl);
    cudaGetSymbolAddress((void**)&wqkvh,  g_wqkvh);
    cudaGetSymbolAddress((void**)&waph,   g_waph);
    cudaGetSymbolAddress((void**)&wfch,   g_wfch);
    cudaGetSymbolAddress((void**)&wmph,   g_wmph);
    cudaGetSymbolAddress((void**)&wtef,   g_wtef);
    cudaGetSymbolAddress((void**)&lnf16,  g_lnf16);

    const int D = DMODEL;
    const int SMEM2 = 2 * 3 * TILE_E * 2;                  // 61440 (2 stages x 3 tiles)
    const int SMEM1 = 2 * 2 * TILE_E * 2;                  // 40960 (2 stages x 2 tiles)
    const int FSMEM = (3 * 128 * KSQ + 128 * KSVR) * 2;    // 73728

    cudaFuncSetAttribute(bgemm_kernel<2>,
                         cudaFuncAttributeMaxDynamicSharedMemorySize, SMEM2);
    cudaFuncSetAttribute(bgemm_kernel<1>,
                         cudaFuncAttributeMaxDynamicSharedMemorySize, SMEM1);
    cudaFuncSetAttribute(flash_kernel,
                         cudaFuncAttributeMaxDynamicSharedMemorySize, FSMEM);

    // ---- weight prep (once per call) ----
    {
        dim3 b32(32, 8);
        tsplit_kernel<<<dim3(D / 32, 3 * D / 32, NLAYER), b32>>>(attn_w,  wqkvh, D, 3 * D);
        tsplit_kernel<<<dim3(D / 32, D / 32, NLAYER),     b32>>>(aproj_w, waph,  D, D);
        tsplit_kernel<<<dim3(D / 32, 4 * D / 32, NLAYER), b32>>>(fc_w,    wfch,  D, 4 * D);
        tsplit_kernel<<<dim3(4 * D / 32, D / 32, NLAYER), b32>>>(mproj_w, wmph,  4 * D, D);
        long nwte = (long)NVOCAB * D;
        splitf16_kernel<<<(unsigned)((nwte + 255) / 256), 256>>>(wte, wtef, nwte);
    }

    embed_kernel<<<NTOK, 256>>>(tok, wte, wpe, x);

    for (int l = 0; l < NLAYER; l++) {
        layernorm_kernel<<<NTOK / 8, 256>>>(x, ln1_w + l * D, ln1_b + l * D, lnh, lnl);

        // qkv = h @ attn_w[l] + attn_b[l] -> fp16 hi (+lo for Q cols only)
        {
            dim3 g(3 * D / 128, NTOK / 128);
            bgemm_kernel<2><<<g, 256, SMEM2>>>(
                (const uint16_t*)lnh, (const uint16_t*)lnl, D,
                (const uint16_t*)(wqkvh + (long)l * 3 * D * D), D,
                nullptr, qkvh, qkvl, 3 * D,
                attn_b + (long)l * 3 * D,
                NTOK, 3 * D, D, 16, D);
        }

        // fused flash attention -> attnh/attnl
        flash_kernel<<<dim3(NSEQ / 128, 2 * NHEAD), 256, FSMEM>>>(qkvh, qkvl, attnh, attnl);

        // x += attn @ aproj_w[l] + aproj_b[l]
        {
            dim3 g(D / 128, NTOK / 128);
            bgemm_kernel<2><<<g, 256, SMEM2>>>(
                (const uint16_t*)attnh, (const uint16_t*)attnl, D,
                (const uint16_t*)(waph + (long)l * D * D), D,
                x, nullptr, nullptr, D,
                aproj_b + (long)l * D,
                NTOK, D, D, 1 | 8, 0);
        }

        layernorm_kernel<<<NTOK / 8, 256>>>(x, ln2_w + l * D, ln2_b + l * D, lnh, lnl);

        // mid = gelu(h @ fc_w[l] + fc_b[l]) -> fp16 hi/lo
        {
            dim3 g(4 * D / 128, NTOK / 128);
            bgemm_kernel<2><<<g, 256, SMEM2>>>(
                (const uint16_t*)lnh, (const uint16_t*)lnl, D,
                (const uint16_t*)(wfch + (long)l * 4 * D * D), D,
                nullptr, midh, midl, 4 * D,
                fc_b + (long)l * 4 * D,
                NTOK, 4 * D, D, 2 | 16, 4 * D);
        }

        // x += mid @ mproj_w[l] + mproj_b[l]
        {
            dim3 g(D / 128, NTOK / 128);
            bgemm_kernel<2><<<g, 256, SMEM2>>>(
                (const uint16_t*)midh, (const uint16_t*)midl, 4 * D,
                (const uint16_t*)(wmph + (long)l * D * 4 * D), 4 * D,
                x, nullptr, nullptr, D,
                mproj_b + (long)l * D,
                NTOK, D, 4 * D, 1 | 8, 0);
        }
    }

    // final LN (fp16) + tied lm_head in single-term fp16: out = LN_f(x) @ wte^T
    // Grid swapped (m fast axis) so the 16 m-tiles sharing one wte tile run
    // concurrently -> each wte tile fetched from DRAM once, L2-hit 15x.
    layernorm_f16_kernel<<<NTOK / 8, 256>>>(x, lnf_w, lnf_b, lnf16);
    {
        dim3 g(NTOK / 128, (NVOCAB + 127) / 128);
        bgemm_kernel<1><<<g, 256, SMEM1>>>(
            (const uint16_t*)lnf16, nullptr, D,
            (const uint16_t*)wtef, D,
            out, nullptr, nullptr, NVOCAB,
            nullptr,
            NTOK, NVOCAB, D, 8 | 32, 0);
    }
}

// round 15
// speedup vs baseline: 1.4936x; 1.1001x over previous
#include <cuda_runtime.h>
#include <cuda_bf16.h>
#include <cuda_fp16.h>
#include <math.h>
#include <stdint.h>

// Problem constants
#define DMODEL 768
#define NTOK   2048          // B*N = 2*1024
#define NSEQ   1024
#define NHEAD  12
#define HDIM   64
#define NLAYER 12
#define NVOCAB 50257

#define KS 40                 // gemm smem k-stride in 16-bit elems (conflict-free)
#define TILE_E (128 * KS)     // elems per smem tile array
#define KSQ 72                // flash Q/K smem stride (64+8)
#define KSVR 72               // flash V row-major smem stride (64+8)

typedef __half f16;

// ---------------------------------------------------------------------------
// Device-global scratch (allocation-free)
// ---------------------------------------------------------------------------
__device__ float g_x[NTOK * DMODEL];                  // residual stream (fp32)

// activations, fp16 hi/lo (lo = A-side correction term)
__device__ f16 g_lnh[NTOK * DMODEL],      g_lnl[NTOK * DMODEL];
__device__ f16 g_qkvh[NTOK * 3 * DMODEL], g_qkvl[NTOK * 3 * DMODEL];
__device__ f16 g_attnh[NTOK * DMODEL],    g_attnl[NTOK * DMODEL];
__device__ f16 g_midh[NTOK * 4 * DMODEL], g_midl[NTOK * 4 * DMODEL];

// final-LN output in fp16 (lm_head only)
__device__ f16 g_lnf16[NTOK * DMODEL];

// weights, transposed to [N,K], fp16 (hi only — B side is single-term)
__device__ f16 g_wqkvh[NLAYER * 3 * DMODEL * DMODEL];
__device__ f16 g_waph [NLAYER * DMODEL * DMODEL];
__device__ f16 g_wfch [NLAYER * 4 * DMODEL * DMODEL];
__device__ f16 g_wmph [NLAYER * DMODEL * 4 * DMODEL];
__device__ f16 g_wtef[(long)NVOCAB * DMODEL];         // wte in fp16 (lm_head)

// ---------------------------------------------------------------------------
// Helpers
// ---------------------------------------------------------------------------
__device__ __forceinline__ void cp16(uint32_t saddr, const void* gaddr) {
    asm volatile("cp.async.cg.shared.global [%0], [%1], 16;\n"
                 :: "r"(saddr), "l"(gaddr));
}

__device__ __forceinline__ void mma16816h(float* d, const uint32_t* a, const uint32_t* b) {
    asm volatile(
        "mma.sync.aligned.m16n8k16.row.col.f32.f16.f16.f32 "
        "{%0,%1,%2,%3},{%4,%5,%6,%7},{%8,%9},{%0,%1,%2,%3};\n"
        : "+f"(d[0]), "+f"(d[1]), "+f"(d[2]), "+f"(d[3])
        : "r"(a[0]), "r"(a[1]), "r"(a[2]), "r"(a[3]), "r"(b[0]), "r"(b[1]));
}

__device__ __forceinline__ void ldm4(uint32_t* r, uint32_t addr) {
    asm volatile("ldmatrix.sync.aligned.m8n8.x4.shared.b16 {%0,%1,%2,%3}, [%4];\n"
                 : "=r"(r[0]), "=r"(r[1]), "=r"(r[2]), "=r"(r[3]) : "r"(addr));
}

__device__ __forceinline__ void ldm4t(uint32_t* r, uint32_t addr) {
    asm volatile("ldmatrix.sync.aligned.m8n8.x4.trans.shared.b16 {%0,%1,%2,%3}, [%4];\n"
                 : "=r"(r[0]), "=r"(r[1]), "=r"(r[2]), "=r"(r[3]) : "r"(addr));
}

__device__ __forceinline__ uint32_t pack2h(float a, float b) {
    __half2 t = __floats2half2_rn(a, b);
    return *(uint32_t*)&t;
}
__device__ __forceinline__ uint32_t packlo2h(float a, float b) {
    float la = a - __half2float(__float2half(a));
    float lb = b - __half2float(__float2half(b));
    return pack2h(la, lb);
}

__device__ __forceinline__ float warpReduceSum(float v) {
#pragma unroll
    for (int o = 16; o; o >>= 1) v += __shfl_xor_sync(0xffffffffu, v, o);
    return v;
}

// ---------------------------------------------------------------------------
// Weight prep: transpose W[z][K][N] -> T[z][N][K], fp16 (hi only)
// ---------------------------------------------------------------------------
__global__ void tsplit_kernel(const float* __restrict__ W,
                              f16* __restrict__ Th, int K, int N) {
    __shared__ float t[32][33];
    long zoff = (long)blockIdx.z * K * N;
    W += zoff; Th += zoff;
    int k0 = blockIdx.x * 32, n0 = blockIdx.y * 32;
    int tx = threadIdx.x, ty = threadIdx.y;
#pragma unroll
    for (int i = 0; i < 4; i++)
        t[ty + i * 8][tx] = W[(long)(k0 + ty + i * 8) * N + n0 + tx];
    __syncthreads();
#pragma unroll
    for (int i = 0; i < 4; i++) {
        int n = n0 + ty + i * 8, k = k0 + tx;
        Th[(long)n * K + k] = __float2half(t[tx][ty + i * 8]);
    }
}

// Elementwise fp32 -> fp16 (wte is already [V, D] = [N, K])
__global__ void splitf16_kernel(const float* __restrict__ in,
                                f16* __restrict__ o, long n) {
    long i = (long)blockIdx.x * 256 + threadIdx.x;
    if (i < n) o[i] = __float2half(in[i]);
}

// ---------------------------------------------------------------------------
// Embedding
// ---------------------------------------------------------------------------
__global__ void embed_kernel(const int* __restrict__ tok,
                             const float* __restrict__ wte,
                             const float* __restrict__ wpe,
                             float* __restrict__ x) {
    int t = blockIdx.x;
    int n = t & (NSEQ - 1);
    int id = tok[t];
    const float* w1 = wte + (long)id * DMODEL;
    const float* w2 = wpe + (long)n * DMODEL;
    float* xo = x + (long)t * DMODEL;
    for (int d = threadIdx.x; d < DMODEL; d += blockDim.x)
        xo[d] = w1[d] + w2[d];
}

// ---------------------------------------------------------------------------
// Warp-per-row LayerNorm: fp32 in -> fp16 hi/lo out.
// ---------------------------------------------------------------------------
__global__ __launch_bounds__(256) void layernorm_kernel(
    const float* __restrict__ x, const float* __restrict__ w,
    const float* __restrict__ b,
    f16* __restrict__ oh, f16* __restrict__ ol) {
    int lane = threadIdx.x & 31, wq = threadIdx.x >> 5;
    int t = blockIdx.x * 8 + wq;
    const float* xr = x + (long)t * DMODEL;
    long base = (long)t * DMODEL;

    float lx[24];
    float s = 0.f;
#pragma unroll
    for (int i = 0; i < 24; i++) { lx[i] = xr[lane + i * 32]; s += lx[i]; }
    s = warpReduceSum(s);
    float mu = s * (1.f / 768.f);

    float var = 0.f;
#pragma unroll
    for (int i = 0; i < 24; i++) { float d = lx[i] - mu; var += d * d; }
    var = warpReduceSum(var);
    float rstd = rsqrtf(var * (1.f / 768.f) + 1e-5f);

#pragma unroll
    for (int i = 0; i < 24; i++) {
        int d = lane + i * 32;
        float v = (lx[i] - mu) * rstd * w[d] + b[d];
        f16 h = __float2half(v);
        oh[base + d] = h;
        ol[base + d] = __float2half(v - __half2float(h));
    }
}

// Warp-per-row LayerNorm: fp32 in -> single fp16 out (final LN)
__global__ __launch_bounds__(256) void layernorm_f16_kernel(
    const float* __restrict__ x, const float* __restrict__ w,
    const float* __restrict__ b, f16* __restrict__ o) {
    int lane = threadIdx.x & 31, wq = threadIdx.x >> 5;
    int t = blockIdx.x * 8 + wq;
    const float* xr = x + (long)t * DMODEL;
    long base = (long)t * DMODEL;

    float lx[24];
    float s = 0.f;
#pragma unroll
    for (int i = 0; i < 24; i++) { lx[i] = xr[lane + i * 32]; s += lx[i]; }
    s = warpReduceSum(s);
    float mu = s * (1.f / 768.f);

    float var = 0.f;
#pragma unroll
    for (int i = 0; i < 24; i++) { float d = lx[i] - mu; var += d * d; }
    var = warpReduceSum(var);
    float rstd = rsqrtf(var * (1.f / 768.f) + 1e-5f);

#pragma unroll
    for (int i = 0; i < 24; i++) {
        int d = lane + i * 32;
        float v = (lx[i] - mu) * rstd * w[d] + b[d];
        o[base + d] = __float2half(v);
    }
}

// ---------------------------------------------------------------------------
// Flash attention, fp16 2-term, K/V double-buffered.
// One block per (q-tile of 128 rows, head z); 8 warps, 16 q-rows each.
// qi reversed (LPT). Smem: Qh, Ql [128*KSQ], Kh[2], V[2] stages.
// ---------------------------------------------------------------------------
__global__ __launch_bounds__(256) void flash_kernel(
    const f16* __restrict__ qkvh, const f16* __restrict__ qkvl,
    f16* __restrict__ attnh, f16* __restrict__ attnl) {

    int qi = gridDim.x - 1 - blockIdx.x;   // LPT: heavy q-tiles start first
    int z = blockIdx.y;
    int b = z / NHEAD, h = z - b * NHEAD;
    const int rs = 3 * DMODEL;
    long base = (long)b * NSEQ * rs + h * HDIM;

    extern __shared__ f16 SM[];
    uint32_t u0 = (uint32_t)__cvta_generic_to_shared(SM);
    const uint32_t uQh = u0;
    const uint32_t uQl = uQh + 128 * KSQ * 2;
    const uint32_t uK0 = uQl + 128 * KSQ * 2;           // 2 stages of Kh
    const uint32_t uV0 = uK0 + 2 * 128 * KSQ * 2;       // 2 stages of V

    int tid = threadIdx.x, lane = tid & 31, wq = tid >> 5;
    int fr = lane >> 2, fc = lane & 3;

    // ---- load Q tile (cp.async, hi/lo) ----
    {
        int r = tid >> 1, c0 = (tid & 1) * 32;
        const f16* g = qkvh + base + (long)(qi * 128 + r) * rs + c0;
        uint32_t s = uQh + (r * KSQ + c0) * 2;
        cp16(s, g); cp16(s + 16, g + 8); cp16(s + 32, g + 16); cp16(s + 48, g + 24);
        g = qkvl + base + (long)(qi * 128 + r) * rs + c0;
        s = uQl + (r * KSQ + c0) * 2;
        cp16(s, g); cp16(s + 16, g + 8); cp16(s + 32, g + 16); cp16(s + 48, g + 24);
        asm volatile("cp.async.commit_group;\n" ::: "memory");
    }

    // ---- K/V stage loader ----
    auto ldKV = [&](int kt, int st) {
        int r = tid >> 1, c0 = (tid & 1) * 32;
        const f16* g = qkvh + base + DMODEL + (long)(kt * 128 + r) * rs + c0;
        uint32_t s = uK0 + st * (128 * KSQ * 2) + (r * KSQ + c0) * 2;
        cp16(s, g); cp16(s + 16, g + 8); cp16(s + 32, g + 16); cp16(s + 48, g + 24);
        g = qkvh + base + 2 * DMODEL + (long)(kt * 128 + r) * rs + c0;
        s = uV0 + st * (128 * KSVR * 2) + (r * KSVR + c0) * 2;
        cp16(s, g); cp16(s + 16, g + 8); cp16(s + 32, g + 16); cp16(s + 48, g + 24);
        asm volatile("cp.async.commit_group;\n" ::: "memory");
    };

    ldKV(0, 0);

    float m0 = -1e30f, m1 = -1e30f, l0 = 0.f, l1 = 0.f;
    float o[8][4] = {};

    for (int kt = 0; kt <= qi; kt++) {
        int st = kt & 1;
        if (kt + 1 <= qi) {
            ldKV(kt + 1, st ^ 1);
            asm volatile("cp.async.wait_group 1;\n" ::: "memory");
        } else {
            asm volatile("cp.async.wait_group 0;\n" ::: "memory");
        }
        __syncthreads();

        uint32_t uKh = uK0 + st * (128 * KSQ * 2);
        uint32_t uVh = uV0 + st * (128 * KSVR * 2);

        // ---- S = Q @ K^T (2-term fp16) ----
        float ss[16][4];
#pragma unroll
        for (int i = 0; i < 16; i++)
#pragma unroll
            for (int r = 0; r < 4; r++) ss[i][r] = 0.f;

#pragma unroll
        for (int ks4 = 0; ks4 < 4; ks4++) {
            int ks = ks4 * 16;
            uint32_t ah[4], al[4];
            uint32_t aoff = ((wq * 16 + (lane & 15)) * KSQ + ks + ((lane >> 4) << 3)) * 2;
            ldm4(ah, uQh + aoff);
            ldm4(al, uQl + aoff);
#pragma unroll
            for (int nip = 0; nip < 8; nip++) {
                uint32_t bh[4];
                uint32_t boff = ((nip * 16 + ((lane >> 4) << 3) + (lane & 7)) * KSQ
                                 + ks + (((lane >> 3) & 1) << 3)) * 2;
                ldm4(bh, uKh + boff);
                int ni = nip * 2;
                mma16816h(ss[ni], ah, bh);     mma16816h(ss[ni + 1], ah, bh + 2);
                mma16816h(ss[ni], al, bh);     mma16816h(ss[ni + 1], al, bh + 2);
            }
        }

        // ---- scale + causal mask ----
#pragma unroll
        for (int i = 0; i < 16; i++)
#pragma unroll
            for (int r = 0; r < 4; r++) ss[i][r] *= 0.125f;
        if (kt == qi) {
#pragma unroll
            for (int i = 0; i < 16; i++)
#pragma unroll
                for (int r = 0; r < 4; r++) {
                    int col = i * 8 + fc * 2 + (r & 1);
                    int row = wq * 16 + fr + ((r >> 1) << 3);
                    if (col > row) ss[i][r] = -1e30f;
                }
        }

        // ---- online softmax ----
        float mx0 = -1e30f, mx1 = -1e30f;
#pragma unroll
        for (int i = 0; i < 16; i++) {
            mx0 = fmaxf(mx0, fmaxf(ss[i][0], ss[i][1]));
            mx1 = fmaxf(mx1, fmaxf(ss[i][2], ss[i][3]));
        }
        mx0 = fmaxf(mx0, __shfl_xor_sync(0xffffffffu, mx0, 1));
        mx0 = fmaxf(mx0, __shfl_xor_sync(0xffffffffu, mx0, 2));
        mx1 = fmaxf(mx1, __shfl_xor_sync(0xffffffffu, mx1, 1));
        mx1 = fmaxf(mx1, __shfl_xor_sync(0xffffffffu, mx1, 2));

        float mn0 = fmaxf(m0, mx0), mn1 = fmaxf(m1, mx1);
        float al0 = __expf(m0 - mn0), al1 = __expf(m1 - mn1);
        float sum0 = 0.f, sum1 = 0.f;
#pragma unroll
        for (int i = 0; i < 16; i++) {
            ss[i][0] = __expf(ss[i][0] - mn0); sum0 += ss[i][0];
            ss[i][1] = __expf(ss[i][1] - mn0); sum0 += ss[i][1];
            ss[i][2] = __expf(ss[i][2] - mn1); sum1 += ss[i][2];
            ss[i][3] = __expf(ss[i][3] - mn1); sum1 += ss[i][3];
        }
        sum0 += __shfl_xor_sync(0xffffffffu, sum0, 1);
        sum0 += __shfl_xor_sync(0xffffffffu, sum0, 2);
        sum1 += __shfl_xor_sync(0xffffffffu, sum1, 1);
        sum1 += __shfl_xor_sync(0xffffffffu, sum1, 2);
        l0 = l0 * al0 + sum0;
        l1 = l1 * al1 + sum1;
        m0 = mn0; m1 = mn1;
#pragma unroll
        for (int v = 0; v < 8; v++) {
            o[v][0] *= al0; o[v][1] *= al0;
            o[v][2] *= al1; o[v][3] *= al1;
        }

        // ---- O += P @ V (P hi/lo fp16 from regs, V via ldmatrix.trans) ----
        int g8 = lane >> 3;                    // 0..3
        int koff = (g8 & 1) * 8 + (lane & 7);  // source k-row within 16
        int noff = (g8 >> 1) * 8;              // source n-col base within 16
#pragma unroll
        for (int ks = 0; ks < 8; ks++) {
            uint32_t ahi[4], alo[4];
            ahi[0] = pack2h(ss[2 * ks][0], ss[2 * ks][1]);
            ahi[1] = pack2h(ss[2 * ks][2], ss[2 * ks][3]);
            ahi[2] = pack2h(ss[2 * ks + 1][0], ss[2 * ks + 1][1]);
            ahi[3] = pack2h(ss[2 * ks + 1][2], ss[2 * ks + 1][3]);
            alo[0] = packlo2h(ss[2 * ks][0], ss[2 * ks][1]);
            alo[1] = packlo2h(ss[2 * ks][2], ss[2 * ks][3]);
            alo[2] = packlo2h(ss[2 * ks + 1][0], ss[2 * ks + 1][1]);
            alo[3] = packlo2h(ss[2 * ks + 1][2], ss[2 * ks + 1][3]);
#pragma unroll
            for (int nvp = 0; nvp < 4; nvp++) {
                uint32_t bv[4];
                uint32_t boff = ((ks * 16 + koff) * KSVR + nvp * 16 + noff) * 2;
                ldm4t(bv, uVh + boff);
                int nv = nvp * 2;
                mma16816h(o[nv], ahi, bv);     mma16816h(o[nv + 1], ahi, bv + 2);
                mma16816h(o[nv], alo, bv);     mma16816h(o[nv + 1], alo, bv + 2);
            }
        }
        __syncthreads();   // all reads of stage st done before it is overwritten
    }

    // ---- epilogue: O /= l, paired __half2 writes ----
    float inv0 = 1.f / l0, inv1 = 1.f / l1;
    int row0 = qi * 128 + wq * 16 + fr;
#pragma unroll
    for (int v = 0; v < 8; v++) {
#pragma unroll
        for (int rp = 0; rp < 2; rp++) {
            int row = row0 + rp * 8;
            int col = h * HDIM + v * 8 + fc * 2;
            float inv = rp ? inv1 : inv0;
            float v0 = o[v][rp * 2] * inv, v1 = o[v][rp * 2 + 1] * inv;
            long gi = (long)(b * NSEQ + row) * DMODEL + col;
            f16 h0 = __float2half(v0), h1 = __float2half(v1);
            __half2 hh; hh.x = h0; hh.y = h1;
            __half2 ll;
            ll.x = __float2half(v0 - __half2float(h0));
            ll.y = __float2half(v1 - __half2float(h1));
            *(__half2*)&attnh[gi] = hh;
            *(__half2*)&attnl[gi] = ll;
        }
    }
}

// ---------------------------------------------------------------------------
// Tensor-core GEMM template (fp16), 2-stage cp.async double buffer.
//   NMMA=2: 2-term hi/lo (Ah/Al + Bh; acc = Ah.Bh + Al.Bh).
//   NMMA=1: single-term (Ah, Bh only).
//   flags: 1=residual, 2=exact GELU, 8=write fp32 C, 16=write fp16 hi/lo,
//          32=grid swapped (blockIdx.x = m-tile, blockIdx.y = n-tile).
//   loN: Cl (lo) written only for columns < loN.
// ---------------------------------------------------------------------------
template<int NMMA>
__global__ __launch_bounds__(256, 2) void bgemm_kernel(
    const uint16_t* __restrict__ Ah, const uint16_t* __restrict__ Al, int lda,
    const uint16_t* __restrict__ Bh, int ldb,
    float* __restrict__ C, f16* __restrict__ Ch, f16* __restrict__ Cl, int ldc,
    const float* __restrict__ bias,
    int M, int N, int K, int flags, int loN) {

    constexpr int TPS = (NMMA == 2) ? 3 : 2;             // tiles per stage
    constexpr int BH_OFF = (NMMA == 2) ? 2 * TILE_E : TILE_E;

    int m0, n0;
    if (flags & 32) { m0 = blockIdx.x * 128; n0 = blockIdx.y * 128; }
    else            { m0 = blockIdx.y * 128; n0 = blockIdx.x * 128; }

    extern __shared__ uint16_t S[];
    uint32_t sbase = (uint32_t)__cvta_generic_to_shared(S);

    int tid = threadIdx.x, lane = tid & 31, wid = tid >> 5;
    int wm = wid & 1, wn = wid >> 1;
    int fr = lane >> 2, fc = lane & 3;

    int r2 = tid >> 1;
    int c2 = (tid & 1) * 16;

    float acc[4][4][4];
#pragma unroll
    for (int i = 0; i < 4; i++)
#pragma unroll
        for (int j = 0; j < 4; j++)
#pragma unroll
            for (int r = 0; r < 4; r++) acc[i][j][r] = 0.f;

    auto ldStage = [&](int k0, int bufi) {
        uint32_t sb = sbase + bufi * (TPS * TILE_E * 2);
        uint32_t sa = sb + r2 * (KS * 2) + c2 * 2;
        const uint16_t* ga = Ah + (long)(m0 + r2) * lda + k0 + c2;
        cp16(sa, ga);            cp16(sa + 16, ga + 8);
        if (NMMA == 2) {
            ga = Al + (long)(m0 + r2) * lda + k0 + c2;
            cp16(sa + TILE_E * 2, ga); cp16(sa + TILE_E * 2 + 16, ga + 8);
        }
        int gn = n0 + r2;
        uint32_t sbB = sb + BH_OFF * 2 + r2 * (KS * 2) + c2 * 2;
        if (gn < N) {
            const uint16_t* gb = Bh + (long)gn * ldb + k0 + c2;
            cp16(sbB, gb);            cp16(sbB + 16, gb + 8);
        } else {
            uint4 zz = make_uint4(0, 0, 0, 0);
            uint16_t* p = S + bufi * TPS * TILE_E + BH_OFF + r2 * KS + c2;
            *(uint4*)p = zz; *(uint4*)(p + 8) = zz;
        }
        asm volatile("cp.async.commit_group;\n" ::: "memory");
    };

    ldStage(0, 0);

    // per-thread ldmatrix address components (elem offsets)
    int aRow = wm * 64 + (lane & 15);
    int aColX = (lane >> 4) << 3;
    int bRow = wn * 32 + ((lane >> 4) << 3) + (lane & 7);
    int bColX = ((lane >> 3) & 1) << 3;

    int KT = K >> 5;
    int buf = 0;
    for (int kt = 0; kt < KT; kt++) {
        asm volatile("cp.async.wait_group 0;\n" ::: "memory");
        __syncthreads();
        if (kt + 1 < KT) ldStage((kt + 1) << 5, buf ^ 1);

        uint32_t sb = sbase + buf * (TPS * TILE_E * 2);

#pragma unroll
        for (int ks = 0; ks < 32; ks += 16) {
            uint32_t ah[4][4], bh[4][2];
            uint32_t aA = sb + (aRow * KS + ks + aColX) * 2;
            uint32_t bB = sb + BH_OFF * 2 + (bRow * KS + ks + bColX) * 2;
#pragma unroll
            for (int mi = 0; mi < 4; mi++) ldm4(ah[mi], aA + mi * (16 * KS * 2));
#pragma unroll
            for (int nip = 0; nip < 2; nip++)
                ldm4(&bh[nip * 2][0], bB + nip * (16 * KS * 2));

#pragma unroll
            for (int mi = 0; mi < 4; mi++)
#pragma unroll
                for (int ni = 0; ni < 4; ni++)
                    mma16816h(acc[mi][ni], ah[mi], bh[ni]);

            if (NMMA == 2) {
                uint32_t al[4][4];
#pragma unroll
                for (int mi = 0; mi < 4; mi++)
                    ldm4(al[mi], aA + mi * (16 * KS * 2) + TILE_E * 2);
#pragma unroll
                for (int mi = 0; mi < 4; mi++)
#pragma unroll
                    for (int ni = 0; ni < 4; ni++)
                        mma16816h(acc[mi][ni], al[mi], bh[ni]);
            }
        }
        __syncthreads();
        buf ^= 1;
    }

    // Epilogue: r-pairs (adjacent columns) -> paired __half2 f16 stores.
#pragma unroll
    for (int mi = 0; mi < 4; mi++) {
        int gm0 = m0 + wm * 64 + mi * 16 + fr;
#pragma unroll
        for (int ni = 0; ni < 4; ni++) {
            int gn = n0 + wn * 32 + ni * 8 + fc * 2;
#pragma unroll
            for (int rp = 0; rp < 2; rp++) {
                int gm = gm0 + rp * 8;
                float v0 = acc[mi][ni][rp * 2];
                float v1 = acc[mi][ni][rp * 2 + 1];
                if (bias) {
                    if (gn < N)     v0 += bias[gn];
                    if (gn + 1 < N) v1 += bias[gn + 1];
                }
                if (flags & 2) {
                    v0 = 0.5f * v0 * (1.f + erff(v0 * 0.70710678118654752f));
                    v1 = 0.5f * v1 * (1.f + erff(v1 * 0.70710678118654752f));
                }
                long idx = (long)gm * ldc + gn;
                if (flags & 1) {
                    if (gn < N)     v0 += C[idx];
                    if (gn + 1 < N) v1 += C[idx + 1];
                }
                if (flags & 8) {
                    if (gn < N)     C[idx] = v0;
                    if (gn + 1 < N) C[idx + 1] = v1;
                }
                if (flags & 16) {
                    f16 h0 = __float2half(v0), h1 = __float2half(v1);
                    if (gn + 1 < N) {
                        __half2 hh; hh.x = h0; hh.y = h1;
                        *(__half2*)&Ch[idx] = hh;
                        if (gn + 1 < loN) {
                            __half2 ll;
                            ll.x = __float2half(v0 - __half2float(h0));
                            ll.y = __float2half(v1 - __half2float(h1));
                            *(__half2*)&Cl[idx] = ll;
                        }
                    } else if (gn < N) {
                        Ch[idx] = h0;
                        if (gn < loN)
                            Cl[idx] = __float2half(v0 - __half2float(h0));
                    }
                }
            }
        }
    }
}

// ---------------------------------------------------------------------------
// Host-side orchestration
// ---------------------------------------------------------------------------
extern "C" void kernel_launch(void* const* d_in, const int* in_sizes, int n_in,
                              void* d_out, int out_size) {
    (void)in_sizes; (void)n_in; (void)out_size;

    const int*   tok     = (const int*)  d_in[0];
    const float* wte     = (const float*)d_in[1];
    const float* wpe     = (const float*)d_in[2];
    const float* ln1_w   = (const float*)d_in[3];
    const float* ln1_b   = (const float*)d_in[4];
    const float* attn_w  = (const float*)d_in[5];
    const float* attn_b  = (const float*)d_in[6];
    const float* aproj_w = (const float*)d_in[7];
    const float* aproj_b = (const float*)d_in[8];
    const float* ln2_w   = (const float*)d_in[9];
    const float* ln2_b   = (const float*)d_in[10];
    const float* fc_w    = (const float*)d_in[11];
    const float* fc_b    = (const float*)d_in[12];
    const float* mproj_w = (const float*)d_in[13];
    const float* mproj_b = (const float*)d_in[14];
    const float* lnf_w   = (const float*)d_in[15];
    const float* lnf_b   = (const float*)d_in[16];
    float* out = (float*)d_out;

    float *x;
    f16 *lnh, *lnl, *qkvh, *qkvl, *attnh, *attnl, *midh, *midl;
    f16 *wqkvh, *waph, *wfch, *wmph, *wtef, *lnf16;
    cudaGetSymbolAddress((void**)&x,      g_x);
    cudaGetSymbolAddress((void**)&lnh,    g_lnh);
    cudaGetSymbolAddress((void**)&lnl,    g_lnl);
    cudaGetSymbolAddress((void**)&qkvh,   g_qkvh);
    cudaGetSymbolAddress((void**)&qkvl,   g_qkvl);
    cudaGetSymbolAddress((void**)&attnh,  g_attnh);
    cudaGetSymbolAddress((void**)&attnl,  g_attnl);
    cudaGetSymbolAddress((void**)&midh,   g_midh);
    cudaGetSymbolAddress((void**)&midl,   g_midl);
    cudaGetSymbolAddress((void**)&wqkvh,  g_wqkvh);
    cudaGetSymbolAddress((void**)&waph,   g_waph);
    cudaGetSymbolAddress((void**)&wfch,   g_wfch);
    cudaGetSymbolAddress((void**)&wmph,   g_wmph);
    cudaGetSymbolAddress((void**)&wtef,   g_wtef);
    cudaGetSymbolAddress((void**)&lnf16,  g_lnf16);

    const int D = DMODEL;
    const int SMEM2 = 2 * 3 * TILE_E * 2;                  // 61440 (2 stages x 3 tiles)
    const int SMEM1 = 2 * 2 * TILE_E * 2;                  // 40960 (2 stages x 2 tiles)
    const int FSMEM = (2 * 128 * KSQ + 2 * 128 * KSQ + 2 * 128 * KSVR) * 2; // 110592

    cudaFuncSetAttribute(bgemm_kernel<2>,
                         cudaFuncAttributeMaxDynamicSharedMemorySize, SMEM2);
    cudaFuncSetAttribute(bgemm_kernel<1>,
                         cudaFuncAttributeMaxDynamicSharedMemorySize, SMEM1);
    cudaFuncSetAttribute(flash_kernel,
                         cudaFuncAttributeMaxDynamicSharedMemorySize, FSMEM);

    // ---- weight prep (once per call) ----
    {
        dim3 b32(32, 8);
        tsplit_kernel<<<dim3(D / 32, 3 * D / 32, NLAYER), b32>>>(attn_w,  wqkvh, D, 3 * D);
        tsplit_kernel<<<dim3(D / 32, D / 32, NLAYER),     b32>>>(aproj_w, waph,  D, D);
        tsplit_kernel<<<dim3(D / 32, 4 * D / 32, NLAYER), b32>>>(fc_w,    wfch,  D, 4 * D);
        tsplit_kernel<<<dim3(4 * D / 32, D / 32, NLAYER), b32>>>(mproj_w, wmph,  4 * D, D);
        long nwte = (long)NVOCAB * D;
        splitf16_kernel<<<(unsigned)((nwte + 255) / 256), 256>>>(wte, wtef, nwte);
    }

    embed_kernel<<<NTOK, 256>>>(tok, wte, wpe, x);

    for (int l = 0; l < NLAYER; l++) {
        layernorm_kernel<<<NTOK / 8, 256>>>(x, ln1_w + l * D, ln1_b + l * D, lnh, lnl);

        // qkv = h @ attn_w[l] + attn_b[l] -> fp16 hi (+lo for Q cols only)
        {
            dim3 g(3 * D / 128, NTOK / 128);
            bgemm_kernel<2><<<g, 256, SMEM2>>>(
                (const uint16_t*)lnh, (const uint16_t*)lnl, D,
                (const uint16_t*)(wqkvh + (long)l * 3 * D * D), D,
                nullptr, qkvh, qkvl, 3 * D,
                attn_b + (long)l * 3 * D,
                NTOK, 3 * D, D, 16, D);
        }

        // fused flash attention -> attnh/attnl
        flash_kernel<<<dim3(NSEQ / 128, 2 * NHEAD), 256, FSMEM>>>(qkvh, qkvl, attnh, attnl);

        // x += attn @ aproj_w[l] + aproj_b[l]
        {
            dim3 g(D / 128, NTOK / 128);
            bgemm_kernel<2><<<g, 256, SMEM2>>>(
                (const uint16_t*)attnh, (const uint16_t*)attnl, D,
                (const uint16_t*)(waph + (long)l * D * D), D,
                x, nullptr, nullptr, D,
                aproj_b + (long)l * D,
                NTOK, D, D, 1 | 8, 0);
        }

        layernorm_kernel<<<NTOK / 8, 256>>>(x, ln2_w + l * D, ln2_b + l * D, lnh, lnl);

        // mid = gelu(h @ fc_w[l] + fc_b[l]) -> fp16 hi/lo
        {
            dim3 g(4 * D / 128, NTOK / 128);
            bgemm_kernel<2><<<g, 256, SMEM2>>>(
                (const uint16_t*)lnh, (const uint16_t*)lnl, D,
                (const uint16_t*)(wfch + (long)l * 4 * D * D), D,
                nullptr, midh, midl, 4 * D,
                fc_b + (long)l * 4 * D,
                NTOK, 4 * D, D, 2 | 16, 4 * D);
        }

        // x += mid @ mproj_w[l] + mproj_b[l]
        {
            dim3 g(D / 128, NTOK / 128);
            bgemm_kernel<2><<<g, 256, SMEM2>>>(
                (const uint16_t*)midh, (const uint16_t*)midl, 4 * D,
                (const uint16_t*)(wmph + (long)l * D * 4 * D), 4 * D,
                x, nullptr, nullptr, D,
                mproj_b + (long)l * D,
                NTOK, D, 4 * D, 1 | 8, 0);
        }
    }

    // final LN (fp16) + tied lm_head in single-term fp16: out = LN_f(x) @ wte^T
    layernorm_f16_kernel<<<NTOK / 8, 256>>>(x, lnf_w, lnf_b, lnf16);
    {
        dim3 g(NTOK / 128, (NVOCAB + 127) / 128);
        bgemm_kernel<1><<<g, 256, SMEM1>>>(
            (const uint16_t*)lnf16, nullptr, D,
            (const uint16_t*)wtef, D,
            out, nullptr, nullptr, NVOCAB,
            nullptr,
            NTOK, NVOCAB, D, 8 | 32, 0);
    }
}

// round 16
// speedup vs baseline: 1.5085x; 1.0100x over previous
#include <cuda_runtime.h>
#include <cuda_bf16.h>
#include <cuda_fp16.h>
#include <math.h>
#include <stdint.h>

// Problem constants
#define DMODEL 768
#define NTOK   2048          // B*N = 2*1024
#define NSEQ   1024
#define NHEAD  12
#define HDIM   64
#define NLAYER 12
#define NVOCAB 50257

#define KS 40                 // gemm smem k-stride in 16-bit elems (conflict-free)
#define TILE_E (128 * KS)     // elems per smem tile array
#define KSQ 72                // flash Q/K smem stride (64+8)
#define KSVR 72               // flash V row-major smem stride (64+8)

typedef __half f16;

// ---------------------------------------------------------------------------
// Device-global scratch (allocation-free)
// ---------------------------------------------------------------------------
__device__ float g_x[NTOK * DMODEL];                  // residual stream (fp32)

// activations, fp16 hi/lo (lo = A-side correction term)
__device__ f16 g_lnh[NTOK * DMODEL],      g_lnl[NTOK * DMODEL];
__device__ f16 g_qkvh[NTOK * 3 * DMODEL], g_qkvl[NTOK * 3 * DMODEL];
__device__ f16 g_attnh[NTOK * DMODEL],    g_attnl[NTOK * DMODEL];
__device__ f16 g_midh[NTOK * 4 * DMODEL], g_midl[NTOK * 4 * DMODEL];

// final-LN output in fp16 (lm_head only)
__device__ f16 g_lnf16[NTOK * DMODEL];

// weights, transposed to [N,K], fp16 (hi only — B side is single-term)
__device__ f16 g_wqkvh[NLAYER * 3 * DMODEL * DMODEL];
__device__ f16 g_waph [NLAYER * DMODEL * DMODEL];
__device__ f16 g_wfch [NLAYER * 4 * DMODEL * DMODEL];
__device__ f16 g_wmph [NLAYER * DMODEL * 4 * DMODEL];
__device__ f16 g_wtef[(long)NVOCAB * DMODEL];         // wte in fp16 (lm_head)

// ---------------------------------------------------------------------------
// Helpers
// ---------------------------------------------------------------------------
__device__ __forceinline__ void cp16(uint32_t saddr, const void* gaddr) {
    asm volatile("cp.async.cg.shared.global [%0], [%1], 16;\n"
                 :: "r"(saddr), "l"(gaddr));
}

__device__ __forceinline__ void mma16816h(float* d, const uint32_t* a, const uint32_t* b) {
    asm volatile(
        "mma.sync.aligned.m16n8k16.row.col.f32.f16.f16.f32 "
        "{%0,%1,%2,%3},{%4,%5,%6,%7},{%8,%9},{%0,%1,%2,%3};\n"
        : "+f"(d[0]), "+f"(d[1]), "+f"(d[2]), "+f"(d[3])
        : "r"(a[0]), "r"(a[1]), "r"(a[2]), "r"(a[3]), "r"(b[0]), "r"(b[1]));
}

__device__ __forceinline__ void ldm4(uint32_t* r, uint32_t addr) {
    asm volatile("ldmatrix.sync.aligned.m8n8.x4.shared.b16 {%0,%1,%2,%3}, [%4];\n"
                 : "=r"(r[0]), "=r"(r[1]), "=r"(r[2]), "=r"(r[3]) : "r"(addr));
}

__device__ __forceinline__ void ldm4t(uint32_t* r, uint32_t addr) {
    asm volatile("ldmatrix.sync.aligned.m8n8.x4.trans.shared.b16 {%0,%1,%2,%3}, [%4];\n"
                 : "=r"(r[0]), "=r"(r[1]), "=r"(r[2]), "=r"(r[3]) : "r"(addr));
}

__device__ __forceinline__ uint32_t pack2h(float a, float b) {
    __half2 t = __floats2half2_rn(a, b);
    return *(uint32_t*)&t;
}
__device__ __forceinline__ uint32_t packlo2h(float a, float b) {
    float la = a - __half2float(__float2half(a));
    float lb = b - __half2float(__float2half(b));
    return pack2h(la, lb);
}

__device__ __forceinline__ float warpReduceSum(float v) {
#pragma unroll
    for (int o = 16; o; o >>= 1) v += __shfl_xor_sync(0xffffffffu, v, o);
    return v;
}

// ---------------------------------------------------------------------------
// Weight prep: transpose W[z][K][N] -> T[z][N][K], fp16 (hi only)
// ---------------------------------------------------------------------------
__global__ void tsplit_kernel(const float* __restrict__ W,
                              f16* __restrict__ Th, int K, int N) {
    __shared__ float t[32][33];
    long zoff = (long)blockIdx.z * K * N;
    W += zoff; Th += zoff;
    int k0 = blockIdx.x * 32, n0 = blockIdx.y * 32;
    int tx = threadIdx.x, ty = threadIdx.y;
#pragma unroll
    for (int i = 0; i < 4; i++)
        t[ty + i * 8][tx] = W[(long)(k0 + ty + i * 8) * N + n0 + tx];
    __syncthreads();
#pragma unroll
    for (int i = 0; i < 4; i++) {
        int n = n0 + ty + i * 8, k = k0 + tx;
        Th[(long)n * K + k] = __float2half(t[tx][ty + i * 8]);
    }
}

// Elementwise fp32 -> fp16, vectorized 4/thread (total count divisible by 4)
__global__ void splitf16_kernel(const float* __restrict__ in,
                                f16* __restrict__ o, long n4) {
    long i = (long)blockIdx.x * 256 + threadIdx.x;
    if (i < n4) {
        float4 v = ((const float4*)in)[i];
        __half2 a = __floats2half2_rn(v.x, v.y);
        __half2 b = __floats2half2_rn(v.z, v.w);
        ((__half2*)o)[i * 2] = a;
        ((__half2*)o)[i * 2 + 1] = b;
    }
}

// ---------------------------------------------------------------------------
// Embedding (float4 vectorized; D = 768 = 192 float4)
// ---------------------------------------------------------------------------
__global__ void embed_kernel(const int* __restrict__ tok,
                             const float* __restrict__ wte,
                             const float* __restrict__ wpe,
                             float* __restrict__ x) {
    int t = blockIdx.x;
    int n = t & (NSEQ - 1);
    int id = tok[t];
    const float4* w1 = (const float4*)(wte + (long)id * DMODEL);
    const float4* w2 = (const float4*)(wpe + (long)n * DMODEL);
    float4* xo = (float4*)(x + (long)t * DMODEL);
    for (int d = threadIdx.x; d < DMODEL / 4; d += blockDim.x) {
        float4 a = w1[d], b = w2[d];
        a.x += b.x; a.y += b.y; a.z += b.z; a.w += b.w;
        xo[d] = a;
    }
}

// ---------------------------------------------------------------------------
// Warp-per-row LayerNorm: fp32 in -> fp16 hi/lo out.
// ---------------------------------------------------------------------------
__global__ __launch_bounds__(256) void layernorm_kernel(
    const float* __restrict__ x, const float* __restrict__ w,
    const float* __restrict__ b,
    f16* __restrict__ oh, f16* __restrict__ ol) {
    int lane = threadIdx.x & 31, wq = threadIdx.x >> 5;
    int t = blockIdx.x * 8 + wq;
    const float* xr = x + (long)t * DMODEL;
    long base = (long)t * DMODEL;

    float lx[24];
    float s = 0.f;
#pragma unroll
    for (int i = 0; i < 24; i++) { lx[i] = xr[lane + i * 32]; s += lx[i]; }
    s = warpReduceSum(s);
    float mu = s * (1.f / 768.f);

    float var = 0.f;
#pragma unroll
    for (int i = 0; i < 24; i++) { float d = lx[i] - mu; var += d * d; }
    var = warpReduceSum(var);
    float rstd = rsqrtf(var * (1.f / 768.f) + 1e-5f);

#pragma unroll
    for (int i = 0; i < 24; i++) {
        int d = lane + i * 32;
        float v = (lx[i] - mu) * rstd * w[d] + b[d];
        f16 h = __float2half(v);
        oh[base + d] = h;
        ol[base + d] = __float2half(v - __half2float(h));
    }
}

// Warp-per-row LayerNorm: fp32 in -> single fp16 out (final LN)
__global__ __launch_bounds__(256) void layernorm_f16_kernel(
    const float* __restrict__ x, const float* __restrict__ w,
    const float* __restrict__ b, f16* __restrict__ o) {
    int lane = threadIdx.x & 31, wq = threadIdx.x >> 5;
    int t = blockIdx.x * 8 + wq;
    const float* xr = x + (long)t * DMODEL;
    long base = (long)t * DMODEL;

    float lx[24];
    float s = 0.f;
#pragma unroll
    for (int i = 0; i < 24; i++) { lx[i] = xr[lane + i * 32]; s += lx[i]; }
    s = warpReduceSum(s);
    float mu = s * (1.f / 768.f);

    float var = 0.f;
#pragma unroll
    for (int i = 0; i < 24; i++) { float d = lx[i] - mu; var += d * d; }
    var = warpReduceSum(var);
    float rstd = rsqrtf(var * (1.f / 768.f) + 1e-5f);

#pragma unroll
    for (int i = 0; i < 24; i++) {
        int d = lane + i * 32;
        float v = (lx[i] - mu) * rstd * w[d] + b[d];
        o[base + d] = __float2half(v);
    }
}

// ---------------------------------------------------------------------------
// Flash attention, fp16 2-term, K/V double-buffered.
// One block per (q-tile of 128 rows, head z); 8 warps, 16 q-rows each.
// qi reversed (LPT). Smem: Qh, Ql [128*KSQ], Kh[2], V[2] stages.
// ---------------------------------------------------------------------------
__global__ __launch_bounds__(256) void flash_kernel(
    const f16* __restrict__ qkvh, const f16* __restrict__ qkvl,
    f16* __restrict__ attnh, f16* __restrict__ attnl) {

    int qi = gridDim.x - 1 - blockIdx.x;   // LPT: heavy q-tiles start first
    int z = blockIdx.y;
    int b = z / NHEAD, h = z - b * NHEAD;
    const int rs = 3 * DMODEL;
    long base = (long)b * NSEQ * rs + h * HDIM;

    extern __shared__ f16 SM[];
    uint32_t u0 = (uint32_t)__cvta_generic_to_shared(SM);
    const uint32_t uQh = u0;
    const uint32_t uQl = uQh + 128 * KSQ * 2;
    const uint32_t uK0 = uQl + 128 * KSQ * 2;           // 2 stages of Kh
    const uint32_t uV0 = uK0 + 2 * 128 * KSQ * 2;       // 2 stages of V

    int tid = threadIdx.x, lane = tid & 31, wq = tid >> 5;
    int fr = lane >> 2, fc = lane & 3;

    // ---- load Q tile (cp.async, hi/lo) ----
    {
        int r = tid >> 1, c0 = (tid & 1) * 32;
        const f16* g = qkvh + base + (long)(qi * 128 + r) * rs + c0;
        uint32_t s = uQh + (r * KSQ + c0) * 2;
        cp16(s, g); cp16(s + 16, g + 8); cp16(s + 32, g + 16); cp16(s + 48, g + 24);
        g = qkvl + base + (long)(qi * 128 + r) * rs + c0;
        s = uQl + (r * KSQ + c0) * 2;
        cp16(s, g); cp16(s + 16, g + 8); cp16(s + 32, g + 16); cp16(s + 48, g + 24);
        asm volatile("cp.async.commit_group;\n" ::: "memory");
    }

    // ---- K/V stage loader ----
    auto ldKV = [&](int kt, int st) {
        int r = tid >> 1, c0 = (tid & 1) * 32;
        const f16* g = qkvh + base + DMODEL + (long)(kt * 128 + r) * rs + c0;
        uint32_t s = uK0 + st * (128 * KSQ * 2) + (r * KSQ + c0) * 2;
        cp16(s, g); cp16(s + 16, g + 8); cp16(s + 32, g + 16); cp16(s + 48, g + 24);
        g = qkvh + base + 2 * DMODEL + (long)(kt * 128 + r) * rs + c0;
        s = uV0 + st * (128 * KSVR * 2) + (r * KSVR + c0) * 2;
        cp16(s, g); cp16(s + 16, g + 8); cp16(s + 32, g + 16); cp16(s + 48, g + 24);
        asm volatile("cp.async.commit_group;\n" ::: "memory");
    };

    ldKV(0, 0);

    float m0 = -1e30f, m1 = -1e30f, l0 = 0.f, l1 = 0.f;
    float o[8][4] = {};

    for (int kt = 0; kt <= qi; kt++) {
        int st = kt & 1;
        if (kt + 1 <= qi) {
            ldKV(kt + 1, st ^ 1);
            asm volatile("cp.async.wait_group 1;\n" ::: "memory");
        } else {
            asm volatile("cp.async.wait_group 0;\n" ::: "memory");
        }
        __syncthreads();

        uint32_t uKh = uK0 + st * (128 * KSQ * 2);
        uint32_t uVh = uV0 + st * (128 * KSVR * 2);

        // ---- S = Q @ K^T (2-term fp16) ----
        float ss[16][4];
#pragma unroll
        for (int i = 0; i < 16; i++)
#pragma unroll
            for (int r = 0; r < 4; r++) ss[i][r] = 0.f;

#pragma unroll
        for (int ks4 = 0; ks4 < 4; ks4++) {
            int ks = ks4 * 16;
            uint32_t ah[4], al[4];
            uint32_t aoff = ((wq * 16 + (lane & 15)) * KSQ + ks + ((lane >> 4) << 3)) * 2;
            ldm4(ah, uQh + aoff);
            ldm4(al, uQl + aoff);
#pragma unroll
            for (int nip = 0; nip < 8; nip++) {
                uint32_t bh[4];
                uint32_t boff = ((nip * 16 + ((lane >> 4) << 3) + (lane & 7)) * KSQ
                                 + ks + (((lane >> 3) & 1) << 3)) * 2;
                ldm4(bh, uKh + boff);
                int ni = nip * 2;
                mma16816h(ss[ni], ah, bh);     mma16816h(ss[ni + 1], ah, bh + 2);
                mma16816h(ss[ni], al, bh);     mma16816h(ss[ni + 1], al, bh + 2);
            }
        }

        // ---- scale + causal mask ----
#pragma unroll
        for (int i = 0; i < 16; i++)
#pragma unroll
            for (int r = 0; r < 4; r++) ss[i][r] *= 0.125f;
        if (kt == qi) {
#pragma unroll
            for (int i = 0; i < 16; i++)
#pragma unroll
                for (int r = 0; r < 4; r++) {
                    int col = i * 8 + fc * 2 + (r & 1);
                    int row = wq * 16 + fr + ((r >> 1) << 3);
                    if (col > row) ss[i][r] = -1e30f;
                }
        }

        // ---- online softmax ----
        float mx0 = -1e30f, mx1 = -1e30f;
#pragma unroll
        for (int i = 0; i < 16; i++) {
            mx0 = fmaxf(mx0, fmaxf(ss[i][0], ss[i][1]));
            mx1 = fmaxf(mx1, fmaxf(ss[i][2], ss[i][3]));
        }
        mx0 = fmaxf(mx0, __shfl_xor_sync(0xffffffffu, mx0, 1));
        mx0 = fmaxf(mx0, __shfl_xor_sync(0xffffffffu, mx0, 2));
        mx1 = fmaxf(mx1, __shfl_xor_sync(0xffffffffu, mx1, 1));
        mx1 = fmaxf(mx1, __shfl_xor_sync(0xffffffffu, mx1, 2));

        float mn0 = fmaxf(m0, mx0), mn1 = fmaxf(m1, mx1);
        float al0 = __expf(m0 - mn0), al1 = __expf(m1 - mn1);
        float sum0 = 0.f, sum1 = 0.f;
#pragma unroll
        for (int i = 0; i < 16; i++) {
            ss[i][0] = __expf(ss[i][0] - mn0); sum0 += ss[i][0];
            ss[i][1] = __expf(ss[i][1] - mn0); sum0 += ss[i][1];
            ss[i][2] = __expf(ss[i][2] - mn1); sum1 += ss[i][2];
            ss[i][3] = __expf(ss[i][3] - mn1); sum1 += ss[i][3];
        }
        sum0 += __shfl_xor_sync(0xffffffffu, sum0, 1);
        sum0 += __shfl_xor_sync(0xffffffffu, sum0, 2);
        sum1 += __shfl_xor_sync(0xffffffffu, sum1, 1);
        sum1 += __shfl_xor_sync(0xffffffffu, sum1, 2);
        l0 = l0 * al0 + sum0;
        l1 = l1 * al1 + sum1;
        m0 = mn0; m1 = mn1;
#pragma unroll
        for (int v = 0; v < 8; v++) {
            o[v][0] *= al0; o[v][1] *= al0;
            o[v][2] *= al1; o[v][3] *= al1;
        }

        // ---- O += P @ V (P hi/lo fp16 from regs, V via ldmatrix.trans) ----
        int g8 = lane >> 3;                    // 0..3
        int koff = (g8 & 1) * 8 + (lane & 7);  // source k-row within 16
        int noff = (g8 >> 1) * 8;              // source n-col base within 16
#pragma unroll
        for (int ks = 0; ks < 8; ks++) {
            uint32_t ahi[4], alo[4];
            ahi[0] = pack2h(ss[2 * ks][0], ss[2 * ks][1]);
            ahi[1] = pack2h(ss[2 * ks][2], ss[2 * ks][3]);
            ahi[2] = pack2h(ss[2 * ks + 1][0], ss[2 * ks + 1][1]);
            ahi[3] = pack2h(ss[2 * ks + 1][2], ss[2 * ks + 1][3]);
            alo[0] = packlo2h(ss[2 * ks][0], ss[2 * ks][1]);
            alo[1] = packlo2h(ss[2 * ks][2], ss[2 * ks][3]);
            alo[2] = packlo2h(ss[2 * ks + 1][0], ss[2 * ks + 1][1]);
            alo[3] = packlo2h(ss[2 * ks + 1][2], ss[2 * ks + 1][3]);
#pragma unroll
            for (int nvp = 0; nvp < 4; nvp++) {
                uint32_t bv[4];
                uint32_t boff = ((ks * 16 + koff) * KSVR + nvp * 16 + noff) * 2;
                ldm4t(bv, uVh + boff);
                int nv = nvp * 2;
                mma16816h(o[nv], ahi, bv);     mma16816h(o[nv + 1], ahi, bv + 2);
                mma16816h(o[nv], alo, bv);     mma16816h(o[nv + 1], alo, bv + 2);
            }
        }
        __syncthreads();   // all reads of stage st done before it is overwritten
    }

    // ---- epilogue: O /= l, paired __half2 writes ----
    float inv0 = 1.f / l0, inv1 = 1.f / l1;
    int row0 = qi * 128 + wq * 16 + fr;
#pragma unroll
    for (int v = 0; v < 8; v++) {
#pragma unroll
        for (int rp = 0; rp < 2; rp++) {
            int row = row0 + rp * 8;
            int col = h * HDIM + v * 8 + fc * 2;
            float inv = rp ? inv1 : inv0;
            float v0 = o[v][rp * 2] * inv, v1 = o[v][rp * 2 + 1] * inv;
            long gi = (long)(b * NSEQ + row) * DMODEL + col;
            f16 h0 = __float2half(v0), h1 = __float2half(v1);
            __half2 hh; hh.x = h0; hh.y = h1;
            __half2 ll;
            ll.x = __float2half(v0 - __half2float(h0));
            ll.y = __float2half(v1 - __half2float(h1));
            *(__half2*)&attnh[gi] = hh;
            *(__half2*)&attnl[gi] = ll;
        }
    }
}

// ---------------------------------------------------------------------------
// Tensor-core GEMM template (fp16), 2-stage cp.async double buffer.
//   NMMA=2: 2-term hi/lo (Ah/Al + Bh; acc = Ah.Bh + Al.Bh).
//   NMMA=1: single-term (Ah, Bh only).
//   flags: 1=residual, 2=exact GELU, 8=write fp32 C, 16=write fp16 hi/lo,
//          32=grid swapped (blockIdx.x = m-tile, blockIdx.y = n-tile).
//   loN: Cl (lo) written only for columns < loN.
// ---------------------------------------------------------------------------
template<int NMMA>
__global__ __launch_bounds__(256, 2) void bgemm_kernel(
    const uint16_t* __restrict__ Ah, const uint16_t* __restrict__ Al, int lda,
    const uint16_t* __restrict__ Bh, int ldb,
    float* __restrict__ C, f16* __restrict__ Ch, f16* __restrict__ Cl, int ldc,
    const float* __restrict__ bias,
    int M, int N, int K, int flags, int loN) {

    constexpr int TPS = (NMMA == 2) ? 3 : 2;             // tiles per stage
    constexpr int BH_OFF = (NMMA == 2) ? 2 * TILE_E : TILE_E;

    int m0, n0;
    if (flags & 32) { m0 = blockIdx.x * 128; n0 = blockIdx.y * 128; }
    else            { m0 = blockIdx.y * 128; n0 = blockIdx.x * 128; }

    extern __shared__ uint16_t S[];
    uint32_t sbase = (uint32_t)__cvta_generic_to_shared(S);

    int tid = threadIdx.x, lane = tid & 31, wid = tid >> 5;
    int wm = wid & 1, wn = wid >> 1;
    int fr = lane >> 2, fc = lane & 3;

    int r2 = tid >> 1;
    int c2 = (tid & 1) * 16;

    float acc[4][4][4];
#pragma unroll
    for (int i = 0; i < 4; i++)
#pragma unroll
        for (int j = 0; j < 4; j++)
#pragma unroll
            for (int r = 0; r < 4; r++) acc[i][j][r] = 0.f;

    auto ldStage = [&](int k0, int bufi) {
        uint32_t sb = sbase + bufi * (TPS * TILE_E * 2);
        uint32_t sa = sb + r2 * (KS * 2) + c2 * 2;
        const uint16_t* ga = Ah + (long)(m0 + r2) * lda + k0 + c2;
        cp16(sa, ga);            cp16(sa + 16, ga + 8);
        if (NMMA == 2) {
            ga = Al + (long)(m0 + r2) * lda + k0 + c2;
            cp16(sa + TILE_E * 2, ga); cp16(sa + TILE_E * 2 + 16, ga + 8);
        }
        int gn = n0 + r2;
        uint32_t sbB = sb + BH_OFF * 2 + r2 * (KS * 2) + c2 * 2;
        if (gn < N) {
            const uint16_t* gb = Bh + (long)gn * ldb + k0 + c2;
            cp16(sbB, gb);            cp16(sbB + 16, gb + 8);
        } else {
            uint4 zz = make_uint4(0, 0, 0, 0);
            uint16_t* p = S + bufi * TPS * TILE_E + BH_OFF + r2 * KS + c2;
            *(uint4*)p = zz; *(uint4*)(p + 8) = zz;
        }
        asm volatile("cp.async.commit_group;\n" ::: "memory");
    };

    ldStage(0, 0);

    // per-thread ldmatrix address components (elem offsets)
    int aRow = wm * 64 + (lane & 15);
    int aColX = (lane >> 4) << 3;
    int bRow = wn * 32 + ((lane >> 4) << 3) + (lane & 7);
    int bColX = ((lane >> 3) & 1) << 3;

    int KT = K >> 5;
    int buf = 0;
    for (int kt = 0; kt < KT; kt++) {
        asm volatile("cp.async.wait_group 0;\n" ::: "memory");
        __syncthreads();
        if (kt + 1 < KT) ldStage((kt + 1) << 5, buf ^ 1);

        uint32_t sb = sbase + buf * (TPS * TILE_E * 2);

#pragma unroll
        for (int ks = 0; ks < 32; ks += 16) {
            uint32_t ah[4][4], bh[4][2];
            uint32_t aA = sb + (aRow * KS + ks + aColX) * 2;
            uint32_t bB = sb + BH_OFF * 2 + (bRow * KS + ks + bColX) * 2;
#pragma unroll
            for (int mi = 0; mi < 4; mi++) ldm4(ah[mi], aA + mi * (16 * KS * 2));
#pragma unroll
            for (int nip = 0; nip < 2; nip++)
                ldm4(&bh[nip * 2][0], bB + nip * (16 * KS * 2));

#pragma unroll
            for (int mi = 0; mi < 4; mi++)
#pragma unroll
                for (int ni = 0; ni < 4; ni++)
                    mma16816h(acc[mi][ni], ah[mi], bh[ni]);

            if (NMMA == 2) {
                uint32_t al[4][4];
#pragma unroll
                for (int mi = 0; mi < 4; mi++)
                    ldm4(al[mi], aA + mi * (16 * KS * 2) + TILE_E * 2);
#pragma unroll
                for (int mi = 0; mi < 4; mi++)
#pragma unroll
                    for (int ni = 0; ni < 4; ni++)
                        mma16816h(acc[mi][ni], al[mi], bh[ni]);
            }
        }
        __syncthreads();
        buf ^= 1;
    }

    // Epilogue: r-pairs (adjacent columns); paired f16 and (ldc even) f32 ops.
    bool evenC = ((ldc & 1) == 0);
#pragma unroll
    for (int mi = 0; mi < 4; mi++) {
        int gm0 = m0 + wm * 64 + mi * 16 + fr;
#pragma unroll
        for (int ni = 0; ni < 4; ni++) {
            int gn = n0 + wn * 32 + ni * 8 + fc * 2;
#pragma unroll
            for (int rp = 0; rp < 2; rp++) {
                int gm = gm0 + rp * 8;
                float v0 = acc[mi][ni][rp * 2];
                float v1 = acc[mi][ni][rp * 2 + 1];
                if (bias) {
                    if (gn < N)     v0 += bias[gn];
                    if (gn + 1 < N) v1 += bias[gn + 1];
                }
                if (flags & 2) {
                    v0 = 0.5f * v0 * (1.f + erff(v0 * 0.70710678118654752f));
                    v1 = 0.5f * v1 * (1.f + erff(v1 * 0.70710678118654752f));
                }
                long idx = (long)gm * ldc + gn;
                if (flags & 1) {
                    if (evenC && gn + 1 < N) {
                        float2 c2v = *(const float2*)&C[idx];
                        v0 += c2v.x; v1 += c2v.y;
                    } else {
                        if (gn < N)     v0 += C[idx];
                        if (gn + 1 < N) v1 += C[idx + 1];
                    }
                }
                if (flags & 8) {
                    if (evenC && gn + 1 < N) {
                        *(float2*)&C[idx] = make_float2(v0, v1);
                    } else {
                        if (gn < N)     C[idx] = v0;
                        if (gn + 1 < N) C[idx + 1] = v1;
                    }
                }
                if (flags & 16) {
                    f16 h0 = __float2half(v0), h1 = __float2half(v1);
                    if (gn + 1 < N) {
                        __half2 hh; hh.x = h0; hh.y = h1;
                        *(__half2*)&Ch[idx] = hh;
                        if (gn + 1 < loN) {
                            __half2 ll;
                            ll.x = __float2half(v0 - __half2float(h0));
                            ll.y = __float2half(v1 - __half2float(h1));
                            *(__half2*)&Cl[idx] = ll;
                        }
                    } else if (gn < N) {
                        Ch[idx] = h0;
                        if (gn < loN)
                            Cl[idx] = __float2half(v0 - __half2float(h0));
                    }
                }
            }
        }
    }
}

// ---------------------------------------------------------------------------
// Host-side orchestration
// ---------------------------------------------------------------------------
extern "C" void kernel_launch(void* const* d_in, const int* in_sizes, int n_in,
                              void* d_out, int out_size) {
    (void)in_sizes; (void)n_in; (void)out_size;

    const int*   tok     = (const int*)  d_in[0];
    const float* wte     = (const float*)d_in[1];
    const float* wpe     = (const float*)d_in[2];
    const float* ln1_w   = (const float*)d_in[3];
    const float* ln1_b   = (const float*)d_in[4];
    const float* attn_w  = (const float*)d_in[5];
    const float* attn_b  = (const float*)d_in[6];
    const float* aproj_w = (const float*)d_in[7];
    const float* aproj_b = (const float*)d_in[8];
    const float* ln2_w   = (const float*)d_in[9];
    const float* ln2_b   = (const float*)d_in[10];
    const float* fc_w    = (const float*)d_in[11];
    const float* fc_b    = (const float*)d_in[12];
    const float* mproj_w = (const float*)d_in[13];
    const float* mproj_b = (const float*)d_in[14];
    const float* lnf_w   = (const float*)d_in[15];
    const float* lnf_b   = (const float*)d_in[16];
    float* out = (float*)d_out;

    float *x;
    f16 *lnh, *lnl, *qkvh, *qkvl, *attnh, *attnl, *midh, *midl;
    f16 *wqkvh, *waph, *wfch, *wmph, *wtef, *lnf16;
    cudaGetSymbolAddress((void**)&x,      g_x);
    cudaGetSymbolAddress((void**)&lnh,    g_lnh);
    cudaGetSymbolAddress((void**)&lnl,    g_lnl);
    cudaGetSymbolAddress((void**)&qkvh,   g_qkvh);
    cudaGetSymbolAddress((void**)&qkvl,   g_qkvl);
    cudaGetSymbolAddress((void**)&attnh,  g_attnh);
    cudaGetSymbolAddress((void**)&attnl,  g_attnl);
    cudaGetSymbolAddress((void**)&midh,   g_midh);
    cudaGetSymbolAddress((void**)&midl,   g_midl);
    cudaGetSymbolAddress((void**)&wqkvh,  g_wqkvh);
    cudaGetSymbolAddress((void**)&waph,   g_waph);
    cudaGetSymbolAddress((void**)&wfch,   g_wfch);
    cudaGetSymbolAddress((void**)&wmph,   g_wmph);
    cudaGetSymbolAddress((void**)&wtef,   g_wtef);
    cudaGetSymbolAddress((void**)&lnf16,  g_lnf16);

    const int D = DMODEL;
    const int SMEM2 = 2 * 3 * TILE_E * 2;                  // 61440 (2 stages x 3 tiles)
    const int SMEM1 = 2 * 2 * TILE_E * 2;                  // 40960 (2 stages x 2 tiles)
    const int FSMEM = (2 * 128 * KSQ + 2 * 128 * KSQ + 2 * 128 * KSVR) * 2; // 110592

    cudaFuncSetAttribute(bgemm_kernel<2>,
                         cudaFuncAttributeMaxDynamicSharedMemorySize, SMEM2);
    cudaFuncSetAttribute(bgemm_kernel<1>,
                         cudaFuncAttributeMaxDynamicSharedMemorySize, SMEM1);
    cudaFuncSetAttribute(flash_kernel,
                         cudaFuncAttributeMaxDynamicSharedMemorySize, FSMEM);

    // ---- weight prep (once per call) ----
    {
        dim3 b32(32, 8);
        tsplit_kernel<<<dim3(D / 32, 3 * D / 32, NLAYER), b32>>>(attn_w,  wqkvh, D, 3 * D);
        tsplit_kernel<<<dim3(D / 32, D / 32, NLAYER),     b32>>>(aproj_w, waph,  D, D);
        tsplit_kernel<<<dim3(D / 32, 4 * D / 32, NLAYER), b32>>>(fc_w,    wfch,  D, 4 * D);
        tsplit_kernel<<<dim3(4 * D / 32, D / 32, NLAYER), b32>>>(mproj_w, wmph,  4 * D, D);
        long nwte4 = (long)NVOCAB * D / 4;
        splitf16_kernel<<<(unsigned)((nwte4 + 255) / 256), 256>>>(wte, wtef, nwte4);
    }

    embed_kernel<<<NTOK, 192>>>(tok, wte, wpe, x);

    for (int l = 0; l < NLAYER; l++) {
        layernorm_kernel<<<NTOK / 8, 256>>>(x, ln1_w + l * D, ln1_b + l * D, lnh, lnl);

        // qkv = h @ attn_w[l] + attn_b[l] -> fp16 hi (+lo for Q cols only)
        {
            dim3 g(3 * D / 128, NTOK / 128);
            bgemm_kernel<2><<<g, 256, SMEM2>>>(
                (const uint16_t*)lnh, (const uint16_t*)lnl, D,
                (const uint16_t*)(wqkvh + (long)l * 3 * D * D), D,
                nullptr, qkvh, qkvl, 3 * D,
                attn_b + (long)l * 3 * D,
                NTOK, 3 * D, D, 16, D);
        }

        // fused flash attention -> attnh/attnl
        flash_kernel<<<dim3(NSEQ / 128, 2 * NHEAD), 256, FSMEM>>>(qkvh, qkvl, attnh, attnl);

        // x += attn @ aproj_w[l] + aproj_b[l]
        {
            dim3 g(D / 128, NTOK / 128);
            bgemm_kernel<2><<<g, 256, SMEM2>>>(
                (const uint16_t*)attnh, (const uint16_t*)attnl, D,
                (const uint16_t*)(waph + (long)l * D * D), D,
                x, nullptr, nullptr, D,
                aproj_b + (long)l * D,
                NTOK, D, D, 1 | 8, 0);
        }

        layernorm_kernel<<<NTOK / 8, 256>>>(x, ln2_w + l * D, ln2_b + l * D, lnh, lnl);

        // mid = gelu(h @ fc_w[l] + fc_b[l]) -> fp16 hi/lo
        {
            dim3 g(4 * D / 128, NTOK / 128);
            bgemm_kernel<2><<<g, 256, SMEM2>>>(
                (const uint16_t*)lnh, (const uint16_t*)lnl, D,
                (const uint16_t*)(wfch + (long)l * 4 * D * D), D,
                nullptr, midh, midl, 4 * D,
                fc_b + (long)l * 4 * D,
                NTOK, 4 * D, D, 2 | 16, 4 * D);
        }

        // x += mid @ mproj_w[l] + mproj_b[l]
        {
            dim3 g(D / 128, NTOK / 128);
            bgemm_kernel<2><<<g, 256, SMEM2>>>(
                (const uint16_t*)midh, (const uint16_t*)midl, 4 * D,
                (const uint16_t*)(wmph + (long)l * D * 4 * D), 4 * D,
                x, nullptr, nullptr, D,
                mproj_b + (long)l * D,
                NTOK, D, 4 * D, 1 | 8, 0);
        }
    }

    // final LN (fp16) + tied lm_head in single-term fp16: out = LN_f(x) @ wte^T
    layernorm_f16_kernel<<<NTOK / 8, 256>>>(x, lnf_w, lnf_b, lnf16);
    {
        dim3 g(NTOK / 128, (NVOCAB + 127) / 128);
        bgemm_kernel<1><<<g, 256, SMEM1>>>(
            (const uint16_t*)lnf16, nullptr, D,
            (const uint16_t*)wtef, D,
            out, nullptr, nullptr, NVOCAB,
            nullptr,
            NTOK, NVOCAB, D, 8 | 32, 0);
    }
}

// round 17
// speedup vs baseline: 1.5130x; 1.0030x over previous
#include <cuda_runtime.h>
#include <cuda_bf16.h>
#include <cuda_fp16.h>
#include <math.h>
#include <stdint.h>

// Problem constants
#define DMODEL 768
#define NTOK   2048          // B*N = 2*1024
#define NSEQ   1024
#define NHEAD  12
#define HDIM   64
#define NLAYER 12
#define NVOCAB 50257

#define KS 40                 // gemm smem k-stride in 16-bit elems (conflict-free)
#define TILE_E (128 * KS)     // elems per smem tile array
#define KSQ 72                // flash Q/K smem stride (64+8)
#define KSVR 72               // flash V row-major smem stride (64+8)

typedef __half f16;

// ---------------------------------------------------------------------------
// Device-global scratch (allocation-free)
// ---------------------------------------------------------------------------
__device__ float g_x[NTOK * DMODEL];                  // residual stream (fp32)

// activations, fp16 hi/lo (lo = A-side correction term)
__device__ f16 g_lnh[NTOK * DMODEL],      g_lnl[NTOK * DMODEL];
__device__ f16 g_qkvh[NTOK * 3 * DMODEL], g_qkvl[NTOK * 3 * DMODEL];
__device__ f16 g_attnh[NTOK * DMODEL],    g_attnl[NTOK * DMODEL];
__device__ f16 g_midh[NTOK * 4 * DMODEL], g_midl[NTOK * 4 * DMODEL];

// final-LN output in fp16 (lm_head only)
__device__ f16 g_lnf16[NTOK * DMODEL];

// weights, transposed to [N,K], fp16 (hi only — B side is single-term)
__device__ f16 g_wqkvh[NLAYER * 3 * DMODEL * DMODEL];
__device__ f16 g_waph [NLAYER * DMODEL * DMODEL];
__device__ f16 g_wfch [NLAYER * 4 * DMODEL * DMODEL];
__device__ f16 g_wmph [NLAYER * DMODEL * 4 * DMODEL];
__device__ f16 g_wtef[(long)NVOCAB * DMODEL];         // wte in fp16 (lm_head)

// ---------------------------------------------------------------------------
// Helpers
// ---------------------------------------------------------------------------
__device__ __forceinline__ void cp16(uint32_t saddr, const void* gaddr) {
    asm volatile("cp.async.cg.shared.global [%0], [%1], 16;\n"
                 :: "r"(saddr), "l"(gaddr));
}

__device__ __forceinline__ void mma16816h(float* d, const uint32_t* a, const uint32_t* b) {
    asm volatile(
        "mma.sync.aligned.m16n8k16.row.col.f32.f16.f16.f32 "
        "{%0,%1,%2,%3},{%4,%5,%6,%7},{%8,%9},{%0,%1,%2,%3};\n"
        : "+f"(d[0]), "+f"(d[1]), "+f"(d[2]), "+f"(d[3])
        : "r"(a[0]), "r"(a[1]), "r"(a[2]), "r"(a[3]), "r"(b[0]), "r"(b[1]));
}

__device__ __forceinline__ void ldm4(uint32_t* r, uint32_t addr) {
    asm volatile("ldmatrix.sync.aligned.m8n8.x4.shared.b16 {%0,%1,%2,%3}, [%4];\n"
                 : "=r"(r[0]), "=r"(r[1]), "=r"(r[2]), "=r"(r[3]) : "r"(addr));
}

__device__ __forceinline__ void ldm4t(uint32_t* r, uint32_t addr) {
    asm volatile("ldmatrix.sync.aligned.m8n8.x4.trans.shared.b16 {%0,%1,%2,%3}, [%4];\n"
                 : "=r"(r[0]), "=r"(r[1]), "=r"(r[2]), "=r"(r[3]) : "r"(addr));
}

__device__ __forceinline__ uint32_t pack2h(float a, float b) {
    __half2 t = __floats2half2_rn(a, b);
    return *(uint32_t*)&t;
}
__device__ __forceinline__ uint32_t packlo2h(float a, float b) {
    float la = a - __half2float(__float2half(a));
    float lb = b - __half2float(__float2half(b));
    return pack2h(la, lb);
}

__device__ __forceinline__ float warpReduceSum(float v) {
#pragma unroll
    for (int o = 16; o; o >>= 1) v += __shfl_xor_sync(0xffffffffu, v, o);
    return v;
}

// ---------------------------------------------------------------------------
// Weight prep: transpose W[z][K][N] -> T[z][N][K], fp16 (hi only).
// Paired __half2 writes (two adjacent k per thread) for full-width sectors.
// ---------------------------------------------------------------------------
__global__ void tsplit_kernel(const float* __restrict__ W,
                              f16* __restrict__ Th, int K, int N) {
    __shared__ float t[32][33];    // [k-local][n-local]
    long zoff = (long)blockIdx.z * K * N;
    W += zoff; Th += zoff;
    int k0 = blockIdx.x * 32, n0 = blockIdx.y * 32;
    int tx = threadIdx.x, ty = threadIdx.y;      // block (32, 8)
#pragma unroll
    for (int i = 0; i < 4; i++)
        t[ty + i * 8][tx] = W[(long)(k0 + ty + i * 8) * N + n0 + tx];
    __syncthreads();
    // write: each thread covers 2 adjacent k at one n-row; 2 iterations x
    // (8 ty x 2 tx-halves) = 32 n-rows.
    int c = (tx & 15) * 2;                        // k-local pair base
    int nh = (tx >> 4) * 8;                       // n-row half offset
#pragma unroll
    for (int i = 0; i < 2; i++) {
        int nn = ty + nh + i * 16;                // n-local
        __half2 h;
        h.x = __float2half(t[c][nn]);
        h.y = __float2half(t[c + 1][nn]);
        *(__half2*)&Th[(long)(n0 + nn) * K + k0 + c] = h;
    }
}

// Elementwise fp32 -> fp16, vectorized 4/thread (total count divisible by 4)
__global__ void splitf16_kernel(const float* __restrict__ in,
                                f16* __restrict__ o, long n4) {
    long i = (long)blockIdx.x * 256 + threadIdx.x;
    if (i < n4) {
        float4 v = ((const float4*)in)[i];
        __half2 a = __floats2half2_rn(v.x, v.y);
        __half2 b = __floats2half2_rn(v.z, v.w);
        ((__half2*)o)[i * 2] = a;
        ((__half2*)o)[i * 2 + 1] = b;
    }
}

// ---------------------------------------------------------------------------
// Embedding (float4 vectorized; D = 768 = 192 float4)
// ---------------------------------------------------------------------------
__global__ void embed_kernel(const int* __restrict__ tok,
                             const float* __restrict__ wte,
                             const float* __restrict__ wpe,
                             float* __restrict__ x) {
    int t = blockIdx.x;
    int n = t & (NSEQ - 1);
    int id = tok[t];
    const float4* w1 = (const float4*)(wte + (long)id * DMODEL);
    const float4* w2 = (const float4*)(wpe + (long)n * DMODEL);
    float4* xo = (float4*)(x + (long)t * DMODEL);
    for (int d = threadIdx.x; d < DMODEL / 4; d += blockDim.x) {
        float4 a = w1[d], b = w2[d];
        a.x += b.x; a.y += b.y; a.z += b.z; a.w += b.w;
        xo[d] = a;
    }
}

// ---------------------------------------------------------------------------
// Warp-per-row LayerNorm: fp32 in -> fp16 hi/lo out.
// ---------------------------------------------------------------------------
__global__ __launch_bounds__(256) void layernorm_kernel(
    const float* __restrict__ x, const float* __restrict__ w,
    const float* __restrict__ b,
    f16* __restrict__ oh, f16* __restrict__ ol) {
    int lane = threadIdx.x & 31, wq = threadIdx.x >> 5;
    int t = blockIdx.x * 8 + wq;
    const float* xr = x + (long)t * DMODEL;
    long base = (long)t * DMODEL;

    float lx[24];
    float s = 0.f;
#pragma unroll
    for (int i = 0; i < 24; i++) { lx[i] = xr[lane + i * 32]; s += lx[i]; }
    s = warpReduceSum(s);
    float mu = s * (1.f / 768.f);

    float var = 0.f;
#pragma unroll
    for (int i = 0; i < 24; i++) { float d = lx[i] - mu; var += d * d; }
    var = warpReduceSum(var);
    float rstd = rsqrtf(var * (1.f / 768.f) + 1e-5f);

#pragma unroll
    for (int i = 0; i < 24; i++) {
        int d = lane + i * 32;
        float v = (lx[i] - mu) * rstd * w[d] + b[d];
        f16 h = __float2half(v);
        oh[base + d] = h;
        ol[base + d] = __float2half(v - __half2float(h));
    }
}

// Warp-per-row LayerNorm: fp32 in -> single fp16 out (final LN)
__global__ __launch_bounds__(256) void layernorm_f16_kernel(
    const float* __restrict__ x, const float* __restrict__ w,
    const float* __restrict__ b, f16* __restrict__ o) {
    int lane = threadIdx.x & 31, wq = threadIdx.x >> 5;
    int t = blockIdx.x * 8 + wq;
    const float* xr = x + (long)t * DMODEL;
    long base = (long)t * DMODEL;

    float lx[24];
    float s = 0.f;
#pragma unroll
    for (int i = 0; i < 24; i++) { lx[i] = xr[lane + i * 32]; s += lx[i]; }
    s = warpReduceSum(s);
    float mu = s * (1.f / 768.f);

    float var = 0.f;
#pragma unroll
    for (int i = 0; i < 24; i++) { float d = lx[i] - mu; var += d * d; }
    var = warpReduceSum(var);
    float rstd = rsqrtf(var * (1.f / 768.f) + 1e-5f);

#pragma unroll
    for (int i = 0; i < 24; i++) {
        int d = lane + i * 32;
        float v = (lx[i] - mu) * rstd * w[d] + b[d];
        o[base + d] = __float2half(v);
    }
}

// ---------------------------------------------------------------------------
// Flash attention, fp16 2-term, K/V double-buffered.
// One block per (q-tile of 128 rows, head z); 8 warps, 16 q-rows each.
// qi reversed (LPT). Smem: Qh, Ql [128*KSQ], Kh[2], V[2] stages.
// ---------------------------------------------------------------------------
__global__ __launch_bounds__(256) void flash_kernel(
    const f16* __restrict__ qkvh, const f16* __restrict__ qkvl,
    f16* __restrict__ attnh, f16* __restrict__ attnl) {

    int qi = gridDim.x - 1 - blockIdx.x;   // LPT: heavy q-tiles start first
    int z = blockIdx.y;
    int b = z / NHEAD, h = z - b * NHEAD;
    const int rs = 3 * DMODEL;
    long base = (long)b * NSEQ * rs + h * HDIM;

    extern __shared__ f16 SM[];
    uint32_t u0 = (uint32_t)__cvta_generic_to_shared(SM);
    const uint32_t uQh = u0;
    const uint32_t uQl = uQh + 128 * KSQ * 2;
    const uint32_t uK0 = uQl + 128 * KSQ * 2;           // 2 stages of Kh
    const uint32_t uV0 = uK0 + 2 * 128 * KSQ * 2;       // 2 stages of V

    int tid = threadIdx.x, lane = tid & 31, wq = tid >> 5;
    int fr = lane >> 2, fc = lane & 3;

    // ---- load Q tile (cp.async, hi/lo) ----
    {
        int r = tid >> 1, c0 = (tid & 1) * 32;
        const f16* g = qkvh + base + (long)(qi * 128 + r) * rs + c0;
        uint32_t s = uQh + (r * KSQ + c0) * 2;
        cp16(s, g); cp16(s + 16, g + 8); cp16(s + 32, g + 16); cp16(s + 48, g + 24);
        g = qkvl + base + (long)(qi * 128 + r) * rs + c0;
        s = uQl + (r * KSQ + c0) * 2;
        cp16(s, g); cp16(s + 16, g + 8); cp16(s + 32, g + 16); cp16(s + 48, g + 24);
        asm volatile("cp.async.commit_group;\n" ::: "memory");
    }

    // ---- K/V stage loader ----
    auto ldKV = [&](int kt, int st) {
        int r = tid >> 1, c0 = (tid & 1) * 32;
        const f16* g = qkvh + base + DMODEL + (long)(kt * 128 + r) * rs + c0;
        uint32_t s = uK0 + st * (128 * KSQ * 2) + (r * KSQ + c0) * 2;
        cp16(s, g); cp16(s + 16, g + 8); cp16(s + 32, g + 16); cp16(s + 48, g + 24);
        g = qkvh + base + 2 * DMODEL + (long)(kt * 128 + r) * rs + c0;
        s = uV0 + st * (128 * KSVR * 2) + (r * KSVR + c0) * 2;
        cp16(s, g); cp16(s + 16, g + 8); cp16(s + 32, g + 16); cp16(s + 48, g + 24);
        asm volatile("cp.async.commit_group;\n" ::: "memory");
    };

    ldKV(0, 0);

    float m0 = -1e30f, m1 = -1e30f, l0 = 0.f, l1 = 0.f;
    float o[8][4] = {};

    for (int kt = 0; kt <= qi; kt++) {
        int st = kt & 1;
        if (kt + 1 <= qi) {
            ldKV(kt + 1, st ^ 1);
            asm volatile("cp.async.wait_group 1;\n" ::: "memory");
        } else {
            asm volatile("cp.async.wait_group 0;\n" ::: "memory");
        }
        __syncthreads();

        uint32_t uKh = uK0 + st * (128 * KSQ * 2);
        uint32_t uVh = uV0 + st * (128 * KSVR * 2);

        // ---- S = Q @ K^T (2-term fp16) ----
        float ss[16][4];
#pragma unroll
        for (int i = 0; i < 16; i++)
#pragma unroll
            for (int r = 0; r < 4; r++) ss[i][r] = 0.f;

#pragma unroll
        for (int ks4 = 0; ks4 < 4; ks4++) {
            int ks = ks4 * 16;
            uint32_t ah[4], al[4];
            uint32_t aoff = ((wq * 16 + (lane & 15)) * KSQ + ks + ((lane >> 4) << 3)) * 2;
            ldm4(ah, uQh + aoff);
            ldm4(al, uQl + aoff);
#pragma unroll
            for (int nip = 0; nip < 8; nip++) {
                uint32_t bh[4];
                uint32_t boff = ((nip * 16 + ((lane >> 4) << 3) + (lane & 7)) * KSQ
                                 + ks + (((lane >> 3) & 1) << 3)) * 2;
                ldm4(bh, uKh + boff);
                int ni = nip * 2;
                mma16816h(ss[ni], ah, bh);     mma16816h(ss[ni + 1], ah, bh + 2);
                mma16816h(ss[ni], al, bh);     mma16816h(ss[ni + 1], al, bh + 2);
            }
        }

        // ---- scale + causal mask ----
#pragma unroll
        for (int i = 0; i < 16; i++)
#pragma unroll
            for (int r = 0; r < 4; r++) ss[i][r] *= 0.125f;
        if (kt == qi) {
#pragma unroll
            for (int i = 0; i < 16; i++)
#pragma unroll
                for (int r = 0; r < 4; r++) {
                    int col = i * 8 + fc * 2 + (r & 1);
                    int row = wq * 16 + fr + ((r >> 1) << 3);
                    if (col > row) ss[i][r] = -1e30f;
                }
        }

        // ---- online softmax ----
        float mx0 = -1e30f, mx1 = -1e30f;
#pragma unroll
        for (int i = 0; i < 16; i++) {
            mx0 = fmaxf(mx0, fmaxf(ss[i][0], ss[i][1]));
            mx1 = fmaxf(mx1, fmaxf(ss[i][2], ss[i][3]));
        }
        mx0 = fmaxf(mx0, __shfl_xor_sync(0xffffffffu, mx0, 1));
        mx0 = fmaxf(mx0, __shfl_xor_sync(0xffffffffu, mx0, 2));
        mx1 = fmaxf(mx1, __shfl_xor_sync(0xffffffffu, mx1, 1));
        mx1 = fmaxf(mx1, __shfl_xor_sync(0xffffffffu, mx1, 2));

        float mn0 = fmaxf(m0, mx0), mn1 = fmaxf(m1, mx1);
        float al0 = __expf(m0 - mn0), al1 = __expf(m1 - mn1);
        float sum0 = 0.f, sum1 = 0.f;
#pragma unroll
        for (int i = 0; i < 16; i++) {
            ss[i][0] = __expf(ss[i][0] - mn0); sum0 += ss[i][0];
            ss[i][1] = __expf(ss[i][1] - mn0); sum0 += ss[i][1];
            ss[i][2] = __expf(ss[i][2] - mn1); sum1 += ss[i][2];
            ss[i][3] = __expf(ss[i][3] - mn1); sum1 += ss[i][3];
        }
        sum0 += __shfl_xor_sync(0xffffffffu, sum0, 1);
        sum0 += __shfl_xor_sync(0xffffffffu, sum0, 2);
        sum1 += __shfl_xor_sync(0xffffffffu, sum1, 1);
        sum1 += __shfl_xor_sync(0xffffffffu, sum1, 2);
        l0 = l0 * al0 + sum0;
        l1 = l1 * al1 + sum1;
        m0 = mn0; m1 = mn1;
#pragma unroll
        for (int v = 0; v < 8; v++) {
            o[v][0] *= al0; o[v][1] *= al0;
            o[v][2] *= al1; o[v][3] *= al1;
        }

        // ---- O += P @ V (P hi/lo fp16 from regs, V via ldmatrix.trans) ----
        int g8 = lane >> 3;                    // 0..3
        int koff = (g8 & 1) * 8 + (lane & 7);  // source k-row within 16
        int noff = (g8 >> 1) * 8;              // source n-col base within 16
#pragma unroll
        for (int ks = 0; ks < 8; ks++) {
            uint32_t ahi[4], alo[4];
            ahi[0] = pack2h(ss[2 * ks][0], ss[2 * ks][1]);
            ahi[1] = pack2h(ss[2 * ks][2], ss[2 * ks][3]);
            ahi[2] = pack2h(ss[2 * ks + 1][0], ss[2 * ks + 1][1]);
            ahi[3] = pack2h(ss[2 * ks + 1][2], ss[2 * ks + 1][3]);
            alo[0] = packlo2h(ss[2 * ks][0], ss[2 * ks][1]);
            alo[1] = packlo2h(ss[2 * ks][2], ss[2 * ks][3]);
            alo[2] = packlo2h(ss[2 * ks + 1][0], ss[2 * ks + 1][1]);
            alo[3] = packlo2h(ss[2 * ks + 1][2], ss[2 * ks + 1][3]);
#pragma unroll
            for (int nvp = 0; nvp < 4; nvp++) {
                uint32_t bv[4];
                uint32_t boff = ((ks * 16 + koff) * KSVR + nvp * 16 + noff) * 2;
                ldm4t(bv, uVh + boff);
                int nv = nvp * 2;
                mma16816h(o[nv], ahi, bv);     mma16816h(o[nv + 1], ahi, bv + 2);
                mma16816h(o[nv], alo, bv);     mma16816h(o[nv + 1], alo, bv + 2);
            }
        }
        __syncthreads();   // all reads of stage st done before it is overwritten
    }

    // ---- epilogue: O /= l, paired __half2 writes ----
    float inv0 = 1.f / l0, inv1 = 1.f / l1;
    int row0 = qi * 128 + wq * 16 + fr;
#pragma unroll
    for (int v = 0; v < 8; v++) {
#pragma unroll
        for (int rp = 0; rp < 2; rp++) {
            int row = row0 + rp * 8;
            int col = h * HDIM + v * 8 + fc * 2;
            float inv = rp ? inv1 : inv0;
            float v0 = o[v][rp * 2] * inv, v1 = o[v][rp * 2 + 1] * inv;
            long gi = (long)(b * NSEQ + row) * DMODEL + col;
            f16 h0 = __float2half(v0), h1 = __float2half(v1);
            __half2 hh; hh.x = h0; hh.y = h1;
            __half2 ll;
            ll.x = __float2half(v0 - __half2float(h0));
            ll.y = __float2half(v1 - __half2float(h1));
            *(__half2*)&attnh[gi] = hh;
            *(__half2*)&attnl[gi] = ll;
        }
    }
}

// ---------------------------------------------------------------------------
// Tensor-core GEMM template (fp16), 2-stage cp.async double buffer.
//   NMMA=2: 2-term hi/lo (Ah/Al + Bh; acc = Ah.Bh + Al.Bh).
//   NMMA=1: single-term (Ah, Bh only).
//   flags: 1=residual, 2=exact GELU, 8=write fp32 C, 16=write fp16 hi/lo,
//          32=grid swapped (blockIdx.x = m-tile, blockIdx.y = n-tile).
//   loN: Cl (lo) written only for columns < loN.
// ---------------------------------------------------------------------------
template<int NMMA>
__global__ __launch_bounds__(256, 2) void bgemm_kernel(
    const uint16_t* __restrict__ Ah, const uint16_t* __restrict__ Al, int lda,
    const uint16_t* __restrict__ Bh, int ldb,
    float* __restrict__ C, f16* __restrict__ Ch, f16* __restrict__ Cl, int ldc,
    const float* __restrict__ bias,
    int M, int N, int K, int flags, int loN) {

    constexpr int TPS = (NMMA == 2) ? 3 : 2;             // tiles per stage
    constexpr int BH_OFF = (NMMA == 2) ? 2 * TILE_E : TILE_E;

    int m0, n0;
    if (flags & 32) { m0 = blockIdx.x * 128; n0 = blockIdx.y * 128; }
    else            { m0 = blockIdx.y * 128; n0 = blockIdx.x * 128; }

    bool tileFull = (n0 + 128 <= N);       // uniform per block

    extern __shared__ uint16_t S[];
    uint32_t sbase = (uint32_t)__cvta_generic_to_shared(S);

    int tid = threadIdx.x, lane = tid & 31, wid = tid >> 5;
    int wm = wid & 1, wn = wid >> 1;
    int fr = lane >> 2, fc = lane & 3;

    int r2 = tid >> 1;
    int c2 = (tid & 1) * 16;

    float acc[4][4][4];
#pragma unroll
    for (int i = 0; i < 4; i++)
#pragma unroll
        for (int j = 0; j < 4; j++)
#pragma unroll
            for (int r = 0; r < 4; r++) acc[i][j][r] = 0.f;

    auto ldStage = [&](int k0, int bufi) {
        uint32_t sb = sbase + bufi * (TPS * TILE_E * 2);
        uint32_t sa = sb + r2 * (KS * 2) + c2 * 2;
        const uint16_t* ga = Ah + (long)(m0 + r2) * lda + k0 + c2;
        cp16(sa, ga);            cp16(sa + 16, ga + 8);
        if (NMMA == 2) {
            ga = Al + (long)(m0 + r2) * lda + k0 + c2;
            cp16(sa + TILE_E * 2, ga); cp16(sa + TILE_E * 2 + 16, ga + 8);
        }
        int gn = n0 + r2;
        uint32_t sbB = sb + BH_OFF * 2 + r2 * (KS * 2) + c2 * 2;
        if (tileFull || gn < N) {
            const uint16_t* gb = Bh + (long)gn * ldb + k0 + c2;
            cp16(sbB, gb);            cp16(sbB + 16, gb + 8);
        } else {
            uint4 zz = make_uint4(0, 0, 0, 0);
            uint16_t* p = S + bufi * TPS * TILE_E + BH_OFF + r2 * KS + c2;
            *(uint4*)p = zz; *(uint4*)(p + 8) = zz;
        }
        asm volatile("cp.async.commit_group;\n" ::: "memory");
    };

    ldStage(0, 0);

    // per-thread ldmatrix address components (elem offsets)
    int aRow = wm * 64 + (lane & 15);
    int aColX = (lane >> 4) << 3;
    int bRow = wn * 32 + ((lane >> 4) << 3) + (lane & 7);
    int bColX = ((lane >> 3) & 1) << 3;

    int KT = K >> 5;
    int buf = 0;
    for (int kt = 0; kt < KT; kt++) {
        asm volatile("cp.async.wait_group 0;\n" ::: "memory");
        __syncthreads();
        if (kt + 1 < KT) ldStage((kt + 1) << 5, buf ^ 1);

        uint32_t sb = sbase + buf * (TPS * TILE_E * 2);

#pragma unroll
        for (int ks = 0; ks < 32; ks += 16) {
            uint32_t ah[4][4], bh[4][2];
            uint32_t aA = sb + (aRow * KS + ks + aColX) * 2;
            uint32_t bB = sb + BH_OFF * 2 + (bRow * KS + ks + bColX) * 2;
#pragma unroll
            for (int mi = 0; mi < 4; mi++) ldm4(ah[mi], aA + mi * (16 * KS * 2));
#pragma unroll
            for (int nip = 0; nip < 2; nip++)
                ldm4(&bh[nip * 2][0], bB + nip * (16 * KS * 2));

#pragma unroll
            for (int mi = 0; mi < 4; mi++)
#pragma unroll
                for (int ni = 0; ni < 4; ni++)
                    mma16816h(acc[mi][ni], ah[mi], bh[ni]);

            if (NMMA == 2) {
                uint32_t al[4][4];
#pragma unroll
                for (int mi = 0; mi < 4; mi++)
                    ldm4(al[mi], aA + mi * (16 * KS * 2) + TILE_E * 2);
#pragma unroll
                for (int mi = 0; mi < 4; mi++)
#pragma unroll
                    for (int ni = 0; ni < 4; ni++)
                        mma16816h(acc[mi][ni], al[mi], bh[ni]);
            }
        }
        __syncthreads();
        buf ^= 1;
    }

    // Epilogue: r-pairs (adjacent columns); paired f16 and (ldc even) f32 ops.
    bool evenC = ((ldc & 1) == 0);
#pragma unroll
    for (int mi = 0; mi < 4; mi++) {
        int gm0 = m0 + wm * 64 + mi * 16 + fr;
#pragma unroll
        for (int ni = 0; ni < 4; ni++) {
            int gn = n0 + wn * 32 + ni * 8 + fc * 2;
#pragma unroll
            for (int rp = 0; rp < 2; rp++) {
                int gm = gm0 + rp * 8;
                float v0 = acc[mi][ni][rp * 2];
                float v1 = acc[mi][ni][rp * 2 + 1];
                if (bias) {
                    if (tileFull || gn < N)     v0 += bias[gn];
                    if (tileFull || gn + 1 < N) v1 += bias[gn + 1];
                }
                if (flags & 2) {
                    v0 = 0.5f * v0 * (1.f + erff(v0 * 0.70710678118654752f));
                    v1 = 0.5f * v1 * (1.f + erff(v1 * 0.70710678118654752f));
                }
                long idx = (long)gm * ldc + gn;
                if (flags & 1) {
                    if (evenC && (tileFull || gn + 1 < N)) {
                        float2 c2v = *(const float2*)&C[idx];
                        v0 += c2v.x; v1 += c2v.y;
                    } else {
                        if (gn < N)     v0 += C[idx];
                        if (gn + 1 < N) v1 += C[idx + 1];
                    }
                }
                if (flags & 8) {
                    if (evenC && (tileFull || gn + 1 < N)) {
                        *(float2*)&C[idx] = make_float2(v0, v1);
                    } else {
                        if (gn < N)     C[idx] = v0;
                        if (gn + 1 < N) C[idx + 1] = v1;
                    }
                }
                if (flags & 16) {
                    f16 h0 = __float2half(v0), h1 = __float2half(v1);
                    if (tileFull || gn + 1 < N) {
                        __half2 hh; hh.x = h0; hh.y = h1;
                        *(__half2*)&Ch[idx] = hh;
                        if (gn + 1 < loN) {
                            __half2 ll;
                            ll.x = __float2half(v0 - __half2float(h0));
                            ll.y = __float2half(v1 - __half2float(h1));
                            *(__half2*)&Cl[idx] = ll;
                        }
                    } else if (gn < N) {
                        Ch[idx] = h0;
                        if (gn < loN)
                            Cl[idx] = __float2half(v0 - __half2float(h0));
                    }
                }
            }
        }
    }
}

// ---------------------------------------------------------------------------
// Host-side orchestration
// ---------------------------------------------------------------------------
extern "C" void kernel_launch(void* const* d_in, const int* in_sizes, int n_in,
                              void* d_out, int out_size) {
    (void)in_sizes; (void)n_in; (void)out_size;

    const int*   tok     = (const int*)  d_in[0];
    const float* wte     = (const float*)d_in[1];
    const float* wpe     = (const float*)d_in[2];
    const float* ln1_w   = (const float*)d_in[3];
    const float* ln1_b   = (const float*)d_in[4];
    const float* attn_w  = (const float*)d_in[5];
    const float* attn_b  = (const float*)d_in[6];
    const float* aproj_w = (const float*)d_in[7];
    const float* aproj_b = (const float*)d_in[8];
    const float* ln2_w   = (const float*)d_in[9];
    const float* ln2_b   = (const float*)d_in[10];
    const float* fc_w    = (const float*)d_in[11];
    const float* fc_b    = (const float*)d_in[12];
    const float* mproj_w = (const float*)d_in[13];
    const float* mproj_b = (const float*)d_in[14];
    const float* lnf_w   = (const float*)d_in[15];
    const float* lnf_b   = (const float*)d_in[16];
    float* out = (float*)d_out;

    float *x;
    f16 *lnh, *lnl, *qkvh, *qkvl, *attnh, *attnl, *midh, *midl;
    f16 *wqkvh, *waph, *wfch, *wmph, *wtef, *lnf16;
    cudaGetSymbolAddress((void**)&x,      g_x);
    cudaGetSymbolAddress((void**)&lnh,    g_lnh);
    cudaGetSymbolAddress((void**)&lnl,    g_lnl);
    cudaGetSymbolAddress((void**)&qkvh,   g_qkvh);
    cudaGetSymbolAddress((void**)&qkvl,   g_qkvl);
    cudaGetSymbolAddress((void**)&attnh,  g_attnh);
    cudaGetSymbolAddress((void**)&attnl,  g_attnl);
    cudaGetSymbolAddress((void**)&midh,   g_midh);
    cudaGetSymbolAddress((void**)&midl,   g_midl);
    cudaGetSymbolAddress((void**)&wqkvh,  g_wqkvh);
    cudaGetSymbolAddress((void**)&waph,   g_waph);
    cudaGetSymbolAddress((void**)&wfch,   g_wfch);
    cudaGetSymbolAddress((void**)&wmph,   g_wmph);
    cudaGetSymbolAddress((void**)&wtef,   g_wtef);
    cudaGetSymbolAddress((void**)&lnf16,  g_lnf16);

    const int D = DMODEL;
    const int SMEM2 = 2 * 3 * TILE_E * 2;                  // 61440 (2 stages x 3 tiles)
    const int SMEM1 = 2 * 2 * TILE_E * 2;                  // 40960 (2 stages x 2 tiles)
    const int FSMEM = (2 * 128 * KSQ + 2 * 128 * KSQ + 2 * 128 * KSVR) * 2; // 110592

    cudaFuncSetAttribute(bgemm_kernel<2>,
                         cudaFuncAttributeMaxDynamicSharedMemorySize, SMEM2);
    cudaFuncSetAttribute(bgemm_kernel<1>,
                         cudaFuncAttributeMaxDynamicSharedMemorySize, SMEM1);
    cudaFuncSetAttribute(flash_kernel,
                         cudaFuncAttributeMaxDynamicSharedMemorySize, FSMEM);

    // ---- weight prep (once per call) ----
    {
        dim3 b32(32, 8);
        tsplit_kernel<<<dim3(D / 32, 3 * D / 32, NLAYER), b32>>>(attn_w,  wqkvh, D, 3 * D);
        tsplit_kernel<<<dim3(D / 32, D / 32, NLAYER),     b32>>>(aproj_w, waph,  D, D);
        tsplit_kernel<<<dim3(D / 32, 4 * D / 32, NLAYER), b32>>>(fc_w,    wfch,  D, 4 * D);
        tsplit_kernel<<<dim3(4 * D / 32, D / 32, NLAYER), b32>>>(mproj_w, wmph,  4 * D, D);
        long nwte4 = (long)NVOCAB * D / 4;
        splitf16_kernel<<<(unsigned)((nwte4 + 255) / 256), 256>>>(wte, wtef, nwte4);
    }

    embed_kernel<<<NTOK, 192>>>(tok, wte, wpe, x);

    for (int l = 0; l < NLAYER; l++) {
        layernorm_kernel<<<NTOK / 8, 256>>>(x, ln1_w + l * D, ln1_b + l * D, lnh, lnl);

        // qkv = h @ attn_w[l] + attn_b[l] -> fp16 hi (+lo for Q cols only)
        {
            dim3 g(3 * D / 128, NTOK / 128);
            bgemm_kernel<2><<<g, 256, SMEM2>>>(
                (const uint16_t*)lnh, (const uint16_t*)lnl, D,
                (const uint16_t*)(wqkvh + (long)l * 3 * D * D), D,
                nullptr, qkvh, qkvl, 3 * D,
                attn_b + (long)l * 3 * D,
                NTOK, 3 * D, D, 16, D);
        }

        // fused flash attention -> attnh/attnl
        flash_kernel<<<dim3(NSEQ / 128, 2 * NHEAD), 256, FSMEM>>>(qkvh, qkvl, attnh, attnl);

        // x += attn @ aproj_w[l] + aproj_b[l]
        {
            dim3 g(D / 128, NTOK / 128);
            bgemm_kernel<2><<<g, 256, SMEM2>>>(
                (const uint16_t*)attnh, (const uint16_t*)attnl, D,
                (const uint16_t*)(waph + (long)l * D * D), D,
                x, nullptr, nullptr, D,
                aproj_b + (long)l * D,
                NTOK, D, D, 1 | 8, 0);
        }

        layernorm_kernel<<<NTOK / 8, 256>>>(x, ln2_w + l * D, ln2_b + l * D, lnh, lnl);

        // mid = gelu(h @ fc_w[l] + fc_b[l]) -> fp16 hi/lo
        {
            dim3 g(4 * D / 128, NTOK / 128);
            bgemm_kernel<2><<<g, 256, SMEM2>>>(
                (const uint16_t*)lnh, (const uint16_t*)lnl, D,
                (const uint16_t*)(wfch + (long)l * 4 * D * D), D,
                nullptr, midh, midl, 4 * D,
                fc_b + (long)l * 4 * D,
                NTOK, 4 * D, D, 2 | 16, 4 * D);
        }

        // x += mid @ mproj_w[l] + mproj_b[l]
        {
            dim3 g(D / 128, NTOK / 128);
            bgemm_kernel<2><<<g, 256, SMEM2>>>(
                (const uint16_t*)midh, (const uint16_t*)midl, 4 * D,
                (const uint16_t*)(wmph + (long)l * D * 4 * D), 4 * D,
                x, nullptr, nullptr, D,
                mproj_b + (long)l * D,
                NTOK, D, 4 * D, 1 | 8, 0);
        }
    }

    // final LN (fp16) + tied lm_head in single-term fp16: out = LN_f(x) @ wte^T
    layernorm_f16_kernel<<<NTOK / 8, 256>>>(x, lnf_w, lnf_b, lnf16);
    {
        dim3 g(NTOK / 128, (NVOCAB + 127) / 128);
        bgemm_kernel<1><<<g, 256, SMEM1>>>(
            (const uint16_t*)lnf16, nullptr, D,
            (const uint16_t*)wtef, D,
            out, nullptr, nullptr, NVOCAB,
            nullptr,
            NTOK, NVOCAB, D, 8 | 32, 0);
    }
}